// round 10
// baseline (speedup 1.0000x reference)
#include <cuda_runtime.h>
#include <cuda_bf16.h>
#include <cstdint>

#define N_NODES 32768
#define N_EDGES 524288
#define NH      4
#define HDIM    128
#define HD      512
#define HID_    128
#define DFF_    2048
#define SLOPE_  0.2f
#define EPS_    1e-5f

// ---------------- scratch ----------------------------------------------------
__device__ float    g_ft [N_NODES*HD];
__device__ float    g_res[N_NODES*HD];
__device__ float    g_el [N_NODES*NH];
__device__ float    g_er [N_NODES*NH];
__device__ float    g_z  [N_NODES*NH];
__device__ int      g_deg[N_NODES];
__device__ int      g_cursor[N_NODES];
__device__ int      g_rowptr[N_NODES+1];
__device__ int      g_esrc[N_EDGES];
__device__ float    g_wsH[NH*N_EDGES];
__device__ float    g_x1 [N_NODES*HID_];

// pre-split hi/lo bf16 transposed weights ([n][k] padded rows)
__device__ __align__(16) __nv_bfloat16 g_w1th[32*64*136];
__device__ __align__(16) __nv_bfloat16 g_w1tl[32*64*136];
__device__ __align__(16) __nv_bfloat16 g_w2th[32*128*72];
__device__ __align__(16) __nv_bfloat16 g_w2tl[32*128*72];
__device__ __align__(16) __nv_bfloat16 g_wfth[512*136];
__device__ __align__(16) __nv_bfloat16 g_wftl[512*136];
__device__ __align__(16) __nv_bfloat16 g_wrth[512*136];
__device__ __align__(16) __nv_bfloat16 g_wrtl[512*136];
__device__ __align__(16) __nv_bfloat16 g_wmth[512*136];
__device__ __align__(16) __nv_bfloat16 g_wmtl[512*136];

// ---------------- helpers ------------------------------------------------------
__device__ __forceinline__ uint32_t smem_u32(const void* p){
    uint32_t a;
    asm("{ .reg .u64 t; cvta.to.shared.u64 t, %1; cvt.u32.u64 %0, t; }" : "=r"(a) : "l"(p));
    return a;
}
__device__ __forceinline__ void ldsm4(unsigned* r, uint32_t addr){
    asm volatile("ldmatrix.sync.aligned.m8n8.x4.shared.b16 {%0,%1,%2,%3}, [%4];"
        : "=r"(r[0]),"=r"(r[1]),"=r"(r[2]),"=r"(r[3]) : "r"(addr));
}
__device__ __forceinline__ void mma_bf16(float* c, const unsigned* a, unsigned b0, unsigned b1){
    asm volatile("mma.sync.aligned.m16n8k16.row.col.f32.bf16.bf16.f32 "
        "{%0,%1,%2,%3},{%4,%5,%6,%7},{%8,%9},{%0,%1,%2,%3};"
        : "+f"(c[0]),"+f"(c[1]),"+f"(c[2]),"+f"(c[3])
        : "r"(a[0]),"r"(a[1]),"r"(a[2]),"r"(a[3]),"r"(b0),"r"(b1));
}
__device__ __forceinline__ void bsplit(float v, __nv_bfloat16& hi, __nv_bfloat16& lo){
    hi = __float2bfloat16(v);
    lo = __float2bfloat16(v - __bfloat162float(hi));
}

// ---------------- init ------------------------------------------------------
__global__ void k_init(){
    int i = blockIdx.x*256 + threadIdx.x;
    g_z[i] = 0.f;
    if (i < N_NODES){ g_deg[i] = 0; g_cursor[i] = 0; }
}

// ---------------- prep --------------------------------------------------------
__global__ void k_prep(const float* __restrict__ W1, const float* __restrict__ W2,
                       const float* __restrict__ Wfc, const float* __restrict__ Wres,
                       const float* __restrict__ Wm){
    int i = blockIdx.x*256 + threadIdx.x;
    {   // W1 [k=128][n=2048]
        int k = i >> 11, n = i & 2047;
        __nv_bfloat16 hv, lv; bsplit(W1[i], hv, lv);
        int c = n >> 6, nn = n & 63;
        g_w1th[(c*64+nn)*136 + k] = hv;
        g_w1tl[(c*64+nn)*136 + k] = lv;
    }
    {   // W2 [k2=2048][n=128]
        int k2 = i >> 7, n = i & 127;
        __nv_bfloat16 hv, lv; bsplit(W2[i], hv, lv);
        int c = k2 >> 6, kk = k2 & 63;
        g_w2th[(c*128+n)*72 + kk] = hv;
        g_w2tl[(c*128+n)*72 + kk] = lv;
    }
    if (i < 65536){
        {   // Wfc/Wres [k=128][n=512]
            int k = i >> 9, n = i & 511;
            __nv_bfloat16 hv, lv;
            bsplit(Wfc[i], hv, lv);
            g_wfth[n*136 + k] = hv; g_wftl[n*136 + k] = lv;
            bsplit(Wres[i], hv, lv);
            g_wrth[n*136 + k] = hv; g_wrtl[n*136 + k] = lv;
        }
        {   // Wm [k2=512][n=128]
            int k2 = i >> 7, n = i & 127;
            __nv_bfloat16 hv, lv; bsplit(Wm[i], hv, lv);
            int c = k2 >> 7, kk = k2 & 127;
            g_wmth[(c*128+n)*136 + kk] = hv;
            g_wmtl[(c*128+n)*136 + kk] = lv;
        }
    }
}

// ---------------- degree count ------------------------------------------------
__global__ __launch_bounds__(256) void k_deg(const int* __restrict__ dst){
    int ei = blockIdx.x*256 + threadIdx.x;
    if (ei < N_EDGES) atomicAdd(&g_deg[dst[ei]], 1);
}

// ---------------- GEMM A: m32n32 warp tiles, both weights per CTA ------------
#define GA_AH  0
#define GA_AL  34816
#define GA_BFH 69632
#define GA_BFL 104448
#define GA_BRH 139264
#define GA_BRL 174080
#define SMEM_GA 208896
#define SMEM_MH 139264

__global__ __launch_bounds__(512,1) void k_gemmA_mma(const float* __restrict__ h,
        const float* __restrict__ attn_l, const float* __restrict__ attn_r){
    extern __shared__ char smem[];
    __shared__ float s_al[128], s_ar[128];
    __shared__ float s_pl[128][4], s_pr[128][4];
    __nv_bfloat16* ah_s = (__nv_bfloat16*)(smem+GA_AH);
    __nv_bfloat16* al_s = (__nv_bfloat16*)(smem+GA_AL);
    const uint32_t sb = smem_u32(smem);
    const int tid = threadIdx.x, lane = tid&31, w = tid>>5;
    const int ws = w>>2, wn = w&3;
    const int m0 = ws*32, ncol0 = wn*32;
    const int col0 = blockIdx.y*128;

    if (tid<128){
        s_al[tid] = attn_l[col0+tid];
        s_ar[tid] = attn_r[col0+tid];
    }
    {   // load both B tiles
        const uint4* fh = (const uint4*)(g_wfth + col0*136);
        const uint4* fl = (const uint4*)(g_wftl + col0*136);
        const uint4* rh = (const uint4*)(g_wrth + col0*136);
        const uint4* rl = (const uint4*)(g_wrtl + col0*136);
        uint4* tfh = (uint4*)(smem+GA_BFH);
        uint4* tfl = (uint4*)(smem+GA_BFL);
        uint4* trh = (uint4*)(smem+GA_BRH);
        uint4* trl = (uint4*)(smem+GA_BRL);
        for (int i=tid;i<2176;i+=512){
            tfh[i]=fh[i]; tfl[i]=fl[i]; trh[i]=rh[i]; trl[i]=rl[i];
        }
    }

    const int a_r = lane & 15, a_c = (lane & 16) >> 1;
    const int b4_r = (lane & 7) + ((lane & 16) >> 1);
    const int b4_c = lane & 8;
    const int q = lane & 3, gq = lane >> 2;

    for (int rt=0; rt<4; rt++){
        const int row0 = (blockIdx.x*4+rt)*128;
        __syncthreads();
        for (int i=tid;i<4096;i+=512){
            int m = i>>5, k4 = (i&31)*4;
            float4 v = *(const float4*)&h[(row0+m)*HID_ + k4];
            __nv_bfloat162 hh, ll;
            bsplit(v.x, hh.x, ll.x); bsplit(v.y, hh.y, ll.y);
            *(__nv_bfloat162*)&ah_s[m*136+k4]   = hh;
            *(__nv_bfloat162*)&al_s[m*136+k4]   = ll;
            bsplit(v.z, hh.x, ll.x); bsplit(v.w, hh.y, ll.y);
            *(__nv_bfloat162*)&ah_s[m*136+k4+2] = hh;
            *(__nv_bfloat162*)&al_s[m*136+k4+2] = ll;
        }
        __syncthreads();

        // ---- target 0: ft (+ el/er partials) ----
        {
            float acc[8][4];   // [mt*4+nt][frag]
            #pragma unroll
            for (int i=0;i<8;i++){ acc[i][0]=0.f; acc[i][1]=0.f; acc[i][2]=0.f; acc[i][3]=0.f; }
            #pragma unroll
            for (int kk=0;kk<8;kk++){
                const int k0 = kk*16;
                unsigned ah[2][4], al[2][4];
                #pragma unroll
                for (int mt=0;mt<2;mt++){
                    uint32_t aaddr = sb + GA_AH + ((m0+mt*16+a_r)*136 + k0 + a_c)*2;
                    ldsm4(ah[mt], aaddr);
                    ldsm4(al[mt], aaddr + (GA_AL-GA_AH));
                }
                #pragma unroll
                for (int ntp=0;ntp<2;ntp++){
                    uint32_t baddr = sb + GA_BFH + ((ncol0+ntp*16+b4_r)*136 + k0 + b4_c)*2;
                    unsigned bh[4], bl[4];
                    ldsm4(bh, baddr);
                    ldsm4(bl, baddr + (GA_BFL-GA_BFH));
                    #pragma unroll
                    for (int mt=0;mt<2;mt++){
                        float* a0 = acc[mt*4+ntp*2], *a1 = acc[mt*4+ntp*2+1];
                        mma_bf16(a0, ah[mt], bh[0], bh[1]);
                        mma_bf16(a0, ah[mt], bl[0], bl[1]);
                        mma_bf16(a0, al[mt], bh[0], bh[1]);
                        mma_bf16(a1, ah[mt], bh[2], bh[3]);
                        mma_bf16(a1, ah[mt], bl[2], bl[3]);
                        mma_bf16(a1, al[mt], bh[2], bh[3]);
                    }
                }
            }
            #pragma unroll
            for (int mt=0;mt<2;mt++)
            #pragma unroll
            for (int half=0; half<2; half++){
                int rl = m0 + mt*16 + gq + half*8;
                int row = row0 + rl;
                float pl=0.f, pr=0.f;
                #pragma unroll
                for (int nt=0;nt<4;nt++){
                    int col = ncol0 + nt*8 + q*2;
                    float v0 = acc[mt*4+nt][half*2], v1 = acc[mt*4+nt][half*2+1];
                    *(float2*)&g_ft[row*HD+col0+col] = make_float2(v0, v1);
                    pl += v0*s_al[col] + v1*s_al[col+1];
                    pr += v0*s_ar[col] + v1*s_ar[col+1];
                }
                pl += __shfl_xor_sync(0xffffffffu, pl, 1);
                pl += __shfl_xor_sync(0xffffffffu, pl, 2);
                pr += __shfl_xor_sync(0xffffffffu, pr, 1);
                pr += __shfl_xor_sync(0xffffffffu, pr, 2);
                if (q==0){ s_pl[rl][wn]=pl; s_pr[rl][wn]=pr; }
            }
        }
        __syncthreads();
        if (tid<128){
            int row = row0 + tid;
            g_el[row*NH + blockIdx.y] = s_pl[tid][0]+s_pl[tid][1]+s_pl[tid][2]+s_pl[tid][3];
            g_er[row*NH + blockIdx.y] = s_pr[tid][0]+s_pr[tid][1]+s_pr[tid][2]+s_pr[tid][3];
        }

        // ---- target 1: res ----
        {
            float acc[8][4];
            #pragma unroll
            for (int i=0;i<8;i++){ acc[i][0]=0.f; acc[i][1]=0.f; acc[i][2]=0.f; acc[i][3]=0.f; }
            #pragma unroll
            for (int kk=0;kk<8;kk++){
                const int k0 = kk*16;
                unsigned ah[2][4], al[2][4];
                #pragma unroll
                for (int mt=0;mt<2;mt++){
                    uint32_t aaddr = sb + GA_AH + ((m0+mt*16+a_r)*136 + k0 + a_c)*2;
                    ldsm4(ah[mt], aaddr);
                    ldsm4(al[mt], aaddr + (GA_AL-GA_AH));
                }
                #pragma unroll
                for (int ntp=0;ntp<2;ntp++){
                    uint32_t baddr = sb + GA_BRH + ((ncol0+ntp*16+b4_r)*136 + k0 + b4_c)*2;
                    unsigned bh[4], bl[4];
                    ldsm4(bh, baddr);
                    ldsm4(bl, baddr + (GA_BRL-GA_BRH));
                    #pragma unroll
                    for (int mt=0;mt<2;mt++){
                        float* a0 = acc[mt*4+ntp*2], *a1 = acc[mt*4+ntp*2+1];
                        mma_bf16(a0, ah[mt], bh[0], bh[1]);
                        mma_bf16(a0, ah[mt], bl[0], bl[1]);
                        mma_bf16(a0, al[mt], bh[0], bh[1]);
                        mma_bf16(a1, ah[mt], bh[2], bh[3]);
                        mma_bf16(a1, ah[mt], bl[2], bl[3]);
                        mma_bf16(a1, al[mt], bh[2], bh[3]);
                    }
                }
            }
            #pragma unroll
            for (int mt=0;mt<2;mt++)
            #pragma unroll
            for (int half=0; half<2; half++){
                int row = row0 + m0 + mt*16 + gq + half*8;
                #pragma unroll
                for (int nt=0;nt<4;nt++){
                    int col = col0 + ncol0 + nt*8 + q*2;
                    *(float2*)&g_res[row*HD+col] =
                        make_float2(acc[mt*4+nt][half*2], acc[mt*4+nt][half*2+1]);
                }
            }
        }
    }
}

// ---------------- merged edge pass + CSR fill --------------------------------
__global__ __launch_bounds__(256) void k_edgefill(const float* __restrict__ e,
        const int* __restrict__ src, const int* __restrict__ dst,
        const float* __restrict__ W_fe, const float* __restrict__ attn_e){
    __shared__ float ce[NH];
    int wid = threadIdx.x>>5, lane = threadIdx.x&31;
    if (wid < NH){
        float p = 0.f;
        #pragma unroll
        for (int q=0;q<4;q++){
            int d = lane + q*32;
            p += W_fe[wid*HDIM+d]*attn_e[wid*HDIM+d];
        }
        #pragma unroll
        for (int off=16; off; off>>=1) p += __shfl_xor_sync(0xffffffffu, p, off);
        if (lane==0) ce[wid]=p;
    }
    __syncthreads();
    int ei = blockIdx.x*256 + threadIdx.x;
    if (ei >= N_EDGES) return;
    int s = src[ei], d = dst[ei];
    float ev = e[ei];
    float4 els = ((const float4*)g_el)[s];
    float4 erd = ((const float4*)g_er)[d];
    float sc[4];
    sc[0] = els.x + erd.x + ev*ce[0];
    sc[1] = els.y + erd.y + ev*ce[1];
    sc[2] = els.z + erd.z + ev*ce[2];
    sc[3] = els.w + erd.w + ev*ce[3];
    int pos = g_rowptr[d] + atomicAdd(&g_cursor[d], 1);
    g_esrc[pos] = s;
    #pragma unroll
    for (int hh=0;hh<4;hh++){
        float v = sc[hh];
        v = v > 0.f ? v : SLOPE_*v;
        float wv = expf(v);
        atomicAdd(&g_z[d*NH+hh], wv);
        g_wsH[hh*N_EDGES+pos] = wv;
    }
}

// ---------------- CSR scan ----------------------------------------------------
__global__ __launch_bounds__(1024) void k_scan(){
    __shared__ int sm[1024];
    int t = threadIdx.x;
    int base = t*32;
    int s = 0;
    #pragma unroll
    for (int i=0;i<32;i++) s += g_deg[base+i];
    sm[t]=s; __syncthreads();
    for (int off=1; off<1024; off<<=1){
        int v = (t>=off)? sm[t-off] : 0;
        __syncthreads();
        if (t>=off) sm[t]+=v;
        __syncthreads();
    }
    int run = sm[t]-s;
    for (int i=0;i<32;i++){ g_rowptr[base+i]=run; run += g_deg[base+i]; }
    if (t==1023) g_rowptr[N_NODES]=run;
}

// ---------------- aggregation (4x unrolled) ------------------------------------
__global__ __launch_bounds__(256) void k_agg(const float* __restrict__ gat_bias){
    int wid = threadIdx.x>>5, lane = threadIdx.x&31;
    int gw = blockIdx.x*8 + wid;
    int n = gw>>2, hh = gw&3;
    int beg = g_rowptr[n], end = g_rowptr[n+1];
    float zz = g_z[n*NH+hh];
    float zi = zz > 0.f ? 1.f/zz : 1.f;
    float4 acc = make_float4(0,0,0,0);
    const float4* ft4 = (const float4*)g_ft;
    const float* wp = g_wsH + hh*N_EDGES;
    int i = beg;
    for (; i+4<=end; i+=4){
        float w0 = wp[i],     w1 = wp[i+1],   w2 = wp[i+2],   w3 = wp[i+3];
        int   s0 = g_esrc[i], s1 = g_esrc[i+1], s2 = g_esrc[i+2], s3 = g_esrc[i+3];
        float4 v0 = ft4[s0*128 + hh*32 + lane];
        float4 v1 = ft4[s1*128 + hh*32 + lane];
        float4 v2 = ft4[s2*128 + hh*32 + lane];
        float4 v3 = ft4[s3*128 + hh*32 + lane];
        acc.x += w0*v0.x + w1*v1.x + w2*v2.x + w3*v3.x;
        acc.y += w0*v0.y + w1*v1.y + w2*v2.y + w3*v3.y;
        acc.z += w0*v0.z + w1*v1.z + w2*v2.z + w3*v3.z;
        acc.w += w0*v0.w + w1*v1.w + w2*v2.w + w3*v3.w;
    }
    for (; i<end; i++){
        float w0 = wp[i];
        int s0 = g_esrc[i];
        float4 v0 = ft4[s0*128 + hh*32 + lane];
        acc.x = fmaf(w0, v0.x, acc.x);
        acc.y = fmaf(w0, v0.y, acc.y);
        acc.z = fmaf(w0, v0.z, acc.z);
        acc.w = fmaf(w0, v0.w, acc.w);
    }
    int base = n*HD + hh*HDIM + lane*4;
    float4 r  = *(const float4*)&g_res[base];
    float4 bv = *(const float4*)&gat_bias[hh*HDIM + lane*4];
    float4 o;
    o.x = fmaxf(acc.x*zi + r.x + bv.x, 0.f);
    o.y = fmaxf(acc.y*zi + r.y + bv.y, 0.f);
    o.z = fmaxf(acc.z*zi + r.z + bv.z, 0.f);
    o.w = fmaxf(acc.w*zi + r.w + bv.w, 0.f);
    *(float4*)&g_res[base] = o;
}

// ---------------- MHA: m32n32 warp tiles + relu + residual + LN1 -------------
__global__ __launch_bounds__(512,1) void k_mha_mma(const float* __restrict__ bm,
        const float* __restrict__ h0, const float* __restrict__ g1,
        const float* __restrict__ be1){
    extern __shared__ char smem[];
    __shared__ float s_s1[128][4], s_s2[128][4];
    __nv_bfloat16* ah_s = (__nv_bfloat16*)(smem+GA_AH);
    __nv_bfloat16* al_s = (__nv_bfloat16*)(smem+GA_AL);
    const uint32_t sb = smem_u32(smem);
    const int tid = threadIdx.x, lane = tid&31, w = tid>>5;
    const int ws = w>>2, wn = w&3;
    const int m0 = ws*32, ncol0 = wn*32;
    const int row0 = blockIdx.x*128;

    const int a_r = lane & 15, a_c = (lane & 16) >> 1;
    const int b4_r = (lane & 7) + ((lane & 16) >> 1);
    const int b4_c = lane & 8;
    const int q = lane & 3, gq = lane >> 2;

    float acc[8][4];
    #pragma unroll
    for (int i=0;i<8;i++){ acc[i][0]=0.f; acc[i][1]=0.f; acc[i][2]=0.f; acc[i][3]=0.f; }

    for (int c=0; c<4; c++){
        __syncthreads();
        for (int i=tid;i<4096;i+=512){
            int m = i>>5, k4 = (i&31)*4;
            float4 v = *(const float4*)&g_res[(row0+m)*HD + c*128 + k4];
            __nv_bfloat162 hh, ll;
            bsplit(v.x, hh.x, ll.x); bsplit(v.y, hh.y, ll.y);
            *(__nv_bfloat162*)&ah_s[m*136+k4]   = hh;
            *(__nv_bfloat162*)&al_s[m*136+k4]   = ll;
            bsplit(v.z, hh.x, ll.x); bsplit(v.w, hh.y, ll.y);
            *(__nv_bfloat162*)&ah_s[m*136+k4+2] = hh;
            *(__nv_bfloat162*)&al_s[m*136+k4+2] = ll;
        }
        {
            const uint4* sh = (const uint4*)(g_wmth + c*128*136);
            const uint4* sl = (const uint4*)(g_wmtl + c*128*136);
            uint4* th = (uint4*)(smem+GA_BFH);
            uint4* tl = (uint4*)(smem+GA_BFL);
            for (int i=tid;i<2176;i+=512){ th[i]=sh[i]; tl[i]=sl[i]; }
        }
        __syncthreads();
        #pragma unroll
        for (int kk=0;kk<8;kk++){
            const int k0 = kk*16;
            unsigned ah[2][4], al[2][4];
            #pragma unroll
            for (int mt=0;mt<2;mt++){
                uint32_t aaddr = sb + GA_AH + ((m0+mt*16+a_r)*136 + k0 + a_c)*2;
                ldsm4(ah[mt], aaddr);
                ldsm4(al[mt], aaddr + (GA_AL-GA_AH));
            }
            #pragma unroll
            for (int ntp=0;ntp<2;ntp++){
                uint32_t baddr = sb + GA_BFH + ((ncol0+ntp*16+b4_r)*136 + k0 + b4_c)*2;
                unsigned bh[4], bl[4];
                ldsm4(bh, baddr);
                ldsm4(bl, baddr + (GA_BFL-GA_BFH));
                #pragma unroll
                for (int mt=0;mt<2;mt++){
                    float* a0 = acc[mt*4+ntp*2], *a1 = acc[mt*4+ntp*2+1];
                    mma_bf16(a0, ah[mt], bh[0], bh[1]);
                    mma_bf16(a0, ah[mt], bl[0], bl[1]);
                    mma_bf16(a0, al[mt], bh[0], bh[1]);
                    mma_bf16(a1, ah[mt], bh[2], bh[3]);
                    mma_bf16(a1, ah[mt], bl[2], bl[3]);
                    mma_bf16(a1, al[mt], bh[2], bh[3]);
                }
            }
        }
    }

    // epilogue: +bm, relu, +h0, LN1 cross-4-warps via smem -> g_x1
    float tv[2][2][8];
    #pragma unroll
    for (int mt=0;mt<2;mt++)
    #pragma unroll
    for (int half=0; half<2; half++){
        int rl = m0 + mt*16 + gq + half*8;
        int row = row0 + rl;
        float s1=0.f, s2=0.f;
        #pragma unroll
        for (int nt=0;nt<4;nt++){
            int col = ncol0 + nt*8 + q*2;
            float t0 = fmaxf(acc[mt*4+nt][half*2+0] + bm[col],   0.f) + h0[row*HID_+col];
            float t1 = fmaxf(acc[mt*4+nt][half*2+1] + bm[col+1], 0.f) + h0[row*HID_+col+1];
            tv[mt][half][nt*2]=t0; tv[mt][half][nt*2+1]=t1;
            s1 += t0+t1; s2 += t0*t0+t1*t1;
        }
        s1 += __shfl_xor_sync(0xffffffffu, s1, 1); s2 += __shfl_xor_sync(0xffffffffu, s2, 1);
        s1 += __shfl_xor_sync(0xffffffffu, s1, 2); s2 += __shfl_xor_sync(0xffffffffu, s2, 2);
        if (q==0){ s_s1[rl][wn]=s1; s_s2[rl][wn]=s2; }
    }
    __syncthreads();
    #pragma unroll
    for (int mt=0;mt<2;mt++)
    #pragma unroll
    for (int half=0; half<2; half++){
        int rl = m0 + mt*16 + gq + half*8;
        int row = row0 + rl;
        float fs1 = s_s1[rl][0]+s_s1[rl][1]+s_s1[rl][2]+s_s1[rl][3];
        float fs2 = s_s2[rl][0]+s_s2[rl][1]+s_s2[rl][2]+s_s2[rl][3];
        float mean = fs1*(1.f/HID_);
        float var  = fs2*(1.f/HID_) - mean*mean;
        float rs   = rsqrtf(var + EPS_);
        #pragma unroll
        for (int nt=0;nt<4;nt++){
            int col = ncol0 + nt*8 + q*2;
            g_x1[row*HID_+col]   = (tv[mt][half][nt*2]  -mean)*rs*g1[col]   + be1[col];
            g_x1[row*HID_+col+1] = (tv[mt][half][nt*2+1]-mean)*rs*g1[col+1] + be1[col+1];
        }
    }
}

// ---------------- FFN: m32 warp tiles + residual + LN2 ------------------------
#define SM_XS_H 0
#define SM_XS_L 34816
#define SM_W1H  69632
#define SM_W1L  87040
#define SM_W2H  104448
#define SM_W2L  122880
#define SM_MIDH 141312
#define SM_MIDL 159744
#define SMEM_FFN 178176

__global__ __launch_bounds__(512,1) void k_ffn_mma(const float* __restrict__ b1v,
        const float* __restrict__ b2v, const float* __restrict__ g2,
        const float* __restrict__ be2, float* __restrict__ out){
    extern __shared__ char smem[];
    __shared__ float s_s1[128][4], s_s2[128][4];
    __nv_bfloat16* xs_h = (__nv_bfloat16*)(smem+SM_XS_H);
    __nv_bfloat16* xs_l = (__nv_bfloat16*)(smem+SM_XS_L);
    __nv_bfloat16* mid_h= (__nv_bfloat16*)(smem+SM_MIDH);
    __nv_bfloat16* mid_l= (__nv_bfloat16*)(smem+SM_MIDL);
    const uint32_t sb = smem_u32(smem);
    const int tid = threadIdx.x, lane = tid&31, w = tid>>5;
    const int ws = w>>2, wn = w&3;
    const int m0 = ws*32, ncol0 = wn*32;
    const int row0 = blockIdx.x*128;

    for (int i=tid;i<128*128;i+=512){
        int m=i>>7, k=i&127;
        float v = g_x1[(row0+m)*HID_ + k];
        __nv_bfloat16 hv, lv; bsplit(v, hv, lv);
        xs_h[m*136+k] = hv;
        xs_l[m*136+k] = lv;
    }

    float acc2[8][4];
    #pragma unroll
    for (int i=0;i<8;i++){ acc2[i][0]=0.f; acc2[i][1]=0.f; acc2[i][2]=0.f; acc2[i][3]=0.f; }

    const int a_r = lane & 15, a_c = (lane & 16) >> 1;
    const int b4_r = (lane & 7) + ((lane & 16) >> 1);
    const int b4_c = lane & 8;
    const int q = lane & 3, gq = lane >> 2;

    for (int c=0; c<32; c++){
        __syncthreads();
        {
            const uint4* s1h = (const uint4*)(g_w1th + c*64*136);
            const uint4* s1l = (const uint4*)(g_w1tl + c*64*136);
            const uint4* s2h = (const uint4*)(g_w2th + c*128*72);
            const uint4* s2l = (const uint4*)(g_w2tl + c*128*72);
            uint4* t1h = (uint4*)(smem+SM_W1H); uint4* t1l = (uint4*)(smem+SM_W1L);
            uint4* t2h = (uint4*)(smem+SM_W2H); uint4* t2l = (uint4*)(smem+SM_W2L);
            for (int i=tid;i<1088;i+=512){ t1h[i]=s1h[i]; t1l[i]=s1l[i]; }
            for (int i=tid;i<1152;i+=512){ t2h[i]=s2h[i]; t2l[i]=s2l[i]; }
        }
        __syncthreads();

        // GEMM1: mid[128x64]; warp = rows m0..+31, mid cols wn*16..+15
        float acc1[4][4];   // [mt*2+nt][frag]
        #pragma unroll
        for (int i=0;i<4;i++){ acc1[i][0]=0.f; acc1[i][1]=0.f; acc1[i][2]=0.f; acc1[i][3]=0.f; }
        #pragma unroll
        for (int kk=0;kk<8;kk++){
            const int k0 = kk*16;
            unsigned ah[2][4], al[2][4];
            #pragma unroll
            for (int mt=0;mt<2;mt++){
                uint32_t aaddr = sb + SM_XS_H + ((m0+mt*16+a_r)*136 + k0 + a_c)*2;
                ldsm4(ah[mt], aaddr);
                ldsm4(al[mt], aaddr + (SM_XS_L - SM_XS_H));
            }
            uint32_t baddr = sb + SM_W1H + ((wn*16+b4_r)*136 + k0 + b4_c)*2;
            unsigned bh[4], bl[4];
            ldsm4(bh, baddr);
            ldsm4(bl, baddr + (SM_W1L - SM_W1H));
            #pragma unroll
            for (int mt=0;mt<2;mt++){
                float* a0 = acc1[mt*2], *a1 = acc1[mt*2+1];
                mma_bf16(a0, ah[mt], bh[0], bh[1]);
                mma_bf16(a0, ah[mt], bl[0], bl[1]);
                mma_bf16(a0, al[mt], bh[0], bh[1]);
                mma_bf16(a1, ah[mt], bh[2], bh[3]);
                mma_bf16(a1, ah[mt], bl[2], bl[3]);
                mma_bf16(a1, al[mt], bh[2], bh[3]);
            }
        }
        {
            #pragma unroll
            for (int mt=0;mt<2;mt++){
                const int r1 = m0 + mt*16 + gq, r2 = r1 + 8;
                #pragma unroll
                for (int nt=0;nt<2;nt++){
                    int col = wn*16 + nt*8 + q*2;
                    float bb0 = b1v[c*64+col], bb1 = b1v[c*64+col+1];
                    float v0 = fmaxf(acc1[mt*2+nt][0]+bb0, 0.f);
                    float v1 = fmaxf(acc1[mt*2+nt][1]+bb1, 0.f);
                    float v2 = fmaxf(acc1[mt*2+nt][2]+bb0, 0.f);
                    float v3 = fmaxf(acc1[mt*2+nt][3]+bb1, 0.f);
                    __nv_bfloat162 hh, ll;
                    bsplit(v0, hh.x, ll.x); bsplit(v1, hh.y, ll.y);
                    *(__nv_bfloat162*)&mid_h[r1*72+col]=hh;
                    *(__nv_bfloat162*)&mid_l[r1*72+col]=ll;
                    bsplit(v2, hh.x, ll.x); bsplit(v3, hh.y, ll.y);
                    *(__nv_bfloat162*)&mid_h[r2*72+col]=hh;
                    *(__nv_bfloat162*)&mid_l[r2*72+col]=ll;
                }
            }
        }
        __syncthreads();

        // GEMM2: acc2 += mid[m0..+31][64] @ W2^T ; out cols ncol0..+31
        #pragma unroll
        for (int kk=0;kk<4;kk++){
            const int k0 = kk*16;
            unsigned ah[2][4], al[2][4];
            #pragma unroll
            for (int mt=0;mt<2;mt++){
                uint32_t aaddr = sb + SM_MIDH + ((m0+mt*16+a_r)*72 + k0 + a_c)*2;
                ldsm4(ah[mt], aaddr);
                ldsm4(al[mt], aaddr + (SM_MIDL - SM_MIDH));
            }
            #pragma unroll
            for (int ntp=0;ntp<2;ntp++){
                uint32_t baddr = sb + SM_W2H + ((ncol0+ntp*16+b4_r)*72 + k0 + b4_c)*2;
                unsigned bh[4], bl[4];
                ldsm4(bh, baddr);
                ldsm4(bl, baddr + (SM_W2L - SM_W2H));
                #pragma unroll
                for (int mt=0;mt<2;mt++){
                    float* a0 = acc2[mt*4+ntp*2], *a1 = acc2[mt*4+ntp*2+1];
                    mma_bf16(a0, ah[mt], bh[0], bh[1]);
                    mma_bf16(a0, ah[mt], bl[0], bl[1]);
                    mma_bf16(a0, al[mt], bh[0], bh[1]);
                    mma_bf16(a1, ah[mt], bh[2], bh[3]);
                    mma_bf16(a1, ah[mt], bl[2], bl[3]);
                    mma_bf16(a1, al[mt], bh[2], bh[3]);
                }
            }
        }
    }

    // epilogue: +b2 + residual + LN2 cross-4-warps via smem
    float tv[2][2][8];
    #pragma unroll
    for (int mt=0;mt<2;mt++)
    #pragma unroll
    for (int half=0; half<2; half++){
        int rl = m0 + mt*16 + gq + half*8;
        int grow = row0 + rl;
        float s1=0.f, s2=0.f;
        #pragma unroll
        for (int nt=0;nt<4;nt++){
            int col = ncol0 + nt*8 + q*2;
            float t0 = acc2[mt*4+nt][half*2+0] + b2v[col]   + g_x1[grow*HID_+col];
            float t1 = acc2[mt*4+nt][half*2+1] + b2v[col+1] + g_x1[grow*HID_+col+1];
            tv[mt][half][nt*2]=t0; tv[mt][half][nt*2+1]=t1;
            s1 += t0+t1; s2 += t0*t0+t1*t1;
        }
        s1 += __shfl_xor_sync(0xffffffffu, s1, 1); s2 += __shfl_xor_sync(0xffffffffu, s2, 1);
        s1 += __shfl_xor_sync(0xffffffffu, s1, 2); s2 += __shfl_xor_sync(0xffffffffu, s2, 2);
        if (q==0){ s_s1[rl][wn]=s1; s_s2[rl][wn]=s2; }
    }
    __syncthreads();
    #pragma unroll
    for (int mt=0;mt<2;mt++)
    #pragma unroll
    for (int half=0; half<2; half++){
        int rl = m0 + mt*16 + gq + half*8;
        int grow = row0 + rl;
        float fs1 = s_s1[rl][0]+s_s1[rl][1]+s_s1[rl][2]+s_s1[rl][3];
        float fs2 = s_s2[rl][0]+s_s2[rl][1]+s_s2[rl][2]+s_s2[rl][3];
        float mean = fs1*(1.f/HID_);
        float var  = fs2*(1.f/HID_) - mean*mean;
        float rs   = rsqrtf(var + EPS_);
        #pragma unroll
        for (int nt=0;nt<4;nt++){
            int col = ncol0 + nt*8 + q*2;
            out[grow*HID_+col]   = (tv[mt][half][nt*2]  -mean)*rs*g2[col]   + be2[col];
            out[grow*HID_+col+1] = (tv[mt][half][nt*2+1]-mean)*rs*g2[col+1] + be2[col+1];
        }
    }
}

// ---------------- launch ----------------------------------------------------
extern "C" void kernel_launch(void* const* d_in, const int* in_sizes, int n_in,
                              void* d_out, int out_size){
    int o = (in_sizes[4] == 1) ? 1 : 0;
    const float* h       = (const float*)d_in[0];
    const float* e       = (const float*)d_in[1];
    const int*   src     = (const int*)  d_in[2];
    const int*   dst     = (const int*)  d_in[3];
    const float* W_fc    = (const float*)d_in[4+o];
    const float* attn_l  = (const float*)d_in[5+o];
    const float* attn_r  = (const float*)d_in[6+o];
    const float* W_fe    = (const float*)d_in[7+o];
    const float* attn_e  = (const float*)d_in[8+o];
    const float* W_res   = (const float*)d_in[9+o];
    const float* gatb    = (const float*)d_in[10+o];
    const float* W_mha   = (const float*)d_in[11+o];
    const float* b_mha   = (const float*)d_in[12+o];
    const float* n1_g    = (const float*)d_in[13+o];
    const float* n1_b    = (const float*)d_in[14+o];
    const float* n2_g    = (const float*)d_in[15+o];
    const float* n2_b    = (const float*)d_in[16+o];
    const float* W1      = (const float*)d_in[17+o];
    const float* b1      = (const float*)d_in[18+o];
    const float* W2      = (const float*)d_in[19+o];
    const float* b2      = (const float*)d_in[20+o];
    float* out = (float*)d_out;

    cudaFuncSetAttribute(k_ffn_mma,  cudaFuncAttributeMaxDynamicSharedMemorySize, SMEM_FFN);
    cudaFuncSetAttribute(k_gemmA_mma,cudaFuncAttributeMaxDynamicSharedMemorySize, SMEM_GA);
    cudaFuncSetAttribute(k_mha_mma,  cudaFuncAttributeMaxDynamicSharedMemorySize, SMEM_MH);

    k_init<<<512,256>>>();
    k_prep<<<1024,256>>>(W1, W2, W_fc, W_res, W_mha);
    k_deg<<<N_EDGES/256,256>>>(dst);
    dim3 gA(64, 4);
    k_gemmA_mma<<<gA,512,SMEM_GA>>>(h, attn_l, attn_r);
    k_scan<<<1,1024>>>();
    k_edgefill<<<N_EDGES/256,256>>>(e, src, dst, W_fe, attn_e);
    k_agg<<<N_NODES*NH/8,256>>>(gatb);
    k_mha_mma<<<N_NODES/128,512,SMEM_MH>>>(b_mha, h, n1_g, n1_b);
    k_ffn_mma<<<N_NODES/128,512,SMEM_FFN>>>(b1, b2, n2_g, n2_b, out);
}

// round 11
// speedup vs baseline: 1.1001x; 1.1001x over previous
#include <cuda_runtime.h>
#include <cuda_bf16.h>
#include <cstdint>

#define N_NODES 32768
#define N_EDGES 524288
#define NH      4
#define HDIM    128
#define HD      512
#define HID_    128
#define DFF_    2048
#define SLOPE_  0.2f
#define EPS_    1e-5f

// ---------------- scratch ----------------------------------------------------
__device__ float    g_ft [N_NODES*HD];
__device__ float    g_res[N_NODES*HD];
__device__ float    g_el [N_NODES*NH];
__device__ float    g_er [N_NODES*NH];
__device__ float    g_z  [N_NODES*NH];
__device__ int      g_deg[N_NODES];
__device__ int      g_cursor[N_NODES];
__device__ int      g_rowptr[N_NODES+1];
__device__ int      g_esrc[N_EDGES];
__device__ float    g_wsH[NH*N_EDGES];
__device__ float    g_x1 [N_NODES*HID_];

// pre-split hi/lo bf16 transposed weights ([n][k] padded rows)
__device__ __align__(16) __nv_bfloat16 g_w1th[32*64*136];
__device__ __align__(16) __nv_bfloat16 g_w1tl[32*64*136];
__device__ __align__(16) __nv_bfloat16 g_w2th[32*128*72];
__device__ __align__(16) __nv_bfloat16 g_w2tl[32*128*72];
__device__ __align__(16) __nv_bfloat16 g_wfth[512*136];
__device__ __align__(16) __nv_bfloat16 g_wftl[512*136];
__device__ __align__(16) __nv_bfloat16 g_wrth[512*136];
__device__ __align__(16) __nv_bfloat16 g_wrtl[512*136];
__device__ __align__(16) __nv_bfloat16 g_wmth[512*136];
__device__ __align__(16) __nv_bfloat16 g_wmtl[512*136];

// ---------------- helpers ------------------------------------------------------
__device__ __forceinline__ uint32_t smem_u32(const void* p){
    uint32_t a;
    asm("{ .reg .u64 t; cvta.to.shared.u64 t, %1; cvt.u32.u64 %0, t; }" : "=r"(a) : "l"(p));
    return a;
}
__device__ __forceinline__ void ldsm4(unsigned* r, uint32_t addr){
    asm volatile("ldmatrix.sync.aligned.m8n8.x4.shared.b16 {%0,%1,%2,%3}, [%4];"
        : "=r"(r[0]),"=r"(r[1]),"=r"(r[2]),"=r"(r[3]) : "r"(addr));
}
__device__ __forceinline__ void mma_bf16(float* c, const unsigned* a, unsigned b0, unsigned b1){
    asm volatile("mma.sync.aligned.m16n8k16.row.col.f32.bf16.bf16.f32 "
        "{%0,%1,%2,%3},{%4,%5,%6,%7},{%8,%9},{%0,%1,%2,%3};"
        : "+f"(c[0]),"+f"(c[1]),"+f"(c[2]),"+f"(c[3])
        : "r"(a[0]),"r"(a[1]),"r"(a[2]),"r"(a[3]),"r"(b0),"r"(b1));
}
__device__ __forceinline__ void bsplit(float v, __nv_bfloat16& hi, __nv_bfloat16& lo){
    hi = __float2bfloat16(v);
    lo = __float2bfloat16(v - __bfloat162float(hi));
}
__device__ __forceinline__ void cpa16(uint32_t saddr, const void* g){
    asm volatile("cp.async.cg.shared.global [%0], [%1], 16;" :: "r"(saddr), "l"(g));
}
#define CPA_COMMIT() asm volatile("cp.async.commit_group;" ::: "memory")
#define CPA_WAIT1()  asm volatile("cp.async.wait_group 1;" ::: "memory")
#define CPA_WAIT0()  asm volatile("cp.async.wait_group 0;" ::: "memory")

// ---------------- init ------------------------------------------------------
__global__ void k_init(){
    int i = blockIdx.x*256 + threadIdx.x;
    g_z[i] = 0.f;
    if (i < N_NODES){ g_deg[i] = 0; g_cursor[i] = 0; }
}

// ---------------- prep --------------------------------------------------------
__global__ void k_prep(const float* __restrict__ W1, const float* __restrict__ W2,
                       const float* __restrict__ Wfc, const float* __restrict__ Wres,
                       const float* __restrict__ Wm){
    int i = blockIdx.x*256 + threadIdx.x;
    {   // W1 [k=128][n=2048]
        int k = i >> 11, n = i & 2047;
        __nv_bfloat16 hv, lv; bsplit(W1[i], hv, lv);
        int c = n >> 6, nn = n & 63;
        g_w1th[(c*64+nn)*136 + k] = hv;
        g_w1tl[(c*64+nn)*136 + k] = lv;
    }
    {   // W2 [k2=2048][n=128]
        int k2 = i >> 7, n = i & 127;
        __nv_bfloat16 hv, lv; bsplit(W2[i], hv, lv);
        int c = k2 >> 6, kk = k2 & 63;
        g_w2th[(c*128+n)*72 + kk] = hv;
        g_w2tl[(c*128+n)*72 + kk] = lv;
    }
    if (i < 65536){
        {   // Wfc/Wres [k=128][n=512]
            int k = i >> 9, n = i & 511;
            __nv_bfloat16 hv, lv;
            bsplit(Wfc[i], hv, lv);
            g_wfth[n*136 + k] = hv; g_wftl[n*136 + k] = lv;
            bsplit(Wres[i], hv, lv);
            g_wrth[n*136 + k] = hv; g_wrtl[n*136 + k] = lv;
        }
        {   // Wm [k2=512][n=128]
            int k2 = i >> 7, n = i & 127;
            __nv_bfloat16 hv, lv; bsplit(Wm[i], hv, lv);
            int c = k2 >> 7, kk = k2 & 127;
            g_wmth[(c*128+n)*136 + kk] = hv;
            g_wmtl[(c*128+n)*136 + kk] = lv;
        }
    }
}

// ---------------- degree count ------------------------------------------------
__global__ __launch_bounds__(256) void k_deg(const int* __restrict__ dst){
    int ei = blockIdx.x*256 + threadIdx.x;
    if (ei < N_EDGES) atomicAdd(&g_deg[dst[ei]], 1);
}

// ---------------- GEMM A: m16n64 warp tiles, both weights per CTA ------------
#define GA_AH  0
#define GA_AL  34816
#define GA_BFH 69632
#define GA_BFL 104448
#define GA_BRH 139264
#define GA_BRL 174080
#define SMEM_GA 208896
#define SMEM_MH 139264

__global__ __launch_bounds__(512,1) void k_gemmA_mma(const float* __restrict__ h,
        const float* __restrict__ attn_l, const float* __restrict__ attn_r){
    extern __shared__ char smem[];
    __shared__ float s_al[128], s_ar[128];
    __shared__ float s_pl[128][2], s_pr[128][2];
    __nv_bfloat16* ah_s = (__nv_bfloat16*)(smem+GA_AH);
    __nv_bfloat16* al_s = (__nv_bfloat16*)(smem+GA_AL);
    const uint32_t sb = smem_u32(smem);
    const int tid = threadIdx.x, lane = tid&31, w = tid>>5;
    const int strip = w>>1, nh = w&1;
    const int m0 = strip*16, ncol0 = nh*64;
    const int col0 = blockIdx.y*128;

    if (tid<128){
        s_al[tid] = attn_l[col0+tid];
        s_ar[tid] = attn_r[col0+tid];
    }
    {   // load both B tiles
        const uint4* fh = (const uint4*)(g_wfth + col0*136);
        const uint4* fl = (const uint4*)(g_wftl + col0*136);
        const uint4* rh = (const uint4*)(g_wrth + col0*136);
        const uint4* rl = (const uint4*)(g_wrtl + col0*136);
        uint4* tfh = (uint4*)(smem+GA_BFH);
        uint4* tfl = (uint4*)(smem+GA_BFL);
        uint4* trh = (uint4*)(smem+GA_BRH);
        uint4* trl = (uint4*)(smem+GA_BRL);
        for (int i=tid;i<2176;i+=512){
            tfh[i]=fh[i]; tfl[i]=fl[i]; trh[i]=rh[i]; trl[i]=rl[i];
        }
    }

    const int a_r = lane & 15, a_c = (lane & 16) >> 1;
    const int b4_r = (lane & 7) + ((lane & 16) >> 1);
    const int b4_c = lane & 8;
    const int q = lane & 3, gq = lane >> 2;

    for (int rt=0; rt<4; rt++){
        const int row0 = (blockIdx.x*4+rt)*128;
        __syncthreads();
        for (int i=tid;i<4096;i+=512){
            int m = i>>5, k4 = (i&31)*4;
            float4 v = *(const float4*)&h[(row0+m)*HID_ + k4];
            __nv_bfloat162 hh, ll;
            bsplit(v.x, hh.x, ll.x); bsplit(v.y, hh.y, ll.y);
            *(__nv_bfloat162*)&ah_s[m*136+k4]   = hh;
            *(__nv_bfloat162*)&al_s[m*136+k4]   = ll;
            bsplit(v.z, hh.x, ll.x); bsplit(v.w, hh.y, ll.y);
            *(__nv_bfloat162*)&ah_s[m*136+k4+2] = hh;
            *(__nv_bfloat162*)&al_s[m*136+k4+2] = ll;
        }
        __syncthreads();

        // ---- target 0: ft (+ el/er partials) ----
        {
            float acc[8][4];
            #pragma unroll
            for (int i=0;i<8;i++){ acc[i][0]=0.f; acc[i][1]=0.f; acc[i][2]=0.f; acc[i][3]=0.f; }
            #pragma unroll
            for (int kk=0;kk<8;kk++){
                const int k0 = kk*16;
                uint32_t aaddr = sb + GA_AH + ((m0+a_r)*136 + k0 + a_c)*2;
                unsigned ahf[4], alf[4];
                ldsm4(ahf, aaddr);
                ldsm4(alf, aaddr + (GA_AL-GA_AH));
                #pragma unroll
                for (int ntp=0;ntp<4;ntp++){
                    uint32_t baddr = sb + GA_BFH + ((ncol0+ntp*16+b4_r)*136 + k0 + b4_c)*2;
                    unsigned bh[4], bl[4];
                    ldsm4(bh, baddr);
                    ldsm4(bl, baddr + (GA_BFL-GA_BFH));
                    float* a0 = acc[ntp*2], *a1 = acc[ntp*2+1];
                    mma_bf16(a0, ahf, bh[0], bh[1]);
                    mma_bf16(a0, ahf, bl[0], bl[1]);
                    mma_bf16(a0, alf, bh[0], bh[1]);
                    mma_bf16(a1, ahf, bh[2], bh[3]);
                    mma_bf16(a1, ahf, bl[2], bl[3]);
                    mma_bf16(a1, alf, bh[2], bh[3]);
                }
            }
            #pragma unroll
            for (int half=0; half<2; half++){
                int row = row0 + m0 + gq + half*8;
                #pragma unroll
                for (int nt=0;nt<8;nt++){
                    int col = col0 + ncol0 + nt*8 + q*2;
                    *(float2*)&g_ft[row*HD+col] =
                        make_float2(acc[nt][half*2], acc[nt][half*2+1]);
                }
            }
            #pragma unroll
            for (int half=0; half<2; half++){
                int rl = m0 + gq + half*8;
                float pl=0.f, pr=0.f;
                #pragma unroll
                for (int nt=0;nt<8;nt++){
                    int col = ncol0 + nt*8 + q*2;
                    float v0 = acc[nt][half*2], v1 = acc[nt][half*2+1];
                    pl += v0*s_al[col] + v1*s_al[col+1];
                    pr += v0*s_ar[col] + v1*s_ar[col+1];
                }
                pl += __shfl_xor_sync(0xffffffffu, pl, 1);
                pl += __shfl_xor_sync(0xffffffffu, pl, 2);
                pr += __shfl_xor_sync(0xffffffffu, pr, 1);
                pr += __shfl_xor_sync(0xffffffffu, pr, 2);
                if (q==0){ s_pl[rl][nh]=pl; s_pr[rl][nh]=pr; }
            }
        }
        __syncthreads();
        if (tid<128){
            int row = row0 + tid;
            g_el[row*NH + blockIdx.y] = s_pl[tid][0]+s_pl[tid][1];
            g_er[row*NH + blockIdx.y] = s_pr[tid][0]+s_pr[tid][1];
        }

        // ---- target 1: res ----
        {
            float acc[8][4];
            #pragma unroll
            for (int i=0;i<8;i++){ acc[i][0]=0.f; acc[i][1]=0.f; acc[i][2]=0.f; acc[i][3]=0.f; }
            #pragma unroll
            for (int kk=0;kk<8;kk++){
                const int k0 = kk*16;
                uint32_t aaddr = sb + GA_AH + ((m0+a_r)*136 + k0 + a_c)*2;
                unsigned ahf[4], alf[4];
                ldsm4(ahf, aaddr);
                ldsm4(alf, aaddr + (GA_AL-GA_AH));
                #pragma unroll
                for (int ntp=0;ntp<4;ntp++){
                    uint32_t baddr = sb + GA_BRH + ((ncol0+ntp*16+b4_r)*136 + k0 + b4_c)*2;
                    unsigned bh[4], bl[4];
                    ldsm4(bh, baddr);
                    ldsm4(bl, baddr + (GA_BRL-GA_BRH));
                    float* a0 = acc[ntp*2], *a1 = acc[ntp*2+1];
                    mma_bf16(a0, ahf, bh[0], bh[1]);
                    mma_bf16(a0, ahf, bl[0], bl[1]);
                    mma_bf16(a0, alf, bh[0], bh[1]);
                    mma_bf16(a1, ahf, bh[2], bh[3]);
                    mma_bf16(a1, ahf, bl[2], bl[3]);
                    mma_bf16(a1, alf, bh[2], bh[3]);
                }
            }
            #pragma unroll
            for (int half=0; half<2; half++){
                int row = row0 + m0 + gq + half*8;
                #pragma unroll
                for (int nt=0;nt<8;nt++){
                    int col = col0 + ncol0 + nt*8 + q*2;
                    *(float2*)&g_res[row*HD+col] =
                        make_float2(acc[nt][half*2], acc[nt][half*2+1]);
                }
            }
        }
    }
}

// ---------------- merged edge pass + CSR fill --------------------------------
__global__ __launch_bounds__(256) void k_edgefill(const float* __restrict__ e,
        const int* __restrict__ src, const int* __restrict__ dst,
        const float* __restrict__ W_fe, const float* __restrict__ attn_e){
    __shared__ float ce[NH];
    int wid = threadIdx.x>>5, lane = threadIdx.x&31;
    if (wid < NH){
        float p = 0.f;
        #pragma unroll
        for (int q=0;q<4;q++){
            int d = lane + q*32;
            p += W_fe[wid*HDIM+d]*attn_e[wid*HDIM+d];
        }
        #pragma unroll
        for (int off=16; off; off>>=1) p += __shfl_xor_sync(0xffffffffu, p, off);
        if (lane==0) ce[wid]=p;
    }
    __syncthreads();
    int ei = blockIdx.x*256 + threadIdx.x;
    if (ei >= N_EDGES) return;
    int s = src[ei], d = dst[ei];
    float ev = e[ei];
    float4 els = ((const float4*)g_el)[s];
    float4 erd = ((const float4*)g_er)[d];
    float sc[4];
    sc[0] = els.x + erd.x + ev*ce[0];
    sc[1] = els.y + erd.y + ev*ce[1];
    sc[2] = els.z + erd.z + ev*ce[2];
    sc[3] = els.w + erd.w + ev*ce[3];
    int pos = g_rowptr[d] + atomicAdd(&g_cursor[d], 1);
    g_esrc[pos] = s;
    #pragma unroll
    for (int hh=0;hh<4;hh++){
        float v = sc[hh];
        v = v > 0.f ? v : SLOPE_*v;
        float wv = expf(v);
        atomicAdd(&g_z[d*NH+hh], wv);
        g_wsH[hh*N_EDGES+pos] = wv;
    }
}

// ---------------- CSR scan ----------------------------------------------------
__global__ __launch_bounds__(1024) void k_scan(){
    __shared__ int sm[1024];
    int t = threadIdx.x;
    int base = t*32;
    int s = 0;
    #pragma unroll
    for (int i=0;i<32;i++) s += g_deg[base+i];
    sm[t]=s; __syncthreads();
    for (int off=1; off<1024; off<<=1){
        int v = (t>=off)? sm[t-off] : 0;
        __syncthreads();
        if (t>=off) sm[t]+=v;
        __syncthreads();
    }
    int run = sm[t]-s;
    for (int i=0;i<32;i++){ g_rowptr[base+i]=run; run += g_deg[base+i]; }
    if (t==1023) g_rowptr[N_NODES]=run;
}

// ---------------- aggregation (4x unrolled) ------------------------------------
__global__ __launch_bounds__(256) void k_agg(const float* __restrict__ gat_bias){
    int wid = threadIdx.x>>5, lane = threadIdx.x&31;
    int gw = blockIdx.x*8 + wid;
    int n = gw>>2, hh = gw&3;
    int beg = g_rowptr[n], end = g_rowptr[n+1];
    float zz = g_z[n*NH+hh];
    float zi = zz > 0.f ? 1.f/zz : 1.f;
    float4 acc = make_float4(0,0,0,0);
    const float4* ft4 = (const float4*)g_ft;
    const float* wp = g_wsH + hh*N_EDGES;
    int i = beg;
    for (; i+4<=end; i+=4){
        float w0 = wp[i],     w1 = wp[i+1],   w2 = wp[i+2],   w3 = wp[i+3];
        int   s0 = g_esrc[i], s1 = g_esrc[i+1], s2 = g_esrc[i+2], s3 = g_esrc[i+3];
        float4 v0 = ft4[s0*128 + hh*32 + lane];
        float4 v1 = ft4[s1*128 + hh*32 + lane];
        float4 v2 = ft4[s2*128 + hh*32 + lane];
        float4 v3 = ft4[s3*128 + hh*32 + lane];
        acc.x += w0*v0.x + w1*v1.x + w2*v2.x + w3*v3.x;
        acc.y += w0*v0.y + w1*v1.y + w2*v2.y + w3*v3.y;
        acc.z += w0*v0.z + w1*v1.z + w2*v2.z + w3*v3.z;
        acc.w += w0*v0.w + w1*v1.w + w2*v2.w + w3*v3.w;
    }
    for (; i<end; i++){
        float w0 = wp[i];
        int s0 = g_esrc[i];
        float4 v0 = ft4[s0*128 + hh*32 + lane];
        acc.x = fmaf(w0, v0.x, acc.x);
        acc.y = fmaf(w0, v0.y, acc.y);
        acc.z = fmaf(w0, v0.z, acc.z);
        acc.w = fmaf(w0, v0.w, acc.w);
    }
    int base = n*HD + hh*HDIM + lane*4;
    float4 r  = *(const float4*)&g_res[base];
    float4 bv = *(const float4*)&gat_bias[hh*HDIM + lane*4];
    float4 o;
    o.x = fmaxf(acc.x*zi + r.x + bv.x, 0.f);
    o.y = fmaxf(acc.y*zi + r.y + bv.y, 0.f);
    o.z = fmaxf(acc.z*zi + r.z + bv.z, 0.f);
    o.w = fmaxf(acc.w*zi + r.w + bv.w, 0.f);
    *(float4*)&g_res[base] = o;
}

// ---------------- MHA: m16n64 warp tiles + relu + residual + LN1 -------------
__global__ __launch_bounds__(512,1) void k_mha_mma(const float* __restrict__ bm,
        const float* __restrict__ h0, const float* __restrict__ g1,
        const float* __restrict__ be1){
    extern __shared__ char smem[];
    __shared__ float s_s1[128][2], s_s2[128][2];
    __nv_bfloat16* ah_s = (__nv_bfloat16*)(smem+GA_AH);
    __nv_bfloat16* al_s = (__nv_bfloat16*)(smem+GA_AL);
    const uint32_t sb = smem_u32(smem);
    const int tid = threadIdx.x, lane = tid&31, w = tid>>5;
    const int strip = w>>1, nh = w&1;
    const int m0 = strip*16, ncol0 = nh*64;
    const int row0 = blockIdx.x*128;

    const int a_r = lane & 15, a_c = (lane & 16) >> 1;
    const int b4_r = (lane & 7) + ((lane & 16) >> 1);
    const int b4_c = lane & 8;
    const int q = lane & 3, gq = lane >> 2;

    float acc[8][4];
    #pragma unroll
    for (int i=0;i<8;i++){ acc[i][0]=0.f; acc[i][1]=0.f; acc[i][2]=0.f; acc[i][3]=0.f; }

    for (int c=0; c<4; c++){
        __syncthreads();
        for (int i=tid;i<4096;i+=512){
            int m = i>>5, k4 = (i&31)*4;
            float4 v = *(const float4*)&g_res[(row0+m)*HD + c*128 + k4];
            __nv_bfloat162 hh, ll;
            bsplit(v.x, hh.x, ll.x); bsplit(v.y, hh.y, ll.y);
            *(__nv_bfloat162*)&ah_s[m*136+k4]   = hh;
            *(__nv_bfloat162*)&al_s[m*136+k4]   = ll;
            bsplit(v.z, hh.x, ll.x); bsplit(v.w, hh.y, ll.y);
            *(__nv_bfloat162*)&ah_s[m*136+k4+2] = hh;
            *(__nv_bfloat162*)&al_s[m*136+k4+2] = ll;
        }
        {
            const uint4* sh = (const uint4*)(g_wmth + c*128*136);
            const uint4* sl = (const uint4*)(g_wmtl + c*128*136);
            uint4* th = (uint4*)(smem+GA_BFH);
            uint4* tl = (uint4*)(smem+GA_BFL);
            for (int i=tid;i<2176;i+=512){ th[i]=sh[i]; tl[i]=sl[i]; }
        }
        __syncthreads();
        #pragma unroll
        for (int kk=0;kk<8;kk++){
            const int k0 = kk*16;
            uint32_t aaddr = sb + GA_AH + ((m0+a_r)*136 + k0 + a_c)*2;
            unsigned ahf[4], alf[4];
            ldsm4(ahf, aaddr);
            ldsm4(alf, aaddr + (GA_AL-GA_AH));
            #pragma unroll
            for (int ntp=0;ntp<4;ntp++){
                uint32_t baddr = sb + GA_BFH + ((ncol0+ntp*16+b4_r)*136 + k0 + b4_c)*2;
                unsigned bh[4], bl[4];
                ldsm4(bh, baddr);
                ldsm4(bl, baddr + (GA_BFL-GA_BFH));
                float* a0 = acc[ntp*2], *a1 = acc[ntp*2+1];
                mma_bf16(a0, ahf, bh[0], bh[1]);
                mma_bf16(a0, ahf, bl[0], bl[1]);
                mma_bf16(a0, alf, bh[0], bh[1]);
                mma_bf16(a1, ahf, bh[2], bh[3]);
                mma_bf16(a1, ahf, bl[2], bl[3]);
                mma_bf16(a1, alf, bh[2], bh[3]);
            }
        }
    }

    #pragma unroll
    for (int half=0; half<2; half++){
        int rl = m0 + gq + half*8;
        int row = row0 + rl;
        float tv[16], s1=0.f, s2=0.f;
        #pragma unroll
        for (int nt=0;nt<8;nt++){
            int col = ncol0 + nt*8 + q*2;
            float t0 = fmaxf(acc[nt][half*2+0] + bm[col],   0.f) + h0[row*HID_+col];
            float t1 = fmaxf(acc[nt][half*2+1] + bm[col+1], 0.f) + h0[row*HID_+col+1];
            tv[nt*2]=t0; tv[nt*2+1]=t1;
            s1 += t0+t1; s2 += t0*t0+t1*t1;
        }
        s1 += __shfl_xor_sync(0xffffffffu, s1, 1); s2 += __shfl_xor_sync(0xffffffffu, s2, 1);
        s1 += __shfl_xor_sync(0xffffffffu, s1, 2); s2 += __shfl_xor_sync(0xffffffffu, s2, 2);
        if (q==0){ s_s1[rl][nh]=s1; s_s2[rl][nh]=s2; }
        __syncthreads();
        float fs1 = s_s1[rl][0]+s_s1[rl][1];
        float fs2 = s_s2[rl][0]+s_s2[rl][1];
        float mean = fs1*(1.f/HID_);
        float var  = fs2*(1.f/HID_) - mean*mean;
        float rs   = rsqrtf(var + EPS_);
        #pragma unroll
        for (int nt=0;nt<8;nt++){
            int col = ncol0 + nt*8 + q*2;
            g_x1[row*HID_+col]   = (tv[nt*2]  -mean)*rs*g1[col]   + be1[col];
            g_x1[row*HID_+col+1] = (tv[nt*2+1]-mean)*rs*g1[col+1] + be1[col+1];
        }
        __syncthreads();
    }
}

// ---------------- FFN: m16 warp tiles + W2 double-buffer cp.async ------------
#define SM_XS_H 0
#define SM_XS_L 34816
#define SM_W1H  69632
#define SM_W1L  87040
#define SM_W2H  104448
#define SM_W2L  122880
#define SM_MIDH 141312
#define SM_MIDL 159744
#define SM_W2H2 178176
#define SM_W2L2 196608
#define SMEM_FFN 215040

__global__ __launch_bounds__(512,1) void k_ffn_mma(const float* __restrict__ b1v,
        const float* __restrict__ b2v, const float* __restrict__ g2,
        const float* __restrict__ be2, float* __restrict__ out){
    extern __shared__ char smem[];
    __shared__ float s_s1[128][2], s_s2[128][2];
    __nv_bfloat16* xs_h = (__nv_bfloat16*)(smem+SM_XS_H);
    __nv_bfloat16* xs_l = (__nv_bfloat16*)(smem+SM_XS_L);
    __nv_bfloat16* mid_h= (__nv_bfloat16*)(smem+SM_MIDH);
    __nv_bfloat16* mid_l= (__nv_bfloat16*)(smem+SM_MIDL);
    const uint32_t sb = smem_u32(smem);
    const int tid = threadIdx.x, lane = tid&31, w = tid>>5;
    const int strip = w>>1, nh = w&1;
    const int m0 = strip*16;
    const int row0 = blockIdx.x*128;

    for (int i=tid;i<128*128;i+=512){
        int m=i>>7, k=i&127;
        float v = g_x1[(row0+m)*HID_ + k];
        __nv_bfloat16 hv, lv; bsplit(v, hv, lv);
        xs_h[m*136+k] = hv;
        xs_l[m*136+k] = lv;
    }

    float acc2[8][4];
    #pragma unroll
    for (int i=0;i<8;i++){ acc2[i][0]=0.f; acc2[i][1]=0.f; acc2[i][2]=0.f; acc2[i][3]=0.f; }

    const int a_r = lane & 15, a_c = (lane & 16) >> 1;
    const int b4_r = (lane & 7) + ((lane & 16) >> 1);
    const int b4_c = lane & 8;
    const int q = lane & 3, gq = lane >> 2;

    // prefetch W2[0] into buffer 0
    {
        const uint4* s2h = (const uint4*)(g_w2th);
        const uint4* s2l = (const uint4*)(g_w2tl);
        for (int i=tid;i<1152;i+=512){
            cpa16(sb + SM_W2H + i*16, s2h+i);
            cpa16(sb + SM_W2L + i*16, s2l+i);
        }
        CPA_COMMIT();
    }

    for (int c=0; c<32; c++){
        const int cur = c & 1;
        __syncthreads();   // prior GEMM2 done (mid/W2 buffers reusable)
        // prefetch W2[c+1] into other buffer
        if (c+1 < 32){
            uint32_t dh = cur ? (uint32_t)SM_W2H : (uint32_t)SM_W2H2;
            uint32_t dl = cur ? (uint32_t)SM_W2L : (uint32_t)SM_W2L2;
            const uint4* s2h = (const uint4*)(g_w2th + (c+1)*128*72);
            const uint4* s2l = (const uint4*)(g_w2tl + (c+1)*128*72);
            for (int i=tid;i<1152;i+=512){
                cpa16(sb + dh + i*16, s2h+i);
                cpa16(sb + dl + i*16, s2l+i);
            }
            CPA_COMMIT();
        }
        // synchronous W1[c] copy
        {
            const uint4* s1h = (const uint4*)(g_w1th + c*64*136);
            const uint4* s1l = (const uint4*)(g_w1tl + c*64*136);
            uint4* t1h = (uint4*)(smem+SM_W1H); uint4* t1l = (uint4*)(smem+SM_W1L);
            for (int i=tid;i<1088;i+=512){ t1h[i]=s1h[i]; t1l[i]=s1l[i]; }
        }
        __syncthreads();

        // GEMM1: mid[128x64]; warp rows m0..+15, mid cols nh*32..+31
        float acc1[4][4];
        #pragma unroll
        for (int i=0;i<4;i++){ acc1[i][0]=0.f; acc1[i][1]=0.f; acc1[i][2]=0.f; acc1[i][3]=0.f; }
        #pragma unroll
        for (int kk=0;kk<8;kk++){
            const int k0 = kk*16;
            uint32_t aaddr = sb + SM_XS_H + ((m0+a_r)*136 + k0 + a_c)*2;
            unsigned ah[4], al[4];
            ldsm4(ah, aaddr);
            ldsm4(al, aaddr + (SM_XS_L - SM_XS_H));
            #pragma unroll
            for (int ntp=0;ntp<2;ntp++){
                uint32_t baddr = sb + SM_W1H + ((nh*32+ntp*16+b4_r)*136 + k0 + b4_c)*2;
                unsigned bh[4], bl[4];
                ldsm4(bh, baddr);
                ldsm4(bl, baddr + (SM_W1L - SM_W1H));
                float* a0 = acc1[ntp*2], *a1 = acc1[ntp*2+1];
                mma_bf16(a0, ah, bh[0], bh[1]);
                mma_bf16(a0, ah, bl[0], bl[1]);
                mma_bf16(a0, al, bh[0], bh[1]);
                mma_bf16(a1, ah, bh[2], bh[3]);
                mma_bf16(a1, ah, bl[2], bl[3]);
                mma_bf16(a1, al, bh[2], bh[3]);
            }
        }
        {
            const int r1 = m0 + gq, r2 = r1 + 8;
            #pragma unroll
            for (int nt=0;nt<2;nt++){
                int col = nh*32 + nt*8 + q*2;
                float bb0 = b1v[c*64+col], bb1 = b1v[c*64+col+1];
                float v0 = fmaxf(acc1[nt][0]+bb0, 0.f);
                float v1 = fmaxf(acc1[nt][1]+bb1, 0.f);
                float v2 = fmaxf(acc1[nt][2]+bb0, 0.f);
                float v3 = fmaxf(acc1[nt][3]+bb1, 0.f);
                __nv_bfloat162 hh, ll;
                bsplit(v0, hh.x, ll.x); bsplit(v1, hh.y, ll.y);
                *(__nv_bfloat162*)&mid_h[r1*72+col]=hh;
                *(__nv_bfloat162*)&mid_l[r1*72+col]=ll;
                bsplit(v2, hh.x, ll.x); bsplit(v3, hh.y, ll.y);
                *(__nv_bfloat162*)&mid_h[r2*72+col]=hh;
                *(__nv_bfloat162*)&mid_l[r2*72+col]=ll;
            }
            #pragma unroll
            for (int nt=2;nt<4;nt++){
                int col = nh*32 + (nt-2)*8 + 16 + q*2;
                float bb0 = b1v[c*64+col], bb1 = b1v[c*64+col+1];
                float v0 = fmaxf(acc1[nt][0]+bb0, 0.f);
                float v1 = fmaxf(acc1[nt][1]+bb1, 0.f);
                float v2 = fmaxf(acc1[nt][2]+bb0, 0.f);
                float v3 = fmaxf(acc1[nt][3]+bb1, 0.f);
                __nv_bfloat162 hh, ll;
                bsplit(v0, hh.x, ll.x); bsplit(v1, hh.y, ll.y);
                *(__nv_bfloat162*)&mid_h[r1*72+col]=hh;
                *(__nv_bfloat162*)&mid_l[r1*72+col]=ll;
                bsplit(v2, hh.x, ll.x); bsplit(v3, hh.y, ll.y);
                *(__nv_bfloat162*)&mid_h[r2*72+col]=hh;
                *(__nv_bfloat162*)&mid_l[r2*72+col]=ll;
            }
        }
        // wait W2[c] arrival (allow W2[c+1] still in flight), then sync
        if (c+1 < 32) CPA_WAIT1(); else CPA_WAIT0();
        __syncthreads();

        // GEMM2: acc2 += mid[m0..+15][64] @ W2^T ; out cols nh*64..+63
        const uint32_t w2h_base = cur ? (uint32_t)SM_W2H2 : (uint32_t)SM_W2H;
        #pragma unroll
        for (int kk=0;kk<4;kk++){
            const int k0 = kk*16;
            uint32_t aaddr = sb + SM_MIDH + ((m0+a_r)*72 + k0 + a_c)*2;
            unsigned ah[4], al[4];
            ldsm4(ah, aaddr);
            ldsm4(al, aaddr + (SM_MIDL - SM_MIDH));
            #pragma unroll
            for (int ntp=0;ntp<4;ntp++){
                uint32_t baddr = sb + w2h_base + ((nh*64+ntp*16+b4_r)*72 + k0 + b4_c)*2;
                unsigned bh[4], bl[4];
                ldsm4(bh, baddr);
                ldsm4(bl, baddr + 18432);
                float* a0 = acc2[ntp*2], *a1 = acc2[ntp*2+1];
                mma_bf16(a0, ah, bh[0], bh[1]);
                mma_bf16(a0, ah, bl[0], bl[1]);
                mma_bf16(a0, al, bh[0], bh[1]);
                mma_bf16(a1, ah, bh[2], bh[3]);
                mma_bf16(a1, ah, bl[2], bl[3]);
                mma_bf16(a1, al, bh[2], bh[3]);
            }
        }
    }

    // epilogue: +b2 + residual + LN2
    #pragma unroll
    for (int half=0; half<2; half++){
        int rl = m0 + gq + half*8;
        int grow = row0 + rl;
        float tv[16], s1=0.f, s2=0.f;
        #pragma unroll
        for (int nt=0;nt<8;nt++){
            int col = nh*64 + nt*8 + q*2;
            float t0 = acc2[nt][half*2+0] + b2v[col]   + g_x1[grow*HID_+col];
            float t1 = acc2[nt][half*2+1] + b2v[col+1] + g_x1[grow*HID_+col+1];
            tv[nt*2]=t0; tv[nt*2+1]=t1;
            s1 += t0+t1; s2 += t0*t0+t1*t1;
        }
        s1 += __shfl_xor_sync(0xffffffffu, s1, 1); s2 += __shfl_xor_sync(0xffffffffu, s2, 1);
        s1 += __shfl_xor_sync(0xffffffffu, s1, 2); s2 += __shfl_xor_sync(0xffffffffu, s2, 2);
        if (q==0){ s_s1[rl][nh]=s1; s_s2[rl][nh]=s2; }
        __syncthreads();
        float fs1 = s_s1[rl][0]+s_s1[rl][1];
        float fs2 = s_s2[rl][0]+s_s2[rl][1];
        float mean = fs1*(1.f/HID_);
        float var  = fs2*(1.f/HID_) - mean*mean;
        float rs   = rsqrtf(var + EPS_);
        #pragma unroll
        for (int nt=0;nt<8;nt++){
            int col = nh*64 + nt*8 + q*2;
            out[grow*HID_+col]   = (tv[nt*2]  -mean)*rs*g2[col]   + be2[col];
            out[grow*HID_+col+1] = (tv[nt*2+1]-mean)*rs*g2[col+1] + be2[col+1];
        }
        __syncthreads();
    }
}

// ---------------- launch ----------------------------------------------------
extern "C" void kernel_launch(void* const* d_in, const int* in_sizes, int n_in,
                              void* d_out, int out_size){
    int o = (in_sizes[4] == 1) ? 1 : 0;
    const float* h       = (const float*)d_in[0];
    const float* e       = (const float*)d_in[1];
    const int*   src     = (const int*)  d_in[2];
    const int*   dst     = (const int*)  d_in[3];
    const float* W_fc    = (const float*)d_in[4+o];
    const float* attn_l  = (const float*)d_in[5+o];
    const float* attn_r  = (const float*)d_in[6+o];
    const float* W_fe    = (const float*)d_in[7+o];
    const float* attn_e  = (const float*)d_in[8+o];
    const float* W_res   = (const float*)d_in[9+o];
    const float* gatb    = (const float*)d_in[10+o];
    const float* W_mha   = (const float*)d_in[11+o];
    const float* b_mha   = (const float*)d_in[12+o];
    const float* n1_g    = (const float*)d_in[13+o];
    const float* n1_b    = (const float*)d_in[14+o];
    const float* n2_g    = (const float*)d_in[15+o];
    const float* n2_b    = (const float*)d_in[16+o];
    const float* W1      = (const float*)d_in[17+o];
    const float* b1      = (const float*)d_in[18+o];
    const float* W2      = (const float*)d_in[19+o];
    const float* b2      = (const float*)d_in[20+o];
    float* out = (float*)d_out;

    cudaFuncSetAttribute(k_ffn_mma,  cudaFuncAttributeMaxDynamicSharedMemorySize, SMEM_FFN);
    cudaFuncSetAttribute(k_gemmA_mma,cudaFuncAttributeMaxDynamicSharedMemorySize, SMEM_GA);
    cudaFuncSetAttribute(k_mha_mma,  cudaFuncAttributeMaxDynamicSharedMemorySize, SMEM_MH);

    k_init<<<512,256>>>();
    k_prep<<<1024,256>>>(W1, W2, W_fc, W_res, W_mha);
    k_deg<<<N_EDGES/256,256>>>(dst);
    dim3 gA(64, 4);
    k_gemmA_mma<<<gA,512,SMEM_GA>>>(h, attn_l, attn_r);
    k_scan<<<1,1024>>>();
    k_edgefill<<<N_EDGES/256,256>>>(e, src, dst, W_fe, attn_e);
    k_agg<<<N_NODES*NH/8,256>>>(gatb);
    k_mha_mma<<<N_NODES/128,512,SMEM_MH>>>(b_mha, h, n1_g, n1_b);
    k_ffn_mma<<<N_NODES/128,512,SMEM_FFN>>>(b1, b2, n2_g, n2_b, out);
}

// round 12
// speedup vs baseline: 1.1761x; 1.0691x over previous
#include <cuda_runtime.h>
#include <cuda_bf16.h>
#include <cstdint>

#define N_NODES 32768
#define N_EDGES 524288
#define NH      4
#define HDIM    128
#define HD      512
#define HID_    128
#define DFF_    2048
#define SLOPE_  0.2f
#define EPS_    1e-5f

// ---------------- scratch ----------------------------------------------------
__device__ float    g_ft [N_NODES*HD];
__device__ float    g_res[N_NODES*HD];
__device__ float    g_el [N_NODES*NH];
__device__ float    g_er [N_NODES*NH];
__device__ float    g_z  [N_NODES*NH];
__device__ int      g_deg[N_NODES];
__device__ int      g_cursor[N_NODES];
__device__ int      g_rowptr[N_NODES+1];
__device__ int      g_esrc[N_EDGES];
__device__ float    g_wsH[NH*N_EDGES];
__device__ float    g_x1 [N_NODES*HID_];

// pre-split activations (bf16 hi/lo, 136-padded rows for ldsm staging)
__device__ __align__(16) __nv_bfloat16 g_hh  [N_NODES*136];
__device__ __align__(16) __nv_bfloat16 g_hl  [N_NODES*136];
__device__ __align__(16) __nv_bfloat16 g_resh[N_NODES*544];   // 4 chunks x 136
__device__ __align__(16) __nv_bfloat16 g_resl[N_NODES*544];
__device__ __align__(16) __nv_bfloat16 g_x1h [N_NODES*136];
__device__ __align__(16) __nv_bfloat16 g_x1l [N_NODES*136];

// pre-split hi/lo bf16 transposed weights ([n][k] padded rows)
__device__ __align__(16) __nv_bfloat16 g_w1th[32*64*136];
__device__ __align__(16) __nv_bfloat16 g_w1tl[32*64*136];
__device__ __align__(16) __nv_bfloat16 g_w2th[32*128*72];
__device__ __align__(16) __nv_bfloat16 g_w2tl[32*128*72];
__device__ __align__(16) __nv_bfloat16 g_wfth[512*136];
__device__ __align__(16) __nv_bfloat16 g_wftl[512*136];
__device__ __align__(16) __nv_bfloat16 g_wrth[512*136];
__device__ __align__(16) __nv_bfloat16 g_wrtl[512*136];
__device__ __align__(16) __nv_bfloat16 g_wmth[512*136];
__device__ __align__(16) __nv_bfloat16 g_wmtl[512*136];

// ---------------- helpers ------------------------------------------------------
__device__ __forceinline__ uint32_t smem_u32(const void* p){
    uint32_t a;
    asm("{ .reg .u64 t; cvta.to.shared.u64 t, %1; cvt.u32.u64 %0, t; }" : "=r"(a) : "l"(p));
    return a;
}
__device__ __forceinline__ void ldsm4(unsigned* r, uint32_t addr){
    asm volatile("ldmatrix.sync.aligned.m8n8.x4.shared.b16 {%0,%1,%2,%3}, [%4];"
        : "=r"(r[0]),"=r"(r[1]),"=r"(r[2]),"=r"(r[3]) : "r"(addr));
}
__device__ __forceinline__ void mma_bf16(float* c, const unsigned* a, unsigned b0, unsigned b1){
    asm volatile("mma.sync.aligned.m16n8k16.row.col.f32.bf16.bf16.f32 "
        "{%0,%1,%2,%3},{%4,%5,%6,%7},{%8,%9},{%0,%1,%2,%3};"
        : "+f"(c[0]),"+f"(c[1]),"+f"(c[2]),"+f"(c[3])
        : "r"(a[0]),"r"(a[1]),"r"(a[2]),"r"(a[3]),"r"(b0),"r"(b1));
}
__device__ __forceinline__ void bsplit(float v, __nv_bfloat16& hi, __nv_bfloat16& lo){
    hi = __float2bfloat16(v);
    lo = __float2bfloat16(v - __bfloat162float(hi));
}
__device__ __forceinline__ void cpa16(uint32_t saddr, const void* g){
    asm volatile("cp.async.cg.shared.global [%0], [%1], 16;" :: "r"(saddr), "l"(g));
}
#define CPA_COMMIT() asm volatile("cp.async.commit_group;" ::: "memory")
#define CPA_WAIT1()  asm volatile("cp.async.wait_group 1;" ::: "memory")
#define CPA_WAIT0()  asm volatile("cp.async.wait_group 0;" ::: "memory")

// ---------------- init ------------------------------------------------------
__global__ void k_init(){
    int i = blockIdx.x*256 + threadIdx.x;
    g_z[i] = 0.f;
    if (i < N_NODES){ g_deg[i] = 0; g_cursor[i] = 0; }
}

// ---------------- prep --------------------------------------------------------
__global__ void k_prep(const float* __restrict__ W1, const float* __restrict__ W2,
                       const float* __restrict__ Wfc, const float* __restrict__ Wres,
                       const float* __restrict__ Wm, const float* __restrict__ h){
    int i = blockIdx.x*256 + threadIdx.x;   // 262144 threads
    {   // W1 [k=128][n=2048]
        int k = i >> 11, n = i & 2047;
        __nv_bfloat16 hv, lv; bsplit(W1[i], hv, lv);
        int c = n >> 6, nn = n & 63;
        g_w1th[(c*64+nn)*136 + k] = hv;
        g_w1tl[(c*64+nn)*136 + k] = lv;
    }
    {   // W2 [k2=2048][n=128]
        int k2 = i >> 7, n = i & 127;
        __nv_bfloat16 hv, lv; bsplit(W2[i], hv, lv);
        int c = k2 >> 6, kk = k2 & 63;
        g_w2th[(c*128+n)*72 + kk] = hv;
        g_w2tl[(c*128+n)*72 + kk] = lv;
    }
    // h split: 4.19M elements, 16 per thread
    #pragma unroll
    for (int j=0;j<16;j++){
        int idx = i + j*262144;
        int n = idx >> 7, k = idx & 127;
        __nv_bfloat16 hv, lv; bsplit(h[idx], hv, lv);
        g_hh[n*136+k] = hv;
        g_hl[n*136+k] = lv;
    }
    if (i < 65536){
        {   // Wfc/Wres [k=128][n=512]
            int k = i >> 9, n = i & 511;
            __nv_bfloat16 hv, lv;
            bsplit(Wfc[i], hv, lv);
            g_wfth[n*136 + k] = hv; g_wftl[n*136 + k] = lv;
            bsplit(Wres[i], hv, lv);
            g_wrth[n*136 + k] = hv; g_wrtl[n*136 + k] = lv;
        }
        {   // Wm [k2=512][n=128]
            int k2 = i >> 7, n = i & 127;
            __nv_bfloat16 hv, lv; bsplit(Wm[i], hv, lv);
            int c = k2 >> 7, kk = k2 & 127;
            g_wmth[(c*128+n)*136 + kk] = hv;
            g_wmtl[(c*128+n)*136 + kk] = lv;
        }
    }
}

// ---------------- degree count ------------------------------------------------
__global__ __launch_bounds__(256) void k_deg(const int* __restrict__ dst){
    int ei = blockIdx.x*256 + threadIdx.x;
    if (ei < N_EDGES) atomicAdd(&g_deg[dst[ei]], 1);
}

// ---------------- GEMM A: m16n64 warp tiles, both weights, cp.async A --------
#define GA_AH  0
#define GA_AL  34816
#define GA_BFH 69632
#define GA_BFL 104448
#define GA_BRH 139264
#define GA_BRL 174080
#define SMEM_GA 208896

__global__ __launch_bounds__(512,1) void k_gemmA_mma(
        const float* __restrict__ attn_l, const float* __restrict__ attn_r){
    extern __shared__ char smem[];
    __shared__ float s_al[128], s_ar[128];
    __shared__ float s_pl[128][2], s_pr[128][2];
    const uint32_t sb = smem_u32(smem);
    const int tid = threadIdx.x, lane = tid&31, w = tid>>5;
    const int strip = w>>1, nh = w&1;
    const int m0 = strip*16, ncol0 = nh*64;
    const int col0 = blockIdx.y*128;

    if (tid<128){
        s_al[tid] = attn_l[col0+tid];
        s_ar[tid] = attn_r[col0+tid];
    }
    {   // load both B tiles
        const uint4* fh = (const uint4*)(g_wfth + col0*136);
        const uint4* fl = (const uint4*)(g_wftl + col0*136);
        const uint4* rh = (const uint4*)(g_wrth + col0*136);
        const uint4* rl = (const uint4*)(g_wrtl + col0*136);
        uint4* tfh = (uint4*)(smem+GA_BFH);
        uint4* tfl = (uint4*)(smem+GA_BFL);
        uint4* trh = (uint4*)(smem+GA_BRH);
        uint4* trl = (uint4*)(smem+GA_BRL);
        for (int i=tid;i<2176;i+=512){
            tfh[i]=fh[i]; tfl[i]=fl[i]; trh[i]=rh[i]; trl[i]=rl[i];
        }
    }

    const int a_r = lane & 15, a_c = (lane & 16) >> 1;
    const int b4_r = (lane & 7) + ((lane & 16) >> 1);
    const int b4_c = lane & 8;
    const int q = lane & 3, gq = lane >> 2;

    for (int rt=0; rt<4; rt++){
        const int row0 = (blockIdx.x*4+rt)*128;
        __syncthreads();
        {   // A tile hi/lo via cp.async (flat copy, pre-split)
            const char* sh = (const char*)g_hh + row0*272;
            const char* sl = (const char*)g_hl + row0*272;
            for (int i=tid;i<2176;i+=512){
                cpa16(sb + GA_AH + i*16, sh + i*16);
                cpa16(sb + GA_AL + i*16, sl + i*16);
            }
            CPA_COMMIT();
            CPA_WAIT0();
        }
        __syncthreads();

        // ---- target 0: ft (+ el/er partials) ----
        {
            float acc[8][4];
            #pragma unroll
            for (int i=0;i<8;i++){ acc[i][0]=0.f; acc[i][1]=0.f; acc[i][2]=0.f; acc[i][3]=0.f; }
            #pragma unroll
            for (int kk=0;kk<8;kk++){
                const int k0 = kk*16;
                uint32_t aaddr = sb + GA_AH + ((m0+a_r)*136 + k0 + a_c)*2;
                unsigned ahf[4], alf[4];
                ldsm4(ahf, aaddr);
                ldsm4(alf, aaddr + (GA_AL-GA_AH));
                #pragma unroll
                for (int ntp=0;ntp<4;ntp++){
                    uint32_t baddr = sb + GA_BFH + ((ncol0+ntp*16+b4_r)*136 + k0 + b4_c)*2;
                    unsigned bh[4], bl[4];
                    ldsm4(bh, baddr);
                    ldsm4(bl, baddr + (GA_BFL-GA_BFH));
                    float* a0 = acc[ntp*2], *a1 = acc[ntp*2+1];
                    mma_bf16(a0, ahf, bh[0], bh[1]);
                    mma_bf16(a0, ahf, bl[0], bl[1]);
                    mma_bf16(a0, alf, bh[0], bh[1]);
                    mma_bf16(a1, ahf, bh[2], bh[3]);
                    mma_bf16(a1, ahf, bl[2], bl[3]);
                    mma_bf16(a1, alf, bh[2], bh[3]);
                }
            }
            #pragma unroll
            for (int half=0; half<2; half++){
                int row = row0 + m0 + gq + half*8;
                #pragma unroll
                for (int nt=0;nt<8;nt++){
                    int col = col0 + ncol0 + nt*8 + q*2;
                    *(float2*)&g_ft[row*HD+col] =
                        make_float2(acc[nt][half*2], acc[nt][half*2+1]);
                }
            }
            #pragma unroll
            for (int half=0; half<2; half++){
                int rl = m0 + gq + half*8;
                float pl=0.f, pr=0.f;
                #pragma unroll
                for (int nt=0;nt<8;nt++){
                    int col = ncol0 + nt*8 + q*2;
                    float v0 = acc[nt][half*2], v1 = acc[nt][half*2+1];
                    pl += v0*s_al[col] + v1*s_al[col+1];
                    pr += v0*s_ar[col] + v1*s_ar[col+1];
                }
                pl += __shfl_xor_sync(0xffffffffu, pl, 1);
                pl += __shfl_xor_sync(0xffffffffu, pl, 2);
                pr += __shfl_xor_sync(0xffffffffu, pr, 1);
                pr += __shfl_xor_sync(0xffffffffu, pr, 2);
                if (q==0){ s_pl[rl][nh]=pl; s_pr[rl][nh]=pr; }
            }
        }
        __syncthreads();
        if (tid<128){
            int row = row0 + tid;
            g_el[row*NH + blockIdx.y] = s_pl[tid][0]+s_pl[tid][1];
            g_er[row*NH + blockIdx.y] = s_pr[tid][0]+s_pr[tid][1];
        }

        // ---- target 1: res ----
        {
            float acc[8][4];
            #pragma unroll
            for (int i=0;i<8;i++){ acc[i][0]=0.f; acc[i][1]=0.f; acc[i][2]=0.f; acc[i][3]=0.f; }
            #pragma unroll
            for (int kk=0;kk<8;kk++){
                const int k0 = kk*16;
                uint32_t aaddr = sb + GA_AH + ((m0+a_r)*136 + k0 + a_c)*2;
                unsigned ahf[4], alf[4];
                ldsm4(ahf, aaddr);
                ldsm4(alf, aaddr + (GA_AL-GA_AH));
                #pragma unroll
                for (int ntp=0;ntp<4;ntp++){
                    uint32_t baddr = sb + GA_BRH + ((ncol0+ntp*16+b4_r)*136 + k0 + b4_c)*2;
                    unsigned bh[4], bl[4];
                    ldsm4(bh, baddr);
                    ldsm4(bl, baddr + (GA_BRL-GA_BRH));
                    float* a0 = acc[ntp*2], *a1 = acc[ntp*2+1];
                    mma_bf16(a0, ahf, bh[0], bh[1]);
                    mma_bf16(a0, ahf, bl[0], bl[1]);
                    mma_bf16(a0, alf, bh[0], bh[1]);
                    mma_bf16(a1, ahf, bh[2], bh[3]);
                    mma_bf16(a1, ahf, bl[2], bl[3]);
                    mma_bf16(a1, alf, bh[2], bh[3]);
                }
            }
            #pragma unroll
            for (int half=0; half<2; half++){
                int row = row0 + m0 + gq + half*8;
                #pragma unroll
                for (int nt=0;nt<8;nt++){
                    int col = col0 + ncol0 + nt*8 + q*2;
                    *(float2*)&g_res[row*HD+col] =
                        make_float2(acc[nt][half*2], acc[nt][half*2+1]);
                }
            }
        }
    }
}

// ---------------- merged edge pass + CSR fill --------------------------------
__global__ __launch_bounds__(256) void k_edgefill(const float* __restrict__ e,
        const int* __restrict__ src, const int* __restrict__ dst,
        const float* __restrict__ W_fe, const float* __restrict__ attn_e){
    __shared__ float ce[NH];
    int wid = threadIdx.x>>5, lane = threadIdx.x&31;
    if (wid < NH){
        float p = 0.f;
        #pragma unroll
        for (int q=0;q<4;q++){
            int d = lane + q*32;
            p += W_fe[wid*HDIM+d]*attn_e[wid*HDIM+d];
        }
        #pragma unroll
        for (int off=16; off; off>>=1) p += __shfl_xor_sync(0xffffffffu, p, off);
        if (lane==0) ce[wid]=p;
    }
    __syncthreads();
    int ei = blockIdx.x*256 + threadIdx.x;
    if (ei >= N_EDGES) return;
    int s = src[ei], d = dst[ei];
    float ev = e[ei];
    float4 els = ((const float4*)g_el)[s];
    float4 erd = ((const float4*)g_er)[d];
    float sc[4];
    sc[0] = els.x + erd.x + ev*ce[0];
    sc[1] = els.y + erd.y + ev*ce[1];
    sc[2] = els.z + erd.z + ev*ce[2];
    sc[3] = els.w + erd.w + ev*ce[3];
    int pos = g_rowptr[d] + atomicAdd(&g_cursor[d], 1);
    g_esrc[pos] = s;
    #pragma unroll
    for (int hh=0;hh<4;hh++){
        float v = sc[hh];
        v = v > 0.f ? v : SLOPE_*v;
        float wv = expf(v);
        atomicAdd(&g_z[d*NH+hh], wv);
        g_wsH[hh*N_EDGES+pos] = wv;
    }
}

// ---------------- CSR scan ----------------------------------------------------
__global__ __launch_bounds__(1024) void k_scan(){
    __shared__ int sm[1024];
    int t = threadIdx.x;
    int base = t*32;
    int s = 0;
    #pragma unroll
    for (int i=0;i<32;i++) s += g_deg[base+i];
    sm[t]=s; __syncthreads();
    for (int off=1; off<1024; off<<=1){
        int v = (t>=off)? sm[t-off] : 0;
        __syncthreads();
        if (t>=off) sm[t]+=v;
        __syncthreads();
    }
    int run = sm[t]-s;
    for (int i=0;i<32;i++){ g_rowptr[base+i]=run; run += g_deg[base+i]; }
    if (t==1023) g_rowptr[N_NODES]=run;
}

// ---------------- aggregation: writes bf16 hi/lo split -------------------------
__global__ __launch_bounds__(256) void k_agg(const float* __restrict__ gat_bias){
    int wid = threadIdx.x>>5, lane = threadIdx.x&31;
    int gw = blockIdx.x*8 + wid;
    int n = gw>>2, hh = gw&3;
    int beg = g_rowptr[n], end = g_rowptr[n+1];
    float zz = g_z[n*NH+hh];
    float zi = zz > 0.f ? 1.f/zz : 1.f;
    float4 acc = make_float4(0,0,0,0);
    const float4* ft4 = (const float4*)g_ft;
    const float* wp = g_wsH + hh*N_EDGES;
    int i = beg;
    for (; i+4<=end; i+=4){
        float w0 = wp[i],     w1 = wp[i+1],   w2 = wp[i+2],   w3 = wp[i+3];
        int   s0 = g_esrc[i], s1 = g_esrc[i+1], s2 = g_esrc[i+2], s3 = g_esrc[i+3];
        float4 v0 = ft4[s0*128 + hh*32 + lane];
        float4 v1 = ft4[s1*128 + hh*32 + lane];
        float4 v2 = ft4[s2*128 + hh*32 + lane];
        float4 v3 = ft4[s3*128 + hh*32 + lane];
        acc.x += w0*v0.x + w1*v1.x + w2*v2.x + w3*v3.x;
        acc.y += w0*v0.y + w1*v1.y + w2*v2.y + w3*v3.y;
        acc.z += w0*v0.z + w1*v1.z + w2*v2.z + w3*v3.z;
        acc.w += w0*v0.w + w1*v1.w + w2*v2.w + w3*v3.w;
    }
    for (; i<end; i++){
        float w0 = wp[i];
        int s0 = g_esrc[i];
        float4 v0 = ft4[s0*128 + hh*32 + lane];
        acc.x = fmaf(w0, v0.x, acc.x);
        acc.y = fmaf(w0, v0.y, acc.y);
        acc.z = fmaf(w0, v0.z, acc.z);
        acc.w = fmaf(w0, v0.w, acc.w);
    }
    int base = n*HD + hh*HDIM + lane*4;
    float4 r  = *(const float4*)&g_res[base];
    float4 bv = *(const float4*)&gat_bias[hh*HDIM + lane*4];
    float o0 = fmaxf(acc.x*zi + r.x + bv.x, 0.f);
    float o1 = fmaxf(acc.y*zi + r.y + bv.y, 0.f);
    float o2 = fmaxf(acc.z*zi + r.z + bv.z, 0.f);
    float o3 = fmaxf(acc.w*zi + r.w + bv.w, 0.f);
    // write split bf16 (chunk-major: chunk == head)
    int sbase = n*544 + hh*136 + lane*4;
    __nv_bfloat162 h01, h23, l01, l23;
    bsplit(o0, h01.x, l01.x); bsplit(o1, h01.y, l01.y);
    bsplit(o2, h23.x, l23.x); bsplit(o3, h23.y, l23.y);
    *(__nv_bfloat162*)&g_resh[sbase]   = h01;
    *(__nv_bfloat162*)&g_resh[sbase+2] = h23;
    *(__nv_bfloat162*)&g_resl[sbase]   = l01;
    *(__nv_bfloat162*)&g_resl[sbase+2] = l23;
}

// ---------------- MHA: cp.async A + double-buffered Wm -----------------------
#define MH_AH  0
#define MH_AL  34816
#define MH_W0H 69632
#define MH_W0L 104448
#define MH_W1H 139264
#define MH_W1L 174080
#define SMEM_MH 208896

__global__ __launch_bounds__(512,1) void k_mha_mma(const float* __restrict__ bm,
        const float* __restrict__ h0, const float* __restrict__ g1,
        const float* __restrict__ be1){
    extern __shared__ char smem[];
    __shared__ float s_s1[128][2], s_s2[128][2];
    const uint32_t sb = smem_u32(smem);
    const int tid = threadIdx.x, lane = tid&31, w = tid>>5;
    const int strip = w>>1, nh = w&1;
    const int m0 = strip*16, ncol0 = nh*64;
    const int row0 = blockIdx.x*128;

    const int a_r = lane & 15, a_c = (lane & 16) >> 1;
    const int b4_r = (lane & 7) + ((lane & 16) >> 1);
    const int b4_c = lane & 8;
    const int q = lane & 3, gq = lane >> 2;

    float acc[8][4];
    #pragma unroll
    for (int i=0;i<8;i++){ acc[i][0]=0.f; acc[i][1]=0.f; acc[i][2]=0.f; acc[i][3]=0.f; }

    // prefetch Wm[0] into buf0
    {
        const char* sh = (const char*)g_wmth;
        const char* sl = (const char*)g_wmtl;
        for (int i=tid;i<2176;i+=512){
            cpa16(sb + MH_W0H + i*16, sh + i*16);
            cpa16(sb + MH_W0L + i*16, sl + i*16);
        }
        CPA_COMMIT();
    }

    for (int c=0; c<4; c++){
        const int cur = c & 1;
        __syncthreads();
        {   // A(c) via cp.async from pre-split g_resh/g_resl
            for (int i=tid;i<2176;i+=512){
                int m = i/17, o = i - m*17;
                long so = (long)(row0+m)*1088 + c*272 + o*16;
                cpa16(sb + MH_AH + m*272 + o*16, (const char*)g_resh + so);
                cpa16(sb + MH_AL + m*272 + o*16, (const char*)g_resl + so);
            }
            CPA_COMMIT();
        }
        if (c < 3){   // prefetch Wm[c+1] into alt buffer
            uint32_t dh = cur ? (uint32_t)MH_W0H : (uint32_t)MH_W1H;
            uint32_t dl = cur ? (uint32_t)MH_W0L : (uint32_t)MH_W1L;
            const char* sh = (const char*)(g_wmth + (c+1)*128*136);
            const char* sl = (const char*)(g_wmtl + (c+1)*128*136);
            for (int i=tid;i<2176;i+=512){
                cpa16(sb + dh + i*16, sh + i*16);
                cpa16(sb + dl + i*16, sl + i*16);
            }
            CPA_COMMIT();
            CPA_WAIT1();
        } else {
            CPA_WAIT0();
        }
        __syncthreads();

        const uint32_t wbh = cur ? (uint32_t)MH_W1H : (uint32_t)MH_W0H;
        const uint32_t wbl = cur ? (uint32_t)MH_W1L : (uint32_t)MH_W0L;
        #pragma unroll
        for (int kk=0;kk<8;kk++){
            const int k0 = kk*16;
            uint32_t aaddr = sb + MH_AH + ((m0+a_r)*136 + k0 + a_c)*2;
            unsigned ahf[4], alf[4];
            ldsm4(ahf, aaddr);
            ldsm4(alf, aaddr + (MH_AL-MH_AH));
            #pragma unroll
            for (int ntp=0;ntp<4;ntp++){
                uint32_t boff = ((ncol0+ntp*16+b4_r)*136 + k0 + b4_c)*2;
                unsigned bh[4], bl[4];
                ldsm4(bh, sb + wbh + boff);
                ldsm4(bl, sb + wbl + boff);
                float* a0 = acc[ntp*2], *a1 = acc[ntp*2+1];
                mma_bf16(a0, ahf, bh[0], bh[1]);
                mma_bf16(a0, ahf, bl[0], bl[1]);
                mma_bf16(a0, alf, bh[0], bh[1]);
                mma_bf16(a1, ahf, bh[2], bh[3]);
                mma_bf16(a1, ahf, bl[2], bl[3]);
                mma_bf16(a1, alf, bh[2], bh[3]);
            }
        }
    }

    // epilogue: +bm, relu, +h0, LN1 -> g_x1 (fp32) + g_x1h/g_x1l (bf16 split)
    #pragma unroll
    for (int half=0; half<2; half++){
        int rl = m0 + gq + half*8;
        int row = row0 + rl;
        float tv[16], s1=0.f, s2=0.f;
        #pragma unroll
        for (int nt=0;nt<8;nt++){
            int col = ncol0 + nt*8 + q*2;
            float t0 = fmaxf(acc[nt][half*2+0] + bm[col],   0.f) + h0[row*HID_+col];
            float t1 = fmaxf(acc[nt][half*2+1] + bm[col+1], 0.f) + h0[row*HID_+col+1];
            tv[nt*2]=t0; tv[nt*2+1]=t1;
            s1 += t0+t1; s2 += t0*t0+t1*t1;
        }
        s1 += __shfl_xor_sync(0xffffffffu, s1, 1); s2 += __shfl_xor_sync(0xffffffffu, s2, 1);
        s1 += __shfl_xor_sync(0xffffffffu, s1, 2); s2 += __shfl_xor_sync(0xffffffffu, s2, 2);
        if (q==0){ s_s1[rl][nh]=s1; s_s2[rl][nh]=s2; }
        __syncthreads();
        float fs1 = s_s1[rl][0]+s_s1[rl][1];
        float fs2 = s_s2[rl][0]+s_s2[rl][1];
        float mean = fs1*(1.f/HID_);
        float var  = fs2*(1.f/HID_) - mean*mean;
        float rs   = rsqrtf(var + EPS_);
        #pragma unroll
        for (int nt=0;nt<8;nt++){
            int col = ncol0 + nt*8 + q*2;
            float x0 = (tv[nt*2]  -mean)*rs*g1[col]   + be1[col];
            float x1 = (tv[nt*2+1]-mean)*rs*g1[col+1] + be1[col+1];
            *(float2*)&g_x1[row*HID_+col] = make_float2(x0, x1);
            __nv_bfloat162 hh, ll;
            bsplit(x0, hh.x, ll.x); bsplit(x1, hh.y, ll.y);
            *(__nv_bfloat162*)&g_x1h[row*136+col] = hh;
            *(__nv_bfloat162*)&g_x1l[row*136+col] = ll;
        }
        __syncthreads();
    }
}

// ---------------- FFN: cp.async xs/W1 + W2 double-buffer ----------------------
#define SM_XS_H 0
#define SM_XS_L 34816
#define SM_W1H  69632
#define SM_W1L  87040
#define SM_W2H  104448
#define SM_W2L  122880
#define SM_MIDH 141312
#define SM_MIDL 159744
#define SM_W2H2 178176
#define SM_W2L2 196608
#define SMEM_FFN 215040

__global__ __launch_bounds__(512,1) void k_ffn_mma(const float* __restrict__ b1v,
        const float* __restrict__ b2v, const float* __restrict__ g2,
        const float* __restrict__ be2, float* __restrict__ out){
    extern __shared__ char smem[];
    __shared__ float s_s1[128][2], s_s2[128][2];
    __nv_bfloat16* mid_h= (__nv_bfloat16*)(smem+SM_MIDH);
    __nv_bfloat16* mid_l= (__nv_bfloat16*)(smem+SM_MIDL);
    const uint32_t sb = smem_u32(smem);
    const int tid = threadIdx.x, lane = tid&31, w = tid>>5;
    const int strip = w>>1, nh = w&1;
    const int m0 = strip*16;
    const int row0 = blockIdx.x*128;

    // xs staging via cp.async from pre-split g_x1h/g_x1l
    {
        const char* sh = (const char*)g_x1h + row0*272;
        const char* sl = (const char*)g_x1l + row0*272;
        for (int i=tid;i<2176;i+=512){
            cpa16(sb + SM_XS_H + i*16, sh + i*16);
            cpa16(sb + SM_XS_L + i*16, sl + i*16);
        }
        CPA_COMMIT();
    }
    // prefetch W2[0] into buffer 0
    {
        const uint4* s2h = (const uint4*)(g_w2th);
        const uint4* s2l = (const uint4*)(g_w2tl);
        for (int i=tid;i<1152;i+=512){
            cpa16(sb + SM_W2H + i*16, s2h+i);
            cpa16(sb + SM_W2L + i*16, s2l+i);
        }
        CPA_COMMIT();
    }

    float acc2[8][4];
    #pragma unroll
    for (int i=0;i<8;i++){ acc2[i][0]=0.f; acc2[i][1]=0.f; acc2[i][2]=0.f; acc2[i][3]=0.f; }

    const int a_r = lane & 15, a_c = (lane & 16) >> 1;
    const int b4_r = (lane & 7) + ((lane & 16) >> 1);
    const int b4_c = lane & 8;
    const int q = lane & 3, gq = lane >> 2;

    for (int c=0; c<32; c++){
        const int cur = c & 1;
        __syncthreads();   // prev GEMM1/GEMM2 done (W1 buf reusable)
        {   // W1[c] cp.async (committed BEFORE W2[c+1])
            const uint4* s1h = (const uint4*)(g_w1th + c*64*136);
            const uint4* s1l = (const uint4*)(g_w1tl + c*64*136);
            for (int i=tid;i<1088;i+=512){
                cpa16(sb + SM_W1H + i*16, s1h+i);
                cpa16(sb + SM_W1L + i*16, s1l+i);
            }
            CPA_COMMIT();
        }
        if (c+1 < 32){   // prefetch W2[c+1] into alt buffer
            uint32_t dh = cur ? (uint32_t)SM_W2H : (uint32_t)SM_W2H2;
            uint32_t dl = cur ? (uint32_t)SM_W2L : (uint32_t)SM_W2L2;
            const uint4* s2h = (const uint4*)(g_w2th + (c+1)*128*72);
            const uint4* s2l = (const uint4*)(g_w2tl + (c+1)*128*72);
            for (int i=tid;i<1152;i+=512){
                cpa16(sb + dh + i*16, s2h+i);
                cpa16(sb + dl + i*16, s2l+i);
            }
            CPA_COMMIT();
            CPA_WAIT1();   // xs/W2[c]/W1[c] done; W2[c+1] in flight
        } else {
            CPA_WAIT0();
        }
        __syncthreads();

        // GEMM1: mid[128x64]; warp rows m0..+15, mid cols nh*32..+31
        float acc1[4][4];
        #pragma unroll
        for (int i=0;i<4;i++){ acc1[i][0]=0.f; acc1[i][1]=0.f; acc1[i][2]=0.f; acc1[i][3]=0.f; }
        #pragma unroll
        for (int kk=0;kk<8;kk++){
            const int k0 = kk*16;
            uint32_t aaddr = sb + SM_XS_H + ((m0+a_r)*136 + k0 + a_c)*2;
            unsigned ah[4], al[4];
            ldsm4(ah, aaddr);
            ldsm4(al, aaddr + (SM_XS_L - SM_XS_H));
            #pragma unroll
            for (int ntp=0;ntp<2;ntp++){
                uint32_t baddr = sb + SM_W1H + ((nh*32+ntp*16+b4_r)*136 + k0 + b4_c)*2;
                unsigned bh[4], bl[4];
                ldsm4(bh, baddr);
                ldsm4(bl, baddr + (SM_W1L - SM_W1H));
                float* a0 = acc1[ntp*2], *a1 = acc1[ntp*2+1];
                mma_bf16(a0, ah, bh[0], bh[1]);
                mma_bf16(a0, ah, bl[0], bl[1]);
                mma_bf16(a0, al, bh[0], bh[1]);
                mma_bf16(a1, ah, bh[2], bh[3]);
                mma_bf16(a1, ah, bl[2], bl[3]);
                mma_bf16(a1, al, bh[2], bh[3]);
            }
        }
        {
            const int r1 = m0 + gq, r2 = r1 + 8;
            #pragma unroll
            for (int nt=0;nt<2;nt++){
                int col = nh*32 + nt*8 + q*2;
                float bb0 = b1v[c*64+col], bb1 = b1v[c*64+col+1];
                float v0 = fmaxf(acc1[nt][0]+bb0, 0.f);
                float v1 = fmaxf(acc1[nt][1]+bb1, 0.f);
                float v2 = fmaxf(acc1[nt][2]+bb0, 0.f);
                float v3 = fmaxf(acc1[nt][3]+bb1, 0.f);
                __nv_bfloat162 hh, ll;
                bsplit(v0, hh.x, ll.x); bsplit(v1, hh.y, ll.y);
                *(__nv_bfloat162*)&mid_h[r1*72+col]=hh;
                *(__nv_bfloat162*)&mid_l[r1*72+col]=ll;
                bsplit(v2, hh.x, ll.x); bsplit(v3, hh.y, ll.y);
                *(__nv_bfloat162*)&mid_h[r2*72+col]=hh;
                *(__nv_bfloat162*)&mid_l[r2*72+col]=ll;
            }
            #pragma unroll
            for (int nt=2;nt<4;nt++){
                int col = nh*32 + (nt-2)*8 + 16 + q*2;
                float bb0 = b1v[c*64+col], bb1 = b1v[c*64+col+1];
                float v0 = fmaxf(acc1[nt][0]+bb0, 0.f);
                float v1 = fmaxf(acc1[nt][1]+bb1, 0.f);
                float v2 = fmaxf(acc1[nt][2]+bb0, 0.f);
                float v3 = fmaxf(acc1[nt][3]+bb1, 0.f);
                __nv_bfloat162 hh, ll;
                bsplit(v0, hh.x, ll.x); bsplit(v1, hh.y, ll.y);
                *(__nv_bfloat162*)&mid_h[r1*72+col]=hh;
                *(__nv_bfloat162*)&mid_l[r1*72+col]=ll;
                bsplit(v2, hh.x, ll.x); bsplit(v3, hh.y, ll.y);
                *(__nv_bfloat162*)&mid_h[r2*72+col]=hh;
                *(__nv_bfloat162*)&mid_l[r2*72+col]=ll;
            }
        }
        __syncthreads();

        // GEMM2: acc2 += mid[m0..+15][64] @ W2^T ; out cols nh*64..+63
        const uint32_t w2h_base = cur ? (uint32_t)SM_W2H2 : (uint32_t)SM_W2H;
        #pragma unroll
        for (int kk=0;kk<4;kk++){
            const int k0 = kk*16;
            uint32_t aaddr = sb + SM_MIDH + ((m0+a_r)*72 + k0 + a_c)*2;
            unsigned ah[4], al[4];
            ldsm4(ah, aaddr);
            ldsm4(al, aaddr + (SM_MIDL - SM_MIDH));
            #pragma unroll
            for (int ntp=0;ntp<4;ntp++){
                uint32_t baddr = sb + w2h_base + ((nh*64+ntp*16+b4_r)*72 + k0 + b4_c)*2;
                unsigned bh[4], bl[4];
                ldsm4(bh, baddr);
                ldsm4(bl, baddr + 18432);
                float* a0 = acc2[ntp*2], *a1 = acc2[ntp*2+1];
                mma_bf16(a0, ah, bh[0], bh[1]);
                mma_bf16(a0, ah, bl[0], bl[1]);
                mma_bf16(a0, al, bh[0], bh[1]);
                mma_bf16(a1, ah, bh[2], bh[3]);
                mma_bf16(a1, ah, bl[2], bl[3]);
                mma_bf16(a1, al, bh[2], bh[3]);
            }
        }
    }

    // epilogue: +b2 + residual + LN2
    #pragma unroll
    for (int half=0; half<2; half++){
        int rl = m0 + gq + half*8;
        int grow = row0 + rl;
        float tv[16], s1=0.f, s2=0.f;
        #pragma unroll
        for (int nt=0;nt<8;nt++){
            int col = nh*64 + nt*8 + q*2;
            float t0 = acc2[nt][half*2+0] + b2v[col]   + g_x1[grow*HID_+col];
            float t1 = acc2[nt][half*2+1] + b2v[col+1] + g_x1[grow*HID_+col+1];
            tv[nt*2]=t0; tv[nt*2+1]=t1;
            s1 += t0+t1; s2 += t0*t0+t1*t1;
        }
        s1 += __shfl_xor_sync(0xffffffffu, s1, 1); s2 += __shfl_xor_sync(0xffffffffu, s2, 1);
        s1 += __shfl_xor_sync(0xffffffffu, s1, 2); s2 += __shfl_xor_sync(0xffffffffu, s2, 2);
        if (q==0){ s_s1[rl][nh]=s1; s_s2[rl][nh]=s2; }
        __syncthreads();
        float fs1 = s_s1[rl][0]+s_s1[rl][1];
        float fs2 = s_s2[rl][0]+s_s2[rl][1];
        float mean = fs1*(1.f/HID_);
        float var  = fs2*(1.f/HID_) - mean*mean;
        float rs   = rsqrtf(var + EPS_);
        #pragma unroll
        for (int nt=0;nt<8;nt++){
            int col = nh*64 + nt*8 + q*2;
            out[grow*HID_+col]   = (tv[nt*2]  -mean)*rs*g2[col]   + be2[col];
            out[grow*HID_+col+1] = (tv[nt*2+1]-mean)*rs*g2[col+1] + be2[col+1];
        }
        __syncthreads();
    }
}

// ---------------- launch ----------------------------------------------------
extern "C" void kernel_launch(void* const* d_in, const int* in_sizes, int n_in,
                              void* d_out, int out_size){
    int o = (in_sizes[4] == 1) ? 1 : 0;
    const float* h       = (const float*)d_in[0];
    const float* e       = (const float*)d_in[1];
    const int*   src     = (const int*)  d_in[2];
    const int*   dst     = (const int*)  d_in[3];
    const float* W_fc    = (const float*)d_in[4+o];
    const float* attn_l  = (const float*)d_in[5+o];
    const float* attn_r  = (const float*)d_in[6+o];
    const float* W_fe    = (const float*)d_in[7+o];
    const float* attn_e  = (const float*)d_in[8+o];
    const float* W_res   = (const float*)d_in[9+o];
    const float* gatb    = (const float*)d_in[10+o];
    const float* W_mha   = (const float*)d_in[11+o];
    const float* b_mha   = (const float*)d_in[12+o];
    const float* n1_g    = (const float*)d_in[13+o];
    const float* n1_b    = (const float*)d_in[14+o];
    const float* n2_g    = (const float*)d_in[15+o];
    const float* n2_b    = (const float*)d_in[16+o];
    const float* W1      = (const float*)d_in[17+o];
    const float* b1      = (const float*)d_in[18+o];
    const float* W2      = (const float*)d_in[19+o];
    const float* b2      = (const float*)d_in[20+o];
    float* out = (float*)d_out;

    cudaFuncSetAttribute(k_ffn_mma,  cudaFuncAttributeMaxDynamicSharedMemorySize, SMEM_FFN);
    cudaFuncSetAttribute(k_gemmA_mma,cudaFuncAttributeMaxDynamicSharedMemorySize, SMEM_GA);
    cudaFuncSetAttribute(k_mha_mma,  cudaFuncAttributeMaxDynamicSharedMemorySize, SMEM_MH);

    k_init<<<512,256>>>();
    k_prep<<<1024,256>>>(W1, W2, W_fc, W_res, W_mha, h);
    k_deg<<<N_EDGES/256,256>>>(dst);
    dim3 gA(64, 4);
    k_gemmA_mma<<<gA,512,SMEM_GA>>>(attn_l, attn_r);
    k_scan<<<1,1024>>>();
    k_edgefill<<<N_EDGES/256,256>>>(e, src, dst, W_fe, attn_e);
    k_agg<<<N_NODES*NH/8,256>>>(gatb);
    k_mha_mma<<<N_NODES/128,512,SMEM_MH>>>(b_mha, h, n1_g, n1_b);
    k_ffn_mma<<<N_NODES/128,512,SMEM_FFN>>>(b1, b2, n2_g, n2_b, out);
}

// round 13
// speedup vs baseline: 1.2292x; 1.0451x over previous
#include <cuda_runtime.h>
#include <cuda_bf16.h>
#include <cstdint>

#define N_NODES 32768
#define N_EDGES 524288
#define NH      4
#define HDIM    128
#define HD      512
#define HID_    128
#define DFF_    2048
#define SLOPE_  0.2f
#define EPS_    1e-5f

// ---------------- scratch ----------------------------------------------------
__device__ float    g_ft [N_NODES*HD];
__device__ float    g_res[N_NODES*HD];
__device__ float    g_el [N_NODES*NH];
__device__ float    g_er [N_NODES*NH];
__device__ int      g_deg[N_NODES];
__device__ int      g_cursor[N_NODES];
__device__ int      g_rowptr[N_NODES+1];
__device__ int      g_esrc[N_EDGES];
__device__ __align__(16) float g_wsH[N_EDGES*4];   // interleaved w[edge][head]
__device__ float    g_x1 [N_NODES*HID_];

// pre-split activations (bf16 hi/lo, 136-padded rows)
__device__ __align__(16) __nv_bfloat16 g_hh  [N_NODES*136];
__device__ __align__(16) __nv_bfloat16 g_hl  [N_NODES*136];
__device__ __align__(16) __nv_bfloat16 g_resh[N_NODES*544];
__device__ __align__(16) __nv_bfloat16 g_resl[N_NODES*544];
__device__ __align__(16) __nv_bfloat16 g_x1h [N_NODES*136];
__device__ __align__(16) __nv_bfloat16 g_x1l [N_NODES*136];

// pre-split hi/lo bf16 transposed weights ([n][k] padded rows)
__device__ __align__(16) __nv_bfloat16 g_w1th[32*64*136];
__device__ __align__(16) __nv_bfloat16 g_w1tl[32*64*136];
__device__ __align__(16) __nv_bfloat16 g_w2th[32*128*72];
__device__ __align__(16) __nv_bfloat16 g_w2tl[32*128*72];
__device__ __align__(16) __nv_bfloat16 g_wfth[512*136];
__device__ __align__(16) __nv_bfloat16 g_wftl[512*136];
__device__ __align__(16) __nv_bfloat16 g_wrth[512*136];
__device__ __align__(16) __nv_bfloat16 g_wrtl[512*136];
__device__ __align__(16) __nv_bfloat16 g_wmth[512*136];
__device__ __align__(16) __nv_bfloat16 g_wmtl[512*136];

// ---------------- helpers ------------------------------------------------------
__device__ __forceinline__ uint32_t smem_u32(const void* p){
    uint32_t a;
    asm("{ .reg .u64 t; cvta.to.shared.u64 t, %1; cvt.u32.u64 %0, t; }" : "=r"(a) : "l"(p));
    return a;
}
__device__ __forceinline__ void ldsm4(unsigned* r, uint32_t addr){
    asm volatile("ldmatrix.sync.aligned.m8n8.x4.shared.b16 {%0,%1,%2,%3}, [%4];"
        : "=r"(r[0]),"=r"(r[1]),"=r"(r[2]),"=r"(r[3]) : "r"(addr));
}
__device__ __forceinline__ void mma_bf16(float* c, const unsigned* a, unsigned b0, unsigned b1){
    asm volatile("mma.sync.aligned.m16n8k16.row.col.f32.bf16.bf16.f32 "
        "{%0,%1,%2,%3},{%4,%5,%6,%7},{%8,%9},{%0,%1,%2,%3};"
        : "+f"(c[0]),"+f"(c[1]),"+f"(c[2]),"+f"(c[3])
        : "r"(a[0]),"r"(a[1]),"r"(a[2]),"r"(a[3]),"r"(b0),"r"(b1));
}
__device__ __forceinline__ void bsplit(float v, __nv_bfloat16& hi, __nv_bfloat16& lo){
    hi = __float2bfloat16(v);
    lo = __float2bfloat16(v - __bfloat162float(hi));
}
__device__ __forceinline__ void cpa16(uint32_t saddr, const void* g){
    asm volatile("cp.async.cg.shared.global [%0], [%1], 16;" :: "r"(saddr), "l"(g));
}
#define CPA_COMMIT() asm volatile("cp.async.commit_group;" ::: "memory")
#define CPA_WAIT1()  asm volatile("cp.async.wait_group 1;" ::: "memory")
#define CPA_WAIT0()  asm volatile("cp.async.wait_group 0;" ::: "memory")

// ---------------- init ------------------------------------------------------
__global__ void k_init(){
    int i = blockIdx.x*256 + threadIdx.x;
    if (i < N_NODES){ g_deg[i] = 0; g_cursor[i] = 0; }
}

// ---------------- prep (+ degree count) ---------------------------------------
__global__ void k_prep(const float* __restrict__ W1, const float* __restrict__ W2,
                       const float* __restrict__ Wfc, const float* __restrict__ Wres,
                       const float* __restrict__ Wm, const float* __restrict__ h,
                       const int* __restrict__ dst){
    int i = blockIdx.x*256 + threadIdx.x;   // 262144 threads
    atomicAdd(&g_deg[dst[i]], 1);
    atomicAdd(&g_deg[dst[i + 262144]], 1);
    {   // W1 [k=128][n=2048]
        int k = i >> 11, n = i & 2047;
        __nv_bfloat16 hv, lv; bsplit(W1[i], hv, lv);
        int c = n >> 6, nn = n & 63;
        g_w1th[(c*64+nn)*136 + k] = hv;
        g_w1tl[(c*64+nn)*136 + k] = lv;
    }
    {   // W2 [k2=2048][n=128]
        int k2 = i >> 7, n = i & 127;
        __nv_bfloat16 hv, lv; bsplit(W2[i], hv, lv);
        int c = k2 >> 6, kk = k2 & 63;
        g_w2th[(c*128+n)*72 + kk] = hv;
        g_w2tl[(c*128+n)*72 + kk] = lv;
    }
    #pragma unroll
    for (int j=0;j<16;j++){
        int idx = i + j*262144;
        int n = idx >> 7, k = idx & 127;
        __nv_bfloat16 hv, lv; bsplit(h[idx], hv, lv);
        g_hh[n*136+k] = hv;
        g_hl[n*136+k] = lv;
    }
    if (i < 65536){
        {   // Wfc/Wres [k=128][n=512]
            int k = i >> 9, n = i & 511;
            __nv_bfloat16 hv, lv;
            bsplit(Wfc[i], hv, lv);
            g_wfth[n*136 + k] = hv; g_wftl[n*136 + k] = lv;
            bsplit(Wres[i], hv, lv);
            g_wrth[n*136 + k] = hv; g_wrtl[n*136 + k] = lv;
        }
        {   // Wm [k2=512][n=128]
            int k2 = i >> 7, n = i & 127;
            __nv_bfloat16 hv, lv; bsplit(Wm[i], hv, lv);
            int c = k2 >> 7, kk = k2 & 127;
            g_wmth[(c*128+n)*136 + kk] = hv;
            g_wmtl[(c*128+n)*136 + kk] = lv;
        }
    }
}

// ---------------- GEMM A: z-split, A double-buffered via cp.async ------------
#define GZ_A0H 0
#define GZ_A0L 34816
#define GZ_A1H 69632
#define GZ_A1L 104448
#define GZ_BH  139264
#define GZ_BL  174080
#define SMEM_GZ 208896
#define SMEM_MH 208896

__global__ __launch_bounds__(512,1) void k_gemmA_mma(
        const float* __restrict__ attn_l, const float* __restrict__ attn_r){
    extern __shared__ char smem[];
    __shared__ float s_al[128], s_ar[128];
    __shared__ float s_pl[128][2], s_pr[128][2];
    const uint32_t sb = smem_u32(smem);
    const int tid = threadIdx.x, lane = tid&31, w = tid>>5;
    const int strip = w>>1, nh = w&1;
    const int m0 = strip*16, ncol0 = nh*64;
    const int col0 = blockIdx.y*128;
    const int z = blockIdx.z;
    const __nv_bfloat16* Bh = z ? g_wrth : g_wfth;
    const __nv_bfloat16* Bl = z ? g_wrtl : g_wftl;
    float* __restrict__ C = z ? g_res : g_ft;

    if (z==0 && tid<128){
        s_al[tid] = attn_l[col0+tid];
        s_ar[tid] = attn_r[col0+tid];
    }
    {   // G0: B tile + A(0)
        const char* bh = (const char*)(Bh + col0*136);
        const char* bl = (const char*)(Bl + col0*136);
        const char* a0h = (const char*)g_hh + (blockIdx.x*4+0)*128*272;
        const char* a0l = (const char*)g_hl + (blockIdx.x*4+0)*128*272;
        for (int i=tid;i<2176;i+=512){
            cpa16(sb + GZ_BH  + i*16, bh  + i*16);
            cpa16(sb + GZ_BL  + i*16, bl  + i*16);
            cpa16(sb + GZ_A0H + i*16, a0h + i*16);
            cpa16(sb + GZ_A0L + i*16, a0l + i*16);
        }
        CPA_COMMIT();
    }

    const int a_r = lane & 15, a_c = (lane & 16) >> 1;
    const int b4_r = (lane & 7) + ((lane & 16) >> 1);
    const int b4_c = lane & 8;
    const int q = lane & 3, gq = lane >> 2;

    for (int rt=0; rt<4; rt++){
        const int row0 = (blockIdx.x*4+rt)*128;
        __syncthreads();   // all warps done with the alt A buffer
        if (rt<3){
            uint32_t dh = ((rt+1)&1) ? (uint32_t)GZ_A1H : (uint32_t)GZ_A0H;
            uint32_t dl = ((rt+1)&1) ? (uint32_t)GZ_A1L : (uint32_t)GZ_A0L;
            const char* ah = (const char*)g_hh + (blockIdx.x*4+rt+1)*128*272;
            const char* al_= (const char*)g_hl + (blockIdx.x*4+rt+1)*128*272;
            for (int i=tid;i<2176;i+=512){
                cpa16(sb + dh + i*16, ah + i*16);
                cpa16(sb + dl + i*16, al_+ i*16);
            }
            CPA_COMMIT();
            CPA_WAIT1();
        } else {
            CPA_WAIT0();
        }
        __syncthreads();
        const uint32_t A_H = (rt&1) ? (uint32_t)GZ_A1H : (uint32_t)GZ_A0H;
        const uint32_t A_L = (rt&1) ? (uint32_t)GZ_A1L : (uint32_t)GZ_A0L;

        float acc[8][4];
        #pragma unroll
        for (int i=0;i<8;i++){ acc[i][0]=0.f; acc[i][1]=0.f; acc[i][2]=0.f; acc[i][3]=0.f; }
        #pragma unroll
        for (int kk=0;kk<8;kk++){
            const int k0 = kk*16;
            uint32_t aaddr = sb + A_H + ((m0+a_r)*136 + k0 + a_c)*2;
            unsigned ahf[4], alf[4];
            ldsm4(ahf, aaddr);
            ldsm4(alf, aaddr + (A_L-A_H));
            #pragma unroll
            for (int ntp=0;ntp<4;ntp++){
                uint32_t baddr = sb + GZ_BH + ((ncol0+ntp*16+b4_r)*136 + k0 + b4_c)*2;
                unsigned bh[4], bl[4];
                ldsm4(bh, baddr);
                ldsm4(bl, baddr + (GZ_BL-GZ_BH));
                float* a0 = acc[ntp*2], *a1 = acc[ntp*2+1];
                mma_bf16(a0, ahf, bh[0], bh[1]);
                mma_bf16(a0, ahf, bl[0], bl[1]);
                mma_bf16(a0, alf, bh[0], bh[1]);
                mma_bf16(a1, ahf, bh[2], bh[3]);
                mma_bf16(a1, ahf, bl[2], bl[3]);
                mma_bf16(a1, alf, bh[2], bh[3]);
            }
        }
        #pragma unroll
        for (int half=0; half<2; half++){
            int row = row0 + m0 + gq + half*8;
            #pragma unroll
            for (int nt=0;nt<8;nt++){
                int col = col0 + ncol0 + nt*8 + q*2;
                *(float2*)&C[row*HD+col] =
                    make_float2(acc[nt][half*2], acc[nt][half*2+1]);
            }
        }
        if (z==0){
            #pragma unroll
            for (int half=0; half<2; half++){
                int rl = m0 + gq + half*8;
                float pl=0.f, pr=0.f;
                #pragma unroll
                for (int nt=0;nt<8;nt++){
                    int col = ncol0 + nt*8 + q*2;
                    float v0 = acc[nt][half*2], v1 = acc[nt][half*2+1];
                    pl += v0*s_al[col] + v1*s_al[col+1];
                    pr += v0*s_ar[col] + v1*s_ar[col+1];
                }
                pl += __shfl_xor_sync(0xffffffffu, pl, 1);
                pl += __shfl_xor_sync(0xffffffffu, pl, 2);
                pr += __shfl_xor_sync(0xffffffffu, pr, 1);
                pr += __shfl_xor_sync(0xffffffffu, pr, 2);
                if (q==0){ s_pl[rl][nh]=pl; s_pr[rl][nh]=pr; }
            }
            __syncthreads();
            if (tid<128){
                int row = row0 + tid;
                g_el[row*NH + blockIdx.y] = s_pl[tid][0]+s_pl[tid][1];
                g_er[row*NH + blockIdx.y] = s_pr[tid][0]+s_pr[tid][1];
            }
        }
    }
}

// ---------------- edge pass + CSR fill (1 atomic/edge) ------------------------
__global__ __launch_bounds__(256) void k_edgefill(const float* __restrict__ e,
        const int* __restrict__ src, const int* __restrict__ dst,
        const float* __restrict__ W_fe, const float* __restrict__ attn_e){
    __shared__ float ce[NH];
    int wid = threadIdx.x>>5, lane = threadIdx.x&31;
    if (wid < NH){
        float p = 0.f;
        #pragma unroll
        for (int q=0;q<4;q++){
            int d = lane + q*32;
            p += W_fe[wid*HDIM+d]*attn_e[wid*HDIM+d];
        }
        #pragma unroll
        for (int off=16; off; off>>=1) p += __shfl_xor_sync(0xffffffffu, p, off);
        if (lane==0) ce[wid]=p;
    }
    __syncthreads();
    int ei = blockIdx.x*256 + threadIdx.x;
    if (ei >= N_EDGES) return;
    int s = src[ei], d = dst[ei];
    float ev = e[ei];
    float4 els = ((const float4*)g_el)[s];
    float4 erd = ((const float4*)g_er)[d];
    float sc[4];
    sc[0] = els.x + erd.x + ev*ce[0];
    sc[1] = els.y + erd.y + ev*ce[1];
    sc[2] = els.z + erd.z + ev*ce[2];
    sc[3] = els.w + erd.w + ev*ce[3];
    float wv[4];
    #pragma unroll
    for (int hh=0;hh<4;hh++){
        float v = sc[hh];
        v = v > 0.f ? v : SLOPE_*v;
        wv[hh] = expf(v);
    }
    int pos = g_rowptr[d] + atomicAdd(&g_cursor[d], 1);
    g_esrc[pos] = s;
    *(float4*)&g_wsH[pos*4] = make_float4(wv[0],wv[1],wv[2],wv[3]);
}

// ---------------- CSR scan ----------------------------------------------------
__global__ __launch_bounds__(1024) void k_scan(){
    __shared__ int sm[1024];
    int t = threadIdx.x;
    int base = t*32;
    int s = 0;
    #pragma unroll
    for (int i=0;i<32;i++) s += g_deg[base+i];
    sm[t]=s; __syncthreads();
    for (int off=1; off<1024; off<<=1){
        int v = (t>=off)? sm[t-off] : 0;
        __syncthreads();
        if (t>=off) sm[t]+=v;
        __syncthreads();
    }
    int run = sm[t]-s;
    for (int i=0;i<32;i++){ g_rowptr[base+i]=run; run += g_deg[base+i]; }
    if (t==1023) g_rowptr[N_NODES]=run;
}

// ---------------- aggregation: local zsum, interleaved weights ----------------
__global__ __launch_bounds__(256) void k_agg(const float* __restrict__ gat_bias){
    int wid = threadIdx.x>>5, lane = threadIdx.x&31;
    int gw = blockIdx.x*8 + wid;
    int n = gw>>2, hh = gw&3;
    int beg = g_rowptr[n], end = g_rowptr[n+1];
    float4 acc = make_float4(0,0,0,0);
    float zsum = 0.f;
    const float4* ft4 = (const float4*)g_ft;
    const float* wp = g_wsH + hh;
    int i = beg;
    for (; i+4<=end; i+=4){
        float w0 = wp[i*4],   w1 = wp[(i+1)*4], w2 = wp[(i+2)*4], w3 = wp[(i+3)*4];
        int   s0 = g_esrc[i], s1 = g_esrc[i+1], s2 = g_esrc[i+2], s3 = g_esrc[i+3];
        float4 v0 = ft4[s0*128 + hh*32 + lane];
        float4 v1 = ft4[s1*128 + hh*32 + lane];
        float4 v2 = ft4[s2*128 + hh*32 + lane];
        float4 v3 = ft4[s3*128 + hh*32 + lane];
        zsum += w0+w1+w2+w3;
        acc.x += w0*v0.x + w1*v1.x + w2*v2.x + w3*v3.x;
        acc.y += w0*v0.y + w1*v1.y + w2*v2.y + w3*v3.y;
        acc.z += w0*v0.z + w1*v1.z + w2*v2.z + w3*v3.z;
        acc.w += w0*v0.w + w1*v1.w + w2*v2.w + w3*v3.w;
    }
    for (; i<end; i++){
        float w0 = wp[i*4];
        int s0 = g_esrc[i];
        float4 v0 = ft4[s0*128 + hh*32 + lane];
        zsum += w0;
        acc.x = fmaf(w0, v0.x, acc.x);
        acc.y = fmaf(w0, v0.y, acc.y);
        acc.z = fmaf(w0, v0.z, acc.z);
        acc.w = fmaf(w0, v0.w, acc.w);
    }
    float zi = zsum > 0.f ? 1.f/zsum : 1.f;
    int base = n*HD + hh*HDIM + lane*4;
    float4 r  = *(const float4*)&g_res[base];
    float4 bv = *(const float4*)&gat_bias[hh*HDIM + lane*4];
    float o0 = fmaxf(acc.x*zi + r.x + bv.x, 0.f);
    float o1 = fmaxf(acc.y*zi + r.y + bv.y, 0.f);
    float o2 = fmaxf(acc.z*zi + r.z + bv.z, 0.f);
    float o3 = fmaxf(acc.w*zi + r.w + bv.w, 0.f);
    int sbase = n*544 + hh*136 + lane*4;
    __nv_bfloat162 h01, h23, l01, l23;
    bsplit(o0, h01.x, l01.x); bsplit(o1, h01.y, l01.y);
    bsplit(o2, h23.x, l23.x); bsplit(o3, h23.y, l23.y);
    *(__nv_bfloat162*)&g_resh[sbase]   = h01;
    *(__nv_bfloat162*)&g_resh[sbase+2] = h23;
    *(__nv_bfloat162*)&g_resl[sbase]   = l01;
    *(__nv_bfloat162*)&g_resl[sbase+2] = l23;
}

// ---------------- MHA: cp.async A + double-buffered Wm -----------------------
#define MH_AH  0
#define MH_AL  34816
#define MH_W0H 69632
#define MH_W0L 104448
#define MH_W1H 139264
#define MH_W1L 174080

__global__ __launch_bounds__(512,1) void k_mha_mma(const float* __restrict__ bm,
        const float* __restrict__ h0, const float* __restrict__ g1,
        const float* __restrict__ be1){
    extern __shared__ char smem[];
    __shared__ float s_s1[128][2], s_s2[128][2];
    const uint32_t sb = smem_u32(smem);
    const int tid = threadIdx.x, lane = tid&31, w = tid>>5;
    const int strip = w>>1, nh = w&1;
    const int m0 = strip*16, ncol0 = nh*64;
    const int row0 = blockIdx.x*128;

    const int a_r = lane & 15, a_c = (lane & 16) >> 1;
    const int b4_r = (lane & 7) + ((lane & 16) >> 1);
    const int b4_c = lane & 8;
    const int q = lane & 3, gq = lane >> 2;

    float acc[8][4];
    #pragma unroll
    for (int i=0;i<8;i++){ acc[i][0]=0.f; acc[i][1]=0.f; acc[i][2]=0.f; acc[i][3]=0.f; }

    {
        const char* sh = (const char*)g_wmth;
        const char* sl = (const char*)g_wmtl;
        for (int i=tid;i<2176;i+=512){
            cpa16(sb + MH_W0H + i*16, sh + i*16);
            cpa16(sb + MH_W0L + i*16, sl + i*16);
        }
        CPA_COMMIT();
    }

    for (int c=0; c<4; c++){
        const int cur = c & 1;
        __syncthreads();
        {
            for (int i=tid;i<2176;i+=512){
                int m = i/17, o = i - m*17;
                long so = (long)(row0+m)*1088 + c*272 + o*16;
                cpa16(sb + MH_AH + m*272 + o*16, (const char*)g_resh + so);
                cpa16(sb + MH_AL + m*272 + o*16, (const char*)g_resl + so);
            }
            CPA_COMMIT();
        }
        if (c < 3){
            uint32_t dh = cur ? (uint32_t)MH_W0H : (uint32_t)MH_W1H;
            uint32_t dl = cur ? (uint32_t)MH_W0L : (uint32_t)MH_W1L;
            const char* sh = (const char*)(g_wmth + (c+1)*128*136);
            const char* sl = (const char*)(g_wmtl + (c+1)*128*136);
            for (int i=tid;i<2176;i+=512){
                cpa16(sb + dh + i*16, sh + i*16);
                cpa16(sb + dl + i*16, sl + i*16);
            }
            CPA_COMMIT();
            CPA_WAIT1();
        } else {
            CPA_WAIT0();
        }
        __syncthreads();

        const uint32_t wbh = cur ? (uint32_t)MH_W1H : (uint32_t)MH_W0H;
        const uint32_t wbl = cur ? (uint32_t)MH_W1L : (uint32_t)MH_W0L;
        #pragma unroll
        for (int kk=0;kk<8;kk++){
            const int k0 = kk*16;
            uint32_t aaddr = sb + MH_AH + ((m0+a_r)*136 + k0 + a_c)*2;
            unsigned ahf[4], alf[4];
            ldsm4(ahf, aaddr);
            ldsm4(alf, aaddr + (MH_AL-MH_AH));
            #pragma unroll
            for (int ntp=0;ntp<4;ntp++){
                uint32_t boff = ((ncol0+ntp*16+b4_r)*136 + k0 + b4_c)*2;
                unsigned bh[4], bl[4];
                ldsm4(bh, sb + wbh + boff);
                ldsm4(bl, sb + wbl + boff);
                float* a0 = acc[ntp*2], *a1 = acc[ntp*2+1];
                mma_bf16(a0, ahf, bh[0], bh[1]);
                mma_bf16(a0, ahf, bl[0], bl[1]);
                mma_bf16(a0, alf, bh[0], bh[1]);
                mma_bf16(a1, ahf, bh[2], bh[3]);
                mma_bf16(a1, ahf, bl[2], bl[3]);
                mma_bf16(a1, alf, bh[2], bh[3]);
            }
        }
    }

    #pragma unroll
    for (int half=0; half<2; half++){
        int rl = m0 + gq + half*8;
        int row = row0 + rl;
        float tv[16], s1=0.f, s2=0.f;
        #pragma unroll
        for (int nt=0;nt<8;nt++){
            int col = ncol0 + nt*8 + q*2;
            float t0 = fmaxf(acc[nt][half*2+0] + bm[col],   0.f) + h0[row*HID_+col];
            float t1 = fmaxf(acc[nt][half*2+1] + bm[col+1], 0.f) + h0[row*HID_+col+1];
            tv[nt*2]=t0; tv[nt*2+1]=t1;
            s1 += t0+t1; s2 += t0*t0+t1*t1;
        }
        s1 += __shfl_xor_sync(0xffffffffu, s1, 1); s2 += __shfl_xor_sync(0xffffffffu, s2, 1);
        s1 += __shfl_xor_sync(0xffffffffu, s1, 2); s2 += __shfl_xor_sync(0xffffffffu, s2, 2);
        if (q==0){ s_s1[rl][nh]=s1; s_s2[rl][nh]=s2; }
        __syncthreads();
        float fs1 = s_s1[rl][0]+s_s1[rl][1];
        float fs2 = s_s2[rl][0]+s_s2[rl][1];
        float mean = fs1*(1.f/HID_);
        float var  = fs2*(1.f/HID_) - mean*mean;
        float rs   = rsqrtf(var + EPS_);
        #pragma unroll
        for (int nt=0;nt<8;nt++){
            int col = ncol0 + nt*8 + q*2;
            float x0 = (tv[nt*2]  -mean)*rs*g1[col]   + be1[col];
            float x1 = (tv[nt*2+1]-mean)*rs*g1[col+1] + be1[col+1];
            *(float2*)&g_x1[row*HID_+col] = make_float2(x0, x1);
            __nv_bfloat162 hh, ll;
            bsplit(x0, hh.x, ll.x); bsplit(x1, hh.y, ll.y);
            *(__nv_bfloat162*)&g_x1h[row*136+col] = hh;
            *(__nv_bfloat162*)&g_x1l[row*136+col] = ll;
        }
        __syncthreads();
    }
}

// ---------------- FFN: cp.async xs/W1 + W2 double-buffer ----------------------
#define SM_XS_H 0
#define SM_XS_L 34816
#define SM_W1H  69632
#define SM_W1L  87040
#define SM_W2H  104448
#define SM_W2L  122880
#define SM_MIDH 141312
#define SM_MIDL 159744
#define SM_W2H2 178176
#define SM_W2L2 196608
#define SMEM_FFN 215040

__global__ __launch_bounds__(512,1) void k_ffn_mma(const float* __restrict__ b1v,
        const float* __restrict__ b2v, const float* __restrict__ g2,
        const float* __restrict__ be2, float* __restrict__ out){
    extern __shared__ char smem[];
    __shared__ float s_s1[128][2], s_s2[128][2];
    __nv_bfloat16* mid_h= (__nv_bfloat16*)(smem+SM_MIDH);
    __nv_bfloat16* mid_l= (__nv_bfloat16*)(smem+SM_MIDL);
    const uint32_t sb = smem_u32(smem);
    const int tid = threadIdx.x, lane = tid&31, w = tid>>5;
    const int strip = w>>1, nh = w&1;
    const int m0 = strip*16;
    const int row0 = blockIdx.x*128;

    {
        const char* sh = (const char*)g_x1h + row0*272;
        const char* sl = (const char*)g_x1l + row0*272;
        for (int i=tid;i<2176;i+=512){
            cpa16(sb + SM_XS_H + i*16, sh + i*16);
            cpa16(sb + SM_XS_L + i*16, sl + i*16);
        }
        CPA_COMMIT();
    }
    {
        const uint4* s2h = (const uint4*)(g_w2th);
        const uint4* s2l = (const uint4*)(g_w2tl);
        for (int i=tid;i<1152;i+=512){
            cpa16(sb + SM_W2H + i*16, s2h+i);
            cpa16(sb + SM_W2L + i*16, s2l+i);
        }
        CPA_COMMIT();
    }

    float acc2[8][4];
    #pragma unroll
    for (int i=0;i<8;i++){ acc2[i][0]=0.f; acc2[i][1]=0.f; acc2[i][2]=0.f; acc2[i][3]=0.f; }

    const int a_r = lane & 15, a_c = (lane & 16) >> 1;
    const int b4_r = (lane & 7) + ((lane & 16) >> 1);
    const int b4_c = lane & 8;
    const int q = lane & 3, gq = lane >> 2;

    for (int c=0; c<32; c++){
        const int cur = c & 1;
        __syncthreads();
        {
            const uint4* s1h = (const uint4*)(g_w1th + c*64*136);
            const uint4* s1l = (const uint4*)(g_w1tl + c*64*136);
            for (int i=tid;i<1088;i+=512){
                cpa16(sb + SM_W1H + i*16, s1h+i);
                cpa16(sb + SM_W1L + i*16, s1l+i);
            }
            CPA_COMMIT();
        }
        if (c+1 < 32){
            uint32_t dh = cur ? (uint32_t)SM_W2H : (uint32_t)SM_W2H2;
            uint32_t dl = cur ? (uint32_t)SM_W2L : (uint32_t)SM_W2L2;
            const uint4* s2h = (const uint4*)(g_w2th + (c+1)*128*72);
            const uint4* s2l = (const uint4*)(g_w2tl + (c+1)*128*72);
            for (int i=tid;i<1152;i+=512){
                cpa16(sb + dh + i*16, s2h+i);
                cpa16(sb + dl + i*16, s2l+i);
            }
            CPA_COMMIT();
            CPA_WAIT1();
        } else {
            CPA_WAIT0();
        }
        __syncthreads();

        float acc1[4][4];
        #pragma unroll
        for (int i=0;i<4;i++){ acc1[i][0]=0.f; acc1[i][1]=0.f; acc1[i][2]=0.f; acc1[i][3]=0.f; }
        #pragma unroll
        for (int kk=0;kk<8;kk++){
            const int k0 = kk*16;
            uint32_t aaddr = sb + SM_XS_H + ((m0+a_r)*136 + k0 + a_c)*2;
            unsigned ah[4], al[4];
            ldsm4(ah, aaddr);
            ldsm4(al, aaddr + (SM_XS_L - SM_XS_H));
            #pragma unroll
            for (int ntp=0;ntp<2;ntp++){
                uint32_t baddr = sb + SM_W1H + ((nh*32+ntp*16+b4_r)*136 + k0 + b4_c)*2;
                unsigned bh[4], bl[4];
                ldsm4(bh, baddr);
                ldsm4(bl, baddr + (SM_W1L - SM_W1H));
                float* a0 = acc1[ntp*2], *a1 = acc1[ntp*2+1];
                mma_bf16(a0, ah, bh[0], bh[1]);
                mma_bf16(a0, ah, bl[0], bl[1]);
                mma_bf16(a0, al, bh[0], bh[1]);
                mma_bf16(a1, ah, bh[2], bh[3]);
                mma_bf16(a1, ah, bl[2], bl[3]);
                mma_bf16(a1, al, bh[2], bh[3]);
            }
        }
        {
            const int r1 = m0 + gq, r2 = r1 + 8;
            #pragma unroll
            for (int nt=0;nt<2;nt++){
                int col = nh*32 + nt*8 + q*2;
                float bb0 = b1v[c*64+col], bb1 = b1v[c*64+col+1];
                float v0 = fmaxf(acc1[nt][0]+bb0, 0.f);
                float v1 = fmaxf(acc1[nt][1]+bb1, 0.f);
                float v2 = fmaxf(acc1[nt][2]+bb0, 0.f);
                float v3 = fmaxf(acc1[nt][3]+bb1, 0.f);
                __nv_bfloat162 hh, ll;
                bsplit(v0, hh.x, ll.x); bsplit(v1, hh.y, ll.y);
                *(__nv_bfloat162*)&mid_h[r1*72+col]=hh;
                *(__nv_bfloat162*)&mid_l[r1*72+col]=ll;
                bsplit(v2, hh.x, ll.x); bsplit(v3, hh.y, ll.y);
                *(__nv_bfloat162*)&mid_h[r2*72+col]=hh;
                *(__nv_bfloat162*)&mid_l[r2*72+col]=ll;
            }
            #pragma unroll
            for (int nt=2;nt<4;nt++){
                int col = nh*32 + (nt-2)*8 + 16 + q*2;
                float bb0 = b1v[c*64+col], bb1 = b1v[c*64+col+1];
                float v0 = fmaxf(acc1[nt][0]+bb0, 0.f);
                float v1 = fmaxf(acc1[nt][1]+bb1, 0.f);
                float v2 = fmaxf(acc1[nt][2]+bb0, 0.f);
                float v3 = fmaxf(acc1[nt][3]+bb1, 0.f);
                __nv_bfloat162 hh, ll;
                bsplit(v0, hh.x, ll.x); bsplit(v1, hh.y, ll.y);
                *(__nv_bfloat162*)&mid_h[r1*72+col]=hh;
                *(__nv_bfloat162*)&mid_l[r1*72+col]=ll;
                bsplit(v2, hh.x, ll.x); bsplit(v3, hh.y, ll.y);
                *(__nv_bfloat162*)&mid_h[r2*72+col]=hh;
                *(__nv_bfloat162*)&mid_l[r2*72+col]=ll;
            }
        }
        __syncthreads();

        const uint32_t w2h_base = cur ? (uint32_t)SM_W2H2 : (uint32_t)SM_W2H;
        #pragma unroll
        for (int kk=0;kk<4;kk++){
            const int k0 = kk*16;
            uint32_t aaddr = sb + SM_MIDH + ((m0+a_r)*72 + k0 + a_c)*2;
            unsigned ah[4], al[4];
            ldsm4(ah, aaddr);
            ldsm4(al, aaddr + (SM_MIDL - SM_MIDH));
            #pragma unroll
            for (int ntp=0;ntp<4;ntp++){
                uint32_t baddr = sb + w2h_base + ((nh*64+ntp*16+b4_r)*72 + k0 + b4_c)*2;
                unsigned bh[4], bl[4];
                ldsm4(bh, baddr);
                ldsm4(bl, baddr + 18432);
                float* a0 = acc2[ntp*2], *a1 = acc2[ntp*2+1];
                mma_bf16(a0, ah, bh[0], bh[1]);
                mma_bf16(a0, ah, bl[0], bl[1]);
                mma_bf16(a0, al, bh[0], bh[1]);
                mma_bf16(a1, ah, bh[2], bh[3]);
                mma_bf16(a1, ah, bl[2], bl[3]);
                mma_bf16(a1, al, bh[2], bh[3]);
            }
        }
    }

    #pragma unroll
    for (int half=0; half<2; half++){
        int rl = m0 + gq + half*8;
        int grow = row0 + rl;
        float tv[16], s1=0.f, s2=0.f;
        #pragma unroll
        for (int nt=0;nt<8;nt++){
            int col = nh*64 + nt*8 + q*2;
            float t0 = acc2[nt][half*2+0] + b2v[col]   + g_x1[grow*HID_+col];
            float t1 = acc2[nt][half*2+1] + b2v[col+1] + g_x1[grow*HID_+col+1];
            tv[nt*2]=t0; tv[nt*2+1]=t1;
            s1 += t0+t1; s2 += t0*t0+t1*t1;
        }
        s1 += __shfl_xor_sync(0xffffffffu, s1, 1); s2 += __shfl_xor_sync(0xffffffffu, s2, 1);
        s1 += __shfl_xor_sync(0xffffffffu, s1, 2); s2 += __shfl_xor_sync(0xffffffffu, s2, 2);
        if (q==0){ s_s1[rl][nh]=s1; s_s2[rl][nh]=s2; }
        __syncthreads();
        float fs1 = s_s1[rl][0]+s_s1[rl][1];
        float fs2 = s_s2[rl][0]+s_s2[rl][1];
        float mean = fs1*(1.f/HID_);
        float var  = fs2*(1.f/HID_) - mean*mean;
        float rs   = rsqrtf(var + EPS_);
        #pragma unroll
        for (int nt=0;nt<8;nt++){
            int col = nh*64 + nt*8 + q*2;
            out[grow*HID_+col]   = (tv[nt*2]  -mean)*rs*g2[col]   + be2[col];
            out[grow*HID_+col+1] = (tv[nt*2+1]-mean)*rs*g2[col+1] + be2[col+1];
        }
        __syncthreads();
    }
}

// ---------------- launch ----------------------------------------------------
extern "C" void kernel_launch(void* const* d_in, const int* in_sizes, int n_in,
                              void* d_out, int out_size){
    int o = (in_sizes[4] == 1) ? 1 : 0;
    const float* h       = (const float*)d_in[0];
    const float* e       = (const float*)d_in[1];
    const int*   src     = (const int*)  d_in[2];
    const int*   dst     = (const int*)  d_in[3];
    const float* W_fc    = (const float*)d_in[4+o];
    const float* attn_l  = (const float*)d_in[5+o];
    const float* attn_r  = (const float*)d_in[6+o];
    const float* W_fe    = (const float*)d_in[7+o];
    const float* attn_e  = (const float*)d_in[8+o];
    const float* W_res   = (const float*)d_in[9+o];
    const float* gatb    = (const float*)d_in[10+o];
    const float* W_mha   = (const float*)d_in[11+o];
    const float* b_mha   = (const float*)d_in[12+o];
    const float* n1_g    = (const float*)d_in[13+o];
    const float* n1_b    = (const float*)d_in[14+o];
    const float* n2_g    = (const float*)d_in[15+o];
    const float* n2_b    = (const float*)d_in[16+o];
    const float* W1      = (const float*)d_in[17+o];
    const float* b1      = (const float*)d_in[18+o];
    const float* W2      = (const float*)d_in[19+o];
    const float* b2      = (const float*)d_in[20+o];
    float* out = (float*)d_out;

    cudaFuncSetAttribute(k_ffn_mma,  cudaFuncAttributeMaxDynamicSharedMemorySize, SMEM_FFN);
    cudaFuncSetAttribute(k_gemmA_mma,cudaFuncAttributeMaxDynamicSharedMemorySize, SMEM_GZ);
    cudaFuncSetAttribute(k_mha_mma,  cudaFuncAttributeMaxDynamicSharedMemorySize, SMEM_MH);

    k_init<<<128,256>>>();
    k_prep<<<1024,256>>>(W1, W2, W_fc, W_res, W_mha, h, dst);
    dim3 gA(64, 4, 2);
    k_gemmA_mma<<<gA,512,SMEM_GZ>>>(attn_l, attn_r);
    k_scan<<<1,1024>>>();
    k_edgefill<<<N_EDGES/256,256>>>(e, src, dst, W_fe, attn_e);
    k_agg<<<N_NODES*NH/8,256>>>(gatb);
    k_mha_mma<<<N_NODES/128,512,SMEM_MH>>>(b_mha, h, n1_g, n1_b);
    k_ffn_mma<<<N_NODES/128,512,SMEM_FFN>>>(b1, b2, n2_g, n2_b, out);
}

// round 14
// speedup vs baseline: 1.3416x; 1.0914x over previous
#include <cuda_runtime.h>
#include <cuda_bf16.h>
#include <cstdint>

#define N_NODES 32768
#define N_EDGES 524288
#define NH      4
#define HDIM    128
#define HD      512
#define HID_    128
#define DFF_    2048
#define SLOPE_  0.2f
#define EPS_    1e-5f

// ---------------- scratch ----------------------------------------------------
__device__ float    g_ft [N_NODES*HD];
__device__ float    g_res[N_NODES*HD];
__device__ float    g_el [N_NODES*NH];
__device__ float    g_er [N_NODES*NH];
__device__ int      g_deg[N_NODES];
__device__ int      g_cursor[N_NODES];
__device__ int      g_rowptr[N_NODES+1];
__device__ int      g_bsum[128];
__device__ int      g_esrc[N_EDGES];
__device__ __align__(16) float g_wsH[N_EDGES*4];
__device__ float    g_x1 [N_NODES*HID_];

// pre-split activations (bf16 hi/lo, 136-padded rows)
__device__ __align__(16) __nv_bfloat16 g_hh  [N_NODES*136];
__device__ __align__(16) __nv_bfloat16 g_hl  [N_NODES*136];
__device__ __align__(16) __nv_bfloat16 g_resh[N_NODES*544];
__device__ __align__(16) __nv_bfloat16 g_resl[N_NODES*544];
__device__ __align__(16) __nv_bfloat16 g_x1h [N_NODES*136];
__device__ __align__(16) __nv_bfloat16 g_x1l [N_NODES*136];

// pre-split hi/lo bf16 transposed weights ([n][k] padded rows)
__device__ __align__(16) __nv_bfloat16 g_w1th[32*64*136];
__device__ __align__(16) __nv_bfloat16 g_w1tl[32*64*136];
__device__ __align__(16) __nv_bfloat16 g_w2th[32*128*72];
__device__ __align__(16) __nv_bfloat16 g_w2tl[32*128*72];
__device__ __align__(16) __nv_bfloat16 g_wfth[512*136];
__device__ __align__(16) __nv_bfloat16 g_wftl[512*136];
__device__ __align__(16) __nv_bfloat16 g_wrth[512*136];
__device__ __align__(16) __nv_bfloat16 g_wrtl[512*136];
__device__ __align__(16) __nv_bfloat16 g_wmth[512*136];
__device__ __align__(16) __nv_bfloat16 g_wmtl[512*136];

// ---------------- helpers ------------------------------------------------------
__device__ __forceinline__ uint32_t smem_u32(const void* p){
    uint32_t a;
    asm("{ .reg .u64 t; cvta.to.shared.u64 t, %1; cvt.u32.u64 %0, t; }" : "=r"(a) : "l"(p));
    return a;
}
__device__ __forceinline__ void ldsm4(unsigned* r, uint32_t addr){
    asm volatile("ldmatrix.sync.aligned.m8n8.x4.shared.b16 {%0,%1,%2,%3}, [%4];"
        : "=r"(r[0]),"=r"(r[1]),"=r"(r[2]),"=r"(r[3]) : "r"(addr));
}
__device__ __forceinline__ void mma_bf16(float* c, const unsigned* a, unsigned b0, unsigned b1){
    asm volatile("mma.sync.aligned.m16n8k16.row.col.f32.bf16.bf16.f32 "
        "{%0,%1,%2,%3},{%4,%5,%6,%7},{%8,%9},{%0,%1,%2,%3};"
        : "+f"(c[0]),"+f"(c[1]),"+f"(c[2]),"+f"(c[3])
        : "r"(a[0]),"r"(a[1]),"r"(a[2]),"r"(a[3]),"r"(b0),"r"(b1));
}
__device__ __forceinline__ void bsplit(float v, __nv_bfloat16& hi, __nv_bfloat16& lo){
    hi = __float2bfloat16(v);
    lo = __float2bfloat16(v - __bfloat162float(hi));
}
__device__ __forceinline__ void cpa16(uint32_t saddr, const void* g){
    asm volatile("cp.async.cg.shared.global [%0], [%1], 16;" :: "r"(saddr), "l"(g));
}
#define CPA_COMMIT() asm volatile("cp.async.commit_group;" ::: "memory")
#define CPA_WAIT1()  asm volatile("cp.async.wait_group 1;" ::: "memory")
#define CPA_WAIT0()  asm volatile("cp.async.wait_group 0;" ::: "memory")

// ---------------- init ------------------------------------------------------
__global__ void k_init(){
    int i = blockIdx.x*256 + threadIdx.x;
    if (i < N_NODES){ g_deg[i] = 0; g_cursor[i] = 0; }
}

// ---------------- prep (+ degree count) ---------------------------------------
__global__ void k_prep(const float* __restrict__ W1, const float* __restrict__ W2,
                       const float* __restrict__ Wfc, const float* __restrict__ Wres,
                       const float* __restrict__ Wm, const float* __restrict__ h,
                       const int* __restrict__ dst){
    int i = blockIdx.x*256 + threadIdx.x;   // 262144 threads
    atomicAdd(&g_deg[dst[i]], 1);
    atomicAdd(&g_deg[dst[i + 262144]], 1);
    {   // W1 [k=128][n=2048]
        int k = i >> 11, n = i & 2047;
        __nv_bfloat16 hv, lv; bsplit(W1[i], hv, lv);
        int c = n >> 6, nn = n & 63;
        g_w1th[(c*64+nn)*136 + k] = hv;
        g_w1tl[(c*64+nn)*136 + k] = lv;
    }
    {   // W2 [k2=2048][n=128]
        int k2 = i >> 7, n = i & 127;
        __nv_bfloat16 hv, lv; bsplit(W2[i], hv, lv);
        int c = k2 >> 6, kk = k2 & 63;
        g_w2th[(c*128+n)*72 + kk] = hv;
        g_w2tl[(c*128+n)*72 + kk] = lv;
    }
    #pragma unroll
    for (int j=0;j<16;j++){
        int idx = i + j*262144;
        int n = idx >> 7, k = idx & 127;
        __nv_bfloat16 hv, lv; bsplit(h[idx], hv, lv);
        g_hh[n*136+k] = hv;
        g_hl[n*136+k] = lv;
    }
    if (i < 65536){
        {   // Wfc/Wres [k=128][n=512]
            int k = i >> 9, n = i & 511;
            __nv_bfloat16 hv, lv;
            bsplit(Wfc[i], hv, lv);
            g_wfth[n*136 + k] = hv; g_wftl[n*136 + k] = lv;
            bsplit(Wres[i], hv, lv);
            g_wrth[n*136 + k] = hv; g_wrtl[n*136 + k] = lv;
        }
        {   // Wm [k2=512][n=128]
            int k2 = i >> 7, n = i & 127;
            __nv_bfloat16 hv, lv; bsplit(Wm[i], hv, lv);
            int c = k2 >> 7, kk = k2 & 127;
            g_wmth[(c*128+n)*136 + kk] = hv;
            g_wmtl[(c*128+n)*136 + kk] = lv;
        }
    }
}

// ---------------- hierarchical CSR scan ---------------------------------------
__global__ __launch_bounds__(256) void k_scan1(){
    int b = blockIdx.x, t = threadIdx.x;
    int node = b*256 + t;
    int d = g_deg[node];
    int v = d;
    #pragma unroll
    for (int off=1; off<32; off<<=1){
        int nv = __shfl_up_sync(0xffffffffu, v, off);
        if ((t&31) >= off) v += nv;
    }
    __shared__ int wsum[8];
    if ((t&31)==31) wsum[t>>5] = v;
    __syncthreads();
    if (t < 8){
        int wv = wsum[t];
        #pragma unroll
        for (int off=1; off<8; off<<=1){
            int nv = __shfl_up_sync(0xffu, wv, off);
            if (t >= off) wv += nv;
        }
        wsum[t] = wv;
    }
    __syncthreads();
    int incl = v + ((t>=32) ? wsum[(t>>5)-1] : 0);
    g_rowptr[node] = incl - d;
    if (t==255) g_bsum[b] = incl;
}

__global__ __launch_bounds__(128) void k_scan2(){
    int t = threadIdx.x;
    int v = g_bsum[t];
    int x = v;
    #pragma unroll
    for (int off=1; off<32; off<<=1){
        int nv = __shfl_up_sync(0xffffffffu, x, off);
        if ((t&31) >= off) x += nv;
    }
    __shared__ int ws[4];
    if ((t&31)==31) ws[t>>5] = x;
    __syncthreads();
    if (t < 4){
        int wv = ws[t];
        #pragma unroll
        for (int off=1; off<4; off<<=1){
            int nv = __shfl_up_sync(0xfu, wv, off);
            if (t >= off) wv += nv;
        }
        ws[t] = wv;
    }
    __syncthreads();
    int incl = x + ((t>=32) ? ws[(t>>5)-1] : 0);
    g_bsum[t] = incl - v;
    if (t==127) g_rowptr[N_NODES] = incl;
}

__global__ __launch_bounds__(256) void k_scan3(){
    int node = blockIdx.x*256 + threadIdx.x;
    g_rowptr[node] += g_bsum[blockIdx.x];
}

// ---------------- GEMM A: z-split, A double-buffered via cp.async ------------
#define GZ_A0H 0
#define GZ_A0L 34816
#define GZ_A1H 69632
#define GZ_A1L 104448
#define GZ_BH  139264
#define GZ_BL  174080
#define SMEM_GZ 208896
#define SMEM_MH 208896

__global__ __launch_bounds__(512,1) void k_gemmA_mma(
        const float* __restrict__ attn_l, const float* __restrict__ attn_r){
    extern __shared__ char smem[];
    __shared__ float s_al[128], s_ar[128];
    __shared__ float s_pl[128][2], s_pr[128][2];
    const uint32_t sb = smem_u32(smem);
    const int tid = threadIdx.x, lane = tid&31, w = tid>>5;
    const int strip = w>>1, nh = w&1;
    const int m0 = strip*16, ncol0 = nh*64;
    const int col0 = blockIdx.y*128;
    const int z = blockIdx.z;
    const __nv_bfloat16* Bh = z ? g_wrth : g_wfth;
    const __nv_bfloat16* Bl = z ? g_wrtl : g_wftl;
    float* __restrict__ C = z ? g_res : g_ft;

    if (z==0 && tid<128){
        s_al[tid] = attn_l[col0+tid];
        s_ar[tid] = attn_r[col0+tid];
    }
    {   // G0: B tile + A(0)
        const char* bh = (const char*)(Bh + col0*136);
        const char* bl = (const char*)(Bl + col0*136);
        const char* a0h = (const char*)g_hh + (blockIdx.x*4+0)*128*272;
        const char* a0l = (const char*)g_hl + (blockIdx.x*4+0)*128*272;
        for (int i=tid;i<2176;i+=512){
            cpa16(sb + GZ_BH  + i*16, bh  + i*16);
            cpa16(sb + GZ_BL  + i*16, bl  + i*16);
            cpa16(sb + GZ_A0H + i*16, a0h + i*16);
            cpa16(sb + GZ_A0L + i*16, a0l + i*16);
        }
        CPA_COMMIT();
    }

    const int a_r = lane & 15, a_c = (lane & 16) >> 1;
    const int b4_r = (lane & 7) + ((lane & 16) >> 1);
    const int b4_c = lane & 8;
    const int q = lane & 3, gq = lane >> 2;

    for (int rt=0; rt<4; rt++){
        const int row0 = (blockIdx.x*4+rt)*128;
        __syncthreads();
        if (rt<3){
            uint32_t dh = ((rt+1)&1) ? (uint32_t)GZ_A1H : (uint32_t)GZ_A0H;
            uint32_t dl = ((rt+1)&1) ? (uint32_t)GZ_A1L : (uint32_t)GZ_A0L;
            const char* ah = (const char*)g_hh + (blockIdx.x*4+rt+1)*128*272;
            const char* al_= (const char*)g_hl + (blockIdx.x*4+rt+1)*128*272;
            for (int i=tid;i<2176;i+=512){
                cpa16(sb + dh + i*16, ah + i*16);
                cpa16(sb + dl + i*16, al_+ i*16);
            }
            CPA_COMMIT();
            CPA_WAIT1();
        } else {
            CPA_WAIT0();
        }
        __syncthreads();
        const uint32_t A_H = (rt&1) ? (uint32_t)GZ_A1H : (uint32_t)GZ_A0H;
        const uint32_t A_L = (rt&1) ? (uint32_t)GZ_A1L : (uint32_t)GZ_A0L;

        float acc[8][4];
        #pragma unroll
        for (int i=0;i<8;i++){ acc[i][0]=0.f; acc[i][1]=0.f; acc[i][2]=0.f; acc[i][3]=0.f; }
        #pragma unroll
        for (int kk=0;kk<8;kk++){
            const int k0 = kk*16;
            uint32_t aaddr = sb + A_H + ((m0+a_r)*136 + k0 + a_c)*2;
            unsigned ahf[4], alf[4];
            ldsm4(ahf, aaddr);
            ldsm4(alf, aaddr + (A_L-A_H));
            #pragma unroll
            for (int ntp=0;ntp<4;ntp++){
                uint32_t baddr = sb + GZ_BH + ((ncol0+ntp*16+b4_r)*136 + k0 + b4_c)*2;
                unsigned bh[4], bl[4];
                ldsm4(bh, baddr);
                ldsm4(bl, baddr + (GZ_BL-GZ_BH));
                float* a0 = acc[ntp*2], *a1 = acc[ntp*2+1];
                mma_bf16(a0, ahf, bh[0], bh[1]);
                mma_bf16(a0, ahf, bl[0], bl[1]);
                mma_bf16(a0, alf, bh[0], bh[1]);
                mma_bf16(a1, ahf, bh[2], bh[3]);
                mma_bf16(a1, ahf, bl[2], bl[3]);
                mma_bf16(a1, alf, bh[2], bh[3]);
            }
        }
        #pragma unroll
        for (int half=0; half<2; half++){
            int row = row0 + m0 + gq + half*8;
            #pragma unroll
            for (int nt=0;nt<8;nt++){
                int col = col0 + ncol0 + nt*8 + q*2;
                *(float2*)&C[row*HD+col] =
                    make_float2(acc[nt][half*2], acc[nt][half*2+1]);
            }
        }
        if (z==0){
            #pragma unroll
            for (int half=0; half<2; half++){
                int rl = m0 + gq + half*8;
                float pl=0.f, pr=0.f;
                #pragma unroll
                for (int nt=0;nt<8;nt++){
                    int col = ncol0 + nt*8 + q*2;
                    float v0 = acc[nt][half*2], v1 = acc[nt][half*2+1];
                    pl += v0*s_al[col] + v1*s_al[col+1];
                    pr += v0*s_ar[col] + v1*s_ar[col+1];
                }
                pl += __shfl_xor_sync(0xffffffffu, pl, 1);
                pl += __shfl_xor_sync(0xffffffffu, pl, 2);
                pr += __shfl_xor_sync(0xffffffffu, pr, 1);
                pr += __shfl_xor_sync(0xffffffffu, pr, 2);
                if (q==0){ s_pl[rl][nh]=pl; s_pr[rl][nh]=pr; }
            }
            __syncthreads();
            if (tid<128){
                int row = row0 + tid;
                g_el[row*NH + blockIdx.y] = s_pl[tid][0]+s_pl[tid][1];
                g_er[row*NH + blockIdx.y] = s_pr[tid][0]+s_pr[tid][1];
            }
        }
    }
}

// ---------------- edge pass + CSR fill (1 atomic/edge) ------------------------
__global__ __launch_bounds__(256) void k_edgefill(const float* __restrict__ e,
        const int* __restrict__ src, const int* __restrict__ dst,
        const float* __restrict__ W_fe, const float* __restrict__ attn_e){
    __shared__ float ce[NH];
    int wid = threadIdx.x>>5, lane = threadIdx.x&31;
    if (wid < NH){
        float p = 0.f;
        #pragma unroll
        for (int q=0;q<4;q++){
            int d = lane + q*32;
            p += W_fe[wid*HDIM+d]*attn_e[wid*HDIM+d];
        }
        #pragma unroll
        for (int off=16; off; off>>=1) p += __shfl_xor_sync(0xffffffffu, p, off);
        if (lane==0) ce[wid]=p;
    }
    __syncthreads();
    int ei = blockIdx.x*256 + threadIdx.x;
    if (ei >= N_EDGES) return;
    int s = src[ei], d = dst[ei];
    float ev = e[ei];
    float4 els = ((const float4*)g_el)[s];
    float4 erd = ((const float4*)g_er)[d];
    float sc[4];
    sc[0] = els.x + erd.x + ev*ce[0];
    sc[1] = els.y + erd.y + ev*ce[1];
    sc[2] = els.z + erd.z + ev*ce[2];
    sc[3] = els.w + erd.w + ev*ce[3];
    float wv[4];
    #pragma unroll
    for (int hh=0;hh<4;hh++){
        float v = sc[hh];
        v = v > 0.f ? v : SLOPE_*v;
        wv[hh] = expf(v);
    }
    int pos = g_rowptr[d] + atomicAdd(&g_cursor[d], 1);
    g_esrc[pos] = s;
    *(float4*)&g_wsH[pos*4] = make_float4(wv[0],wv[1],wv[2],wv[3]);
}

// ---------------- aggregation: local zsum, interleaved weights ----------------
__global__ __launch_bounds__(256) void k_agg(const float* __restrict__ gat_bias){
    int wid = threadIdx.x>>5, lane = threadIdx.x&31;
    int gw = blockIdx.x*8 + wid;
    int n = gw>>2, hh = gw&3;
    int beg = g_rowptr[n], end = g_rowptr[n+1];
    float4 acc = make_float4(0,0,0,0);
    float zsum = 0.f;
    const float4* ft4 = (const float4*)g_ft;
    const float* wp = g_wsH + hh;
    int i = beg;
    for (; i+4<=end; i+=4){
        float w0 = wp[i*4],   w1 = wp[(i+1)*4], w2 = wp[(i+2)*4], w3 = wp[(i+3)*4];
        int   s0 = g_esrc[i], s1 = g_esrc[i+1], s2 = g_esrc[i+2], s3 = g_esrc[i+3];
        float4 v0 = ft4[s0*128 + hh*32 + lane];
        float4 v1 = ft4[s1*128 + hh*32 + lane];
        float4 v2 = ft4[s2*128 + hh*32 + lane];
        float4 v3 = ft4[s3*128 + hh*32 + lane];
        zsum += w0+w1+w2+w3;
        acc.x += w0*v0.x + w1*v1.x + w2*v2.x + w3*v3.x;
        acc.y += w0*v0.y + w1*v1.y + w2*v2.y + w3*v3.y;
        acc.z += w0*v0.z + w1*v1.z + w2*v2.z + w3*v3.z;
        acc.w += w0*v0.w + w1*v1.w + w2*v2.w + w3*v3.w;
    }
    for (; i<end; i++){
        float w0 = wp[i*4];
        int s0 = g_esrc[i];
        float4 v0 = ft4[s0*128 + hh*32 + lane];
        zsum += w0;
        acc.x = fmaf(w0, v0.x, acc.x);
        acc.y = fmaf(w0, v0.y, acc.y);
        acc.z = fmaf(w0, v0.z, acc.z);
        acc.w = fmaf(w0, v0.w, acc.w);
    }
    float zi = zsum > 0.f ? 1.f/zsum : 1.f;
    int base = n*HD + hh*HDIM + lane*4;
    float4 r  = *(const float4*)&g_res[base];
    float4 bv = *(const float4*)&gat_bias[hh*HDIM + lane*4];
    float o0 = fmaxf(acc.x*zi + r.x + bv.x, 0.f);
    float o1 = fmaxf(acc.y*zi + r.y + bv.y, 0.f);
    float o2 = fmaxf(acc.z*zi + r.z + bv.z, 0.f);
    float o3 = fmaxf(acc.w*zi + r.w + bv.w, 0.f);
    int sbase = n*544 + hh*136 + lane*4;
    __nv_bfloat162 h01, h23, l01, l23;
    bsplit(o0, h01.x, l01.x); bsplit(o1, h01.y, l01.y);
    bsplit(o2, h23.x, l23.x); bsplit(o3, h23.y, l23.y);
    *(__nv_bfloat162*)&g_resh[sbase]   = h01;
    *(__nv_bfloat162*)&g_resh[sbase+2] = h23;
    *(__nv_bfloat162*)&g_resl[sbase]   = l01;
    *(__nv_bfloat162*)&g_resl[sbase+2] = l23;
}

// ---------------- MHA: cp.async A + double-buffered Wm -----------------------
#define MH_AH  0
#define MH_AL  34816
#define MH_W0H 69632
#define MH_W0L 104448
#define MH_W1H 139264
#define MH_W1L 174080

__global__ __launch_bounds__(512,1) void k_mha_mma(const float* __restrict__ bm,
        const float* __restrict__ h0, const float* __restrict__ g1,
        const float* __restrict__ be1){
    extern __shared__ char smem[];
    __shared__ float s_s1[128][2], s_s2[128][2];
    const uint32_t sb = smem_u32(smem);
    const int tid = threadIdx.x, lane = tid&31, w = tid>>5;
    const int strip = w>>1, nh = w&1;
    const int m0 = strip*16, ncol0 = nh*64;
    const int row0 = blockIdx.x*128;

    const int a_r = lane & 15, a_c = (lane & 16) >> 1;
    const int b4_r = (lane & 7) + ((lane & 16) >> 1);
    const int b4_c = lane & 8;
    const int q = lane & 3, gq = lane >> 2;

    float acc[8][4];
    #pragma unroll
    for (int i=0;i<8;i++){ acc[i][0]=0.f; acc[i][1]=0.f; acc[i][2]=0.f; acc[i][3]=0.f; }

    {
        const char* sh = (const char*)g_wmth;
        const char* sl = (const char*)g_wmtl;
        for (int i=tid;i<2176;i+=512){
            cpa16(sb + MH_W0H + i*16, sh + i*16);
            cpa16(sb + MH_W0L + i*16, sl + i*16);
        }
        CPA_COMMIT();
    }

    for (int c=0; c<4; c++){
        const int cur = c & 1;
        __syncthreads();
        {
            for (int i=tid;i<2176;i+=512){
                int m = i/17, o = i - m*17;
                long so = (long)(row0+m)*1088 + c*272 + o*16;
                cpa16(sb + MH_AH + m*272 + o*16, (const char*)g_resh + so);
                cpa16(sb + MH_AL + m*272 + o*16, (const char*)g_resl + so);
            }
            CPA_COMMIT();
        }
        if (c < 3){
            uint32_t dh = cur ? (uint32_t)MH_W0H : (uint32_t)MH_W1H;
            uint32_t dl = cur ? (uint32_t)MH_W0L : (uint32_t)MH_W1L;
            const char* sh = (const char*)(g_wmth + (c+1)*128*136);
            const char* sl = (const char*)(g_wmtl + (c+1)*128*136);
            for (int i=tid;i<2176;i+=512){
                cpa16(sb + dh + i*16, sh + i*16);
                cpa16(sb + dl + i*16, sl + i*16);
            }
            CPA_COMMIT();
            CPA_WAIT1();
        } else {
            CPA_WAIT0();
        }
        __syncthreads();

        const uint32_t wbh = cur ? (uint32_t)MH_W1H : (uint32_t)MH_W0H;
        const uint32_t wbl = cur ? (uint32_t)MH_W1L : (uint32_t)MH_W0L;
        #pragma unroll
        for (int kk=0;kk<8;kk++){
            const int k0 = kk*16;
            uint32_t aaddr = sb + MH_AH + ((m0+a_r)*136 + k0 + a_c)*2;
            unsigned ahf[4], alf[4];
            ldsm4(ahf, aaddr);
            ldsm4(alf, aaddr + (MH_AL-MH_AH));
            #pragma unroll
            for (int ntp=0;ntp<4;ntp++){
                uint32_t boff = ((ncol0+ntp*16+b4_r)*136 + k0 + b4_c)*2;
                unsigned bh[4], bl[4];
                ldsm4(bh, sb + wbh + boff);
                ldsm4(bl, sb + wbl + boff);
                float* a0 = acc[ntp*2], *a1 = acc[ntp*2+1];
                mma_bf16(a0, ahf, bh[0], bh[1]);
                mma_bf16(a0, ahf, bl[0], bl[1]);
                mma_bf16(a0, alf, bh[0], bh[1]);
                mma_bf16(a1, ahf, bh[2], bh[3]);
                mma_bf16(a1, ahf, bl[2], bl[3]);
                mma_bf16(a1, alf, bh[2], bh[3]);
            }
        }
    }

    #pragma unroll
    for (int half=0; half<2; half++){
        int rl = m0 + gq + half*8;
        int row = row0 + rl;
        float tv[16], s1=0.f, s2=0.f;
        #pragma unroll
        for (int nt=0;nt<8;nt++){
            int col = ncol0 + nt*8 + q*2;
            float t0 = fmaxf(acc[nt][half*2+0] + bm[col],   0.f) + h0[row*HID_+col];
            float t1 = fmaxf(acc[nt][half*2+1] + bm[col+1], 0.f) + h0[row*HID_+col+1];
            tv[nt*2]=t0; tv[nt*2+1]=t1;
            s1 += t0+t1; s2 += t0*t0+t1*t1;
        }
        s1 += __shfl_xor_sync(0xffffffffu, s1, 1); s2 += __shfl_xor_sync(0xffffffffu, s2, 1);
        s1 += __shfl_xor_sync(0xffffffffu, s1, 2); s2 += __shfl_xor_sync(0xffffffffu, s2, 2);
        if (q==0){ s_s1[rl][nh]=s1; s_s2[rl][nh]=s2; }
        __syncthreads();
        float fs1 = s_s1[rl][0]+s_s1[rl][1];
        float fs2 = s_s2[rl][0]+s_s2[rl][1];
        float mean = fs1*(1.f/HID_);
        float var  = fs2*(1.f/HID_) - mean*mean;
        float rs   = rsqrtf(var + EPS_);
        #pragma unroll
        for (int nt=0;nt<8;nt++){
            int col = ncol0 + nt*8 + q*2;
            float x0 = (tv[nt*2]  -mean)*rs*g1[col]   + be1[col];
            float x1 = (tv[nt*2+1]-mean)*rs*g1[col+1] + be1[col+1];
            *(float2*)&g_x1[row*HID_+col] = make_float2(x0, x1);
            __nv_bfloat162 hh, ll;
            bsplit(x0, hh.x, ll.x); bsplit(x1, hh.y, ll.y);
            *(__nv_bfloat162*)&g_x1h[row*136+col] = hh;
            *(__nv_bfloat162*)&g_x1l[row*136+col] = ll;
        }
        __syncthreads();
    }
}

// ---------------- FFN: cp.async xs/W1 + W2 double-buffer ----------------------
#define SM_XS_H 0
#define SM_XS_L 34816
#define SM_W1H  69632
#define SM_W1L  87040
#define SM_W2H  104448
#define SM_W2L  122880
#define SM_MIDH 141312
#define SM_MIDL 159744
#define SM_W2H2 178176
#define SM_W2L2 196608
#define SMEM_FFN 215040

__global__ __launch_bounds__(512,1) void k_ffn_mma(const float* __restrict__ b1v,
        const float* __restrict__ b2v, const float* __restrict__ g2,
        const float* __restrict__ be2, float* __restrict__ out){
    extern __shared__ char smem[];
    __shared__ float s_s1[128][2], s_s2[128][2];
    __nv_bfloat16* mid_h= (__nv_bfloat16*)(smem+SM_MIDH);
    __nv_bfloat16* mid_l= (__nv_bfloat16*)(smem+SM_MIDL);
    const uint32_t sb = smem_u32(smem);
    const int tid = threadIdx.x, lane = tid&31, w = tid>>5;
    const int strip = w>>1, nh = w&1;
    const int m0 = strip*16;
    const int row0 = blockIdx.x*128;

    {
        const char* sh = (const char*)g_x1h + row0*272;
        const char* sl = (const char*)g_x1l + row0*272;
        for (int i=tid;i<2176;i+=512){
            cpa16(sb + SM_XS_H + i*16, sh + i*16);
            cpa16(sb + SM_XS_L + i*16, sl + i*16);
        }
        CPA_COMMIT();
    }
    {
        const uint4* s2h = (const uint4*)(g_w2th);
        const uint4* s2l = (const uint4*)(g_w2tl);
        for (int i=tid;i<1152;i+=512){
            cpa16(sb + SM_W2H + i*16, s2h+i);
            cpa16(sb + SM_W2L + i*16, s2l+i);
        }
        CPA_COMMIT();
    }

    float acc2[8][4];
    #pragma unroll
    for (int i=0;i<8;i++){ acc2[i][0]=0.f; acc2[i][1]=0.f; acc2[i][2]=0.f; acc2[i][3]=0.f; }

    const int a_r = lane & 15, a_c = (lane & 16) >> 1;
    const int b4_r = (lane & 7) + ((lane & 16) >> 1);
    const int b4_c = lane & 8;
    const int q = lane & 3, gq = lane >> 2;

    for (int c=0; c<32; c++){
        const int cur = c & 1;
        __syncthreads();
        {
            const uint4* s1h = (const uint4*)(g_w1th + c*64*136);
            const uint4* s1l = (const uint4*)(g_w1tl + c*64*136);
            for (int i=tid;i<1088;i+=512){
                cpa16(sb + SM_W1H + i*16, s1h+i);
                cpa16(sb + SM_W1L + i*16, s1l+i);
            }
            CPA_COMMIT();
        }
        if (c+1 < 32){
            uint32_t dh = cur ? (uint32_t)SM_W2H : (uint32_t)SM_W2H2;
            uint32_t dl = cur ? (uint32_t)SM_W2L : (uint32_t)SM_W2L2;
            const uint4* s2h = (const uint4*)(g_w2th + (c+1)*128*72);
            const uint4* s2l = (const uint4*)(g_w2tl + (c+1)*128*72);
            for (int i=tid;i<1152;i+=512){
                cpa16(sb + dh + i*16, s2h+i);
                cpa16(sb + dl + i*16, s2l+i);
            }
            CPA_COMMIT();
            CPA_WAIT1();
        } else {
            CPA_WAIT0();
        }
        __syncthreads();

        float acc1[4][4];
        #pragma unroll
        for (int i=0;i<4;i++){ acc1[i][0]=0.f; acc1[i][1]=0.f; acc1[i][2]=0.f; acc1[i][3]=0.f; }
        #pragma unroll
        for (int kk=0;kk<8;kk++){
            const int k0 = kk*16;
            uint32_t aaddr = sb + SM_XS_H + ((m0+a_r)*136 + k0 + a_c)*2;
            unsigned ah[4], al[4];
            ldsm4(ah, aaddr);
            ldsm4(al, aaddr + (SM_XS_L - SM_XS_H));
            #pragma unroll
            for (int ntp=0;ntp<2;ntp++){
                uint32_t baddr = sb + SM_W1H + ((nh*32+ntp*16+b4_r)*136 + k0 + b4_c)*2;
                unsigned bh[4], bl[4];
                ldsm4(bh, baddr);
                ldsm4(bl, baddr + (SM_W1L - SM_W1H));
                float* a0 = acc1[ntp*2], *a1 = acc1[ntp*2+1];
                mma_bf16(a0, ah, bh[0], bh[1]);
                mma_bf16(a0, ah, bl[0], bl[1]);
                mma_bf16(a0, al, bh[0], bh[1]);
                mma_bf16(a1, ah, bh[2], bh[3]);
                mma_bf16(a1, ah, bl[2], bl[3]);
                mma_bf16(a1, al, bh[2], bh[3]);
            }
        }
        {
            const int r1 = m0 + gq, r2 = r1 + 8;
            #pragma unroll
            for (int nt=0;nt<2;nt++){
                int col = nh*32 + nt*8 + q*2;
                float bb0 = b1v[c*64+col], bb1 = b1v[c*64+col+1];
                float v0 = fmaxf(acc1[nt][0]+bb0, 0.f);
                float v1 = fmaxf(acc1[nt][1]+bb1, 0.f);
                float v2 = fmaxf(acc1[nt][2]+bb0, 0.f);
                float v3 = fmaxf(acc1[nt][3]+bb1, 0.f);
                __nv_bfloat162 hh, ll;
                bsplit(v0, hh.x, ll.x); bsplit(v1, hh.y, ll.y);
                *(__nv_bfloat162*)&mid_h[r1*72+col]=hh;
                *(__nv_bfloat162*)&mid_l[r1*72+col]=ll;
                bsplit(v2, hh.x, ll.x); bsplit(v3, hh.y, ll.y);
                *(__nv_bfloat162*)&mid_h[r2*72+col]=hh;
                *(__nv_bfloat162*)&mid_l[r2*72+col]=ll;
            }
            #pragma unroll
            for (int nt=2;nt<4;nt++){
                int col = nh*32 + (nt-2)*8 + 16 + q*2;
                float bb0 = b1v[c*64+col], bb1 = b1v[c*64+col+1];
                float v0 = fmaxf(acc1[nt][0]+bb0, 0.f);
                float v1 = fmaxf(acc1[nt][1]+bb1, 0.f);
                float v2 = fmaxf(acc1[nt][2]+bb0, 0.f);
                float v3 = fmaxf(acc1[nt][3]+bb1, 0.f);
                __nv_bfloat162 hh, ll;
                bsplit(v0, hh.x, ll.x); bsplit(v1, hh.y, ll.y);
                *(__nv_bfloat162*)&mid_h[r1*72+col]=hh;
                *(__nv_bfloat162*)&mid_l[r1*72+col]=ll;
                bsplit(v2, hh.x, ll.x); bsplit(v3, hh.y, ll.y);
                *(__nv_bfloat162*)&mid_h[r2*72+col]=hh;
                *(__nv_bfloat162*)&mid_l[r2*72+col]=ll;
            }
        }
        __syncthreads();

        const uint32_t w2h_base = cur ? (uint32_t)SM_W2H2 : (uint32_t)SM_W2H;
        #pragma unroll
        for (int kk=0;kk<4;kk++){
            const int k0 = kk*16;
            uint32_t aaddr = sb + SM_MIDH + ((m0+a_r)*72 + k0 + a_c)*2;
            unsigned ah[4], al[4];
            ldsm4(ah, aaddr);
            ldsm4(al, aaddr + (SM_MIDL - SM_MIDH));
            #pragma unroll
            for (int ntp=0;ntp<4;ntp++){
                uint32_t baddr = sb + w2h_base + ((nh*64+ntp*16+b4_r)*72 + k0 + b4_c)*2;
                unsigned bh[4], bl[4];
                ldsm4(bh, baddr);
                ldsm4(bl, baddr + 18432);
                float* a0 = acc2[ntp*2], *a1 = acc2[ntp*2+1];
                mma_bf16(a0, ah, bh[0], bh[1]);
                mma_bf16(a0, ah, bl[0], bl[1]);
                mma_bf16(a0, al, bh[0], bh[1]);
                mma_bf16(a1, ah, bh[2], bh[3]);
                mma_bf16(a1, ah, bl[2], bl[3]);
                mma_bf16(a1, al, bh[2], bh[3]);
            }
        }
    }

    #pragma unroll
    for (int half=0; half<2; half++){
        int rl = m0 + gq + half*8;
        int grow = row0 + rl;
        float tv[16], s1=0.f, s2=0.f;
        #pragma unroll
        for (int nt=0;nt<8;nt++){
            int col = nh*64 + nt*8 + q*2;
            float t0 = acc2[nt][half*2+0] + b2v[col]   + g_x1[grow*HID_+col];
            float t1 = acc2[nt][half*2+1] + b2v[col+1] + g_x1[grow*HID_+col+1];
            tv[nt*2]=t0; tv[nt*2+1]=t1;
            s1 += t0+t1; s2 += t0*t0+t1*t1;
        }
        s1 += __shfl_xor_sync(0xffffffffu, s1, 1); s2 += __shfl_xor_sync(0xffffffffu, s2, 1);
        s1 += __shfl_xor_sync(0xffffffffu, s1, 2); s2 += __shfl_xor_sync(0xffffffffu, s2, 2);
        if (q==0){ s_s1[rl][nh]=s1; s_s2[rl][nh]=s2; }
        __syncthreads();
        float fs1 = s_s1[rl][0]+s_s1[rl][1];
        float fs2 = s_s2[rl][0]+s_s2[rl][1];
        float mean = fs1*(1.f/HID_);
        float var  = fs2*(1.f/HID_) - mean*mean;
        float rs   = rsqrtf(var + EPS_);
        #pragma unroll
        for (int nt=0;nt<8;nt++){
            int col = nh*64 + nt*8 + q*2;
            out[grow*HID_+col]   = (tv[nt*2]  -mean)*rs*g2[col]   + be2[col];
            out[grow*HID_+col+1] = (tv[nt*2+1]-mean)*rs*g2[col+1] + be2[col+1];
        }
        __syncthreads();
    }
}

// ---------------- launch ----------------------------------------------------
extern "C" void kernel_launch(void* const* d_in, const int* in_sizes, int n_in,
                              void* d_out, int out_size){
    int o = (in_sizes[4] == 1) ? 1 : 0;
    const float* h       = (const float*)d_in[0];
    const float* e       = (const float*)d_in[1];
    const int*   src     = (const int*)  d_in[2];
    const int*   dst     = (const int*)  d_in[3];
    const float* W_fc    = (const float*)d_in[4+o];
    const float* attn_l  = (const float*)d_in[5+o];
    const float* attn_r  = (const float*)d_in[6+o];
    const float* W_fe    = (const float*)d_in[7+o];
    const float* attn_e  = (const float*)d_in[8+o];
    const float* W_res   = (const float*)d_in[9+o];
    const float* gatb    = (const float*)d_in[10+o];
    const float* W_mha   = (const float*)d_in[11+o];
    const float* b_mha   = (const float*)d_in[12+o];
    const float* n1_g    = (const float*)d_in[13+o];
    const float* n1_b    = (const float*)d_in[14+o];
    const float* n2_g    = (const float*)d_in[15+o];
    const float* n2_b    = (const float*)d_in[16+o];
    const float* W1      = (const float*)d_in[17+o];
    const float* b1      = (const float*)d_in[18+o];
    const float* W2      = (const float*)d_in[19+o];
    const float* b2      = (const float*)d_in[20+o];
    float* out = (float*)d_out;

    cudaFuncSetAttribute(k_ffn_mma,  cudaFuncAttributeMaxDynamicSharedMemorySize, SMEM_FFN);
    cudaFuncSetAttribute(k_gemmA_mma,cudaFuncAttributeMaxDynamicSharedMemorySize, SMEM_GZ);
    cudaFuncSetAttribute(k_mha_mma,  cudaFuncAttributeMaxDynamicSharedMemorySize, SMEM_MH);

    k_init<<<128,256>>>();
    k_prep<<<1024,256>>>(W1, W2, W_fc, W_res, W_mha, h, dst);
    k_scan1<<<128,256>>>();
    k_scan2<<<1,128>>>();
    k_scan3<<<128,256>>>();
    dim3 gA(64, 4, 2);
    k_gemmA_mma<<<gA,512,SMEM_GZ>>>(attn_l, attn_r);
    k_edgefill<<<N_EDGES/256,256>>>(e, src, dst, W_fe, attn_e);
    k_agg<<<N_NODES*NH/8,256>>>(gatb);
    k_mha_mma<<<N_NODES/128,512,SMEM_MH>>>(b_mha, h, n1_g, n1_b);
    k_ffn_mma<<<N_NODES/128,512,SMEM_FFN>>>(b1, b2, n2_g, n2_b, out);
}

// round 15
// speedup vs baseline: 1.4121x; 1.0526x over previous
#include <cuda_runtime.h>
#include <cuda_bf16.h>
#include <cuda_fp16.h>
#include <cstdint>

#define N_NODES 32768
#define N_EDGES 524288
#define NH      4
#define HDIM    128
#define HD      512
#define HID_    128
#define DFF_    2048
#define SLOPE_  0.2f
#define EPS_    1e-5f

// ---------------- scratch ----------------------------------------------------
__device__ __align__(16) __half g_fth[N_NODES*HD];   // ft in fp16 (k_agg only)
__device__ float    g_res[N_NODES*HD];
__device__ float    g_el [N_NODES*NH];
__device__ float    g_er [N_NODES*NH];
__device__ int      g_deg[N_NODES];
__device__ int      g_cursor[N_NODES];
__device__ int      g_rowptr[N_NODES+1];
__device__ int      g_bsum[128];
__device__ int      g_esrc[N_EDGES];
__device__ __align__(16) float g_wsH[N_EDGES*4];
__device__ float    g_x1 [N_NODES*HID_];

// pre-split activations (bf16 hi/lo, 136-padded rows)
__device__ __align__(16) __nv_bfloat16 g_hh  [N_NODES*136];
__device__ __align__(16) __nv_bfloat16 g_hl  [N_NODES*136];
__device__ __align__(16) __nv_bfloat16 g_resh[N_NODES*544];
__device__ __align__(16) __nv_bfloat16 g_resl[N_NODES*544];
__device__ __align__(16) __nv_bfloat16 g_x1h [N_NODES*136];
__device__ __align__(16) __nv_bfloat16 g_x1l [N_NODES*136];

// pre-split hi/lo bf16 transposed weights ([n][k] padded rows)
__device__ __align__(16) __nv_bfloat16 g_w1th[32*64*136];
__device__ __align__(16) __nv_bfloat16 g_w1tl[32*64*136];
__device__ __align__(16) __nv_bfloat16 g_w2th[32*128*72];
__device__ __align__(16) __nv_bfloat16 g_w2tl[32*128*72];
__device__ __align__(16) __nv_bfloat16 g_wfth[512*136];
__device__ __align__(16) __nv_bfloat16 g_wftl[512*136];
__device__ __align__(16) __nv_bfloat16 g_wrth[512*136];
__device__ __align__(16) __nv_bfloat16 g_wrtl[512*136];
__device__ __align__(16) __nv_bfloat16 g_wmth[512*136];
__device__ __align__(16) __nv_bfloat16 g_wmtl[512*136];

// ---------------- helpers ------------------------------------------------------
__device__ __forceinline__ uint32_t smem_u32(const void* p){
    uint32_t a;
    asm("{ .reg .u64 t; cvta.to.shared.u64 t, %1; cvt.u32.u64 %0, t; }" : "=r"(a) : "l"(p));
    return a;
}
__device__ __forceinline__ void ldsm4(unsigned* r, uint32_t addr){
    asm volatile("ldmatrix.sync.aligned.m8n8.x4.shared.b16 {%0,%1,%2,%3}, [%4];"
        : "=r"(r[0]),"=r"(r[1]),"=r"(r[2]),"=r"(r[3]) : "r"(addr));
}
__device__ __forceinline__ void mma_bf16(float* c, const unsigned* a, unsigned b0, unsigned b1){
    asm volatile("mma.sync.aligned.m16n8k16.row.col.f32.bf16.bf16.f32 "
        "{%0,%1,%2,%3},{%4,%5,%6,%7},{%8,%9},{%0,%1,%2,%3};"
        : "+f"(c[0]),"+f"(c[1]),"+f"(c[2]),"+f"(c[3])
        : "r"(a[0]),"r"(a[1]),"r"(a[2]),"r"(a[3]),"r"(b0),"r"(b1));
}
__device__ __forceinline__ void bsplit(float v, __nv_bfloat16& hi, __nv_bfloat16& lo){
    hi = __float2bfloat16(v);
    lo = __float2bfloat16(v - __bfloat162float(hi));
}
__device__ __forceinline__ void cpa16(uint32_t saddr, const void* g){
    asm volatile("cp.async.cg.shared.global [%0], [%1], 16;" :: "r"(saddr), "l"(g));
}
#define CPA_COMMIT() asm volatile("cp.async.commit_group;" ::: "memory")
#define CPA_WAIT1()  asm volatile("cp.async.wait_group 1;" ::: "memory")
#define CPA_WAIT0()  asm volatile("cp.async.wait_group 0;" ::: "memory")

// ---------------- init ------------------------------------------------------
__global__ void k_init(){
    int i = blockIdx.x*256 + threadIdx.x;
    if (i < N_NODES){ g_deg[i] = 0; g_cursor[i] = 0; }
}

// ---------------- prep (+ degree count) ---------------------------------------
__global__ void k_prep(const float* __restrict__ W1, const float* __restrict__ W2,
                       const float* __restrict__ Wfc, const float* __restrict__ Wres,
                       const float* __restrict__ Wm, const float* __restrict__ h,
                       const int* __restrict__ dst){
    int i = blockIdx.x*256 + threadIdx.x;   // 262144 threads
    atomicAdd(&g_deg[dst[i]], 1);
    atomicAdd(&g_deg[dst[i + 262144]], 1);
    {   // W1 [k=128][n=2048]
        int k = i >> 11, n = i & 2047;
        __nv_bfloat16 hv, lv; bsplit(W1[i], hv, lv);
        int c = n >> 6, nn = n & 63;
        g_w1th[(c*64+nn)*136 + k] = hv;
        g_w1tl[(c*64+nn)*136 + k] = lv;
    }
    {   // W2 [k2=2048][n=128]
        int k2 = i >> 7, n = i & 127;
        __nv_bfloat16 hv, lv; bsplit(W2[i], hv, lv);
        int c = k2 >> 6, kk = k2 & 63;
        g_w2th[(c*128+n)*72 + kk] = hv;
        g_w2tl[(c*128+n)*72 + kk] = lv;
    }
    #pragma unroll
    for (int j=0;j<16;j++){
        int idx = i + j*262144;
        int n = idx >> 7, k = idx & 127;
        __nv_bfloat16 hv, lv; bsplit(h[idx], hv, lv);
        g_hh[n*136+k] = hv;
        g_hl[n*136+k] = lv;
    }
    if (i < 65536){
        {   // Wfc/Wres [k=128][n=512]
            int k = i >> 9, n = i & 511;
            __nv_bfloat16 hv, lv;
            bsplit(Wfc[i], hv, lv);
            g_wfth[n*136 + k] = hv; g_wftl[n*136 + k] = lv;
            bsplit(Wres[i], hv, lv);
            g_wrth[n*136 + k] = hv; g_wrtl[n*136 + k] = lv;
        }
        {   // Wm [k2=512][n=128]
            int k2 = i >> 7, n = i & 127;
            __nv_bfloat16 hv, lv; bsplit(Wm[i], hv, lv);
            int c = k2 >> 7, kk = k2 & 127;
            g_wmth[(c*128+n)*136 + kk] = hv;
            g_wmtl[(c*128+n)*136 + kk] = lv;
        }
    }
}

// ---------------- hierarchical CSR scan ---------------------------------------
__global__ __launch_bounds__(256) void k_scan1(){
    int b = blockIdx.x, t = threadIdx.x;
    int node = b*256 + t;
    int d = g_deg[node];
    int v = d;
    #pragma unroll
    for (int off=1; off<32; off<<=1){
        int nv = __shfl_up_sync(0xffffffffu, v, off);
        if ((t&31) >= off) v += nv;
    }
    __shared__ int wsum[8];
    if ((t&31)==31) wsum[t>>5] = v;
    __syncthreads();
    if (t < 8){
        int wv = wsum[t];
        #pragma unroll
        for (int off=1; off<8; off<<=1){
            int nv = __shfl_up_sync(0xffu, wv, off);
            if (t >= off) wv += nv;
        }
        wsum[t] = wv;
    }
    __syncthreads();
    int incl = v + ((t>=32) ? wsum[(t>>5)-1] : 0);
    g_rowptr[node] = incl - d;
    if (t==255) g_bsum[b] = incl;
}

__global__ __launch_bounds__(128) void k_scan2(){
    int t = threadIdx.x;
    int v = g_bsum[t];
    int x = v;
    #pragma unroll
    for (int off=1; off<32; off<<=1){
        int nv = __shfl_up_sync(0xffffffffu, x, off);
        if ((t&31) >= off) x += nv;
    }
    __shared__ int ws[4];
    if ((t&31)==31) ws[t>>5] = x;
    __syncthreads();
    if (t < 4){
        int wv = ws[t];
        #pragma unroll
        for (int off=1; off<4; off<<=1){
            int nv = __shfl_up_sync(0xfu, wv, off);
            if (t >= off) wv += nv;
        }
        ws[t] = wv;
    }
    __syncthreads();
    int incl = x + ((t>=32) ? ws[(t>>5)-1] : 0);
    g_bsum[t] = incl - v;
    if (t==127) g_rowptr[N_NODES] = incl;
}

__global__ __launch_bounds__(256) void k_scan3(){
    int node = blockIdx.x*256 + threadIdx.x;
    g_rowptr[node] += g_bsum[blockIdx.x];
}

// ---------------- GEMM A: z-split, A double-buffered via cp.async ------------
#define GZ_A0H 0
#define GZ_A0L 34816
#define GZ_A1H 69632
#define GZ_A1L 104448
#define GZ_BH  139264
#define GZ_BL  174080
#define SMEM_GZ 208896
#define SMEM_MH 208896

__global__ __launch_bounds__(512,1) void k_gemmA_mma(
        const float* __restrict__ attn_l, const float* __restrict__ attn_r){
    extern __shared__ char smem[];
    __shared__ float s_al[128], s_ar[128];
    __shared__ float s_pl[128][2], s_pr[128][2];
    const uint32_t sb = smem_u32(smem);
    const int tid = threadIdx.x, lane = tid&31, w = tid>>5;
    const int strip = w>>1, nh = w&1;
    const int m0 = strip*16, ncol0 = nh*64;
    const int col0 = blockIdx.y*128;
    const int z = blockIdx.z;
    const __nv_bfloat16* Bh = z ? g_wrth : g_wfth;
    const __nv_bfloat16* Bl = z ? g_wrtl : g_wftl;

    if (z==0 && tid<128){
        s_al[tid] = attn_l[col0+tid];
        s_ar[tid] = attn_r[col0+tid];
    }
    {   // G0: B tile + A(0)
        const char* bh = (const char*)(Bh + col0*136);
        const char* bl = (const char*)(Bl + col0*136);
        const char* a0h = (const char*)g_hh + (blockIdx.x*4+0)*128*272;
        const char* a0l = (const char*)g_hl + (blockIdx.x*4+0)*128*272;
        for (int i=tid;i<2176;i+=512){
            cpa16(sb + GZ_BH  + i*16, bh  + i*16);
            cpa16(sb + GZ_BL  + i*16, bl  + i*16);
            cpa16(sb + GZ_A0H + i*16, a0h + i*16);
            cpa16(sb + GZ_A0L + i*16, a0l + i*16);
        }
        CPA_COMMIT();
    }

    const int a_r = lane & 15, a_c = (lane & 16) >> 1;
    const int b4_r = (lane & 7) + ((lane & 16) >> 1);
    const int b4_c = lane & 8;
    const int q = lane & 3, gq = lane >> 2;

    for (int rt=0; rt<4; rt++){
        const int row0 = (blockIdx.x*4+rt)*128;
        __syncthreads();
        if (rt<3){
            uint32_t dh = ((rt+1)&1) ? (uint32_t)GZ_A1H : (uint32_t)GZ_A0H;
            uint32_t dl = ((rt+1)&1) ? (uint32_t)GZ_A1L : (uint32_t)GZ_A0L;
            const char* ah = (const char*)g_hh + (blockIdx.x*4+rt+1)*128*272;
            const char* al_= (const char*)g_hl + (blockIdx.x*4+rt+1)*128*272;
            for (int i=tid;i<2176;i+=512){
                cpa16(sb + dh + i*16, ah + i*16);
                cpa16(sb + dl + i*16, al_+ i*16);
            }
            CPA_COMMIT();
            CPA_WAIT1();
        } else {
            CPA_WAIT0();
        }
        __syncthreads();
        const uint32_t A_H = (rt&1) ? (uint32_t)GZ_A1H : (uint32_t)GZ_A0H;
        const uint32_t A_L = (rt&1) ? (uint32_t)GZ_A1L : (uint32_t)GZ_A0L;

        float acc[8][4];
        #pragma unroll
        for (int i=0;i<8;i++){ acc[i][0]=0.f; acc[i][1]=0.f; acc[i][2]=0.f; acc[i][3]=0.f; }
        #pragma unroll
        for (int kk=0;kk<8;kk++){
            const int k0 = kk*16;
            uint32_t aaddr = sb + A_H + ((m0+a_r)*136 + k0 + a_c)*2;
            unsigned ahf[4], alf[4];
            ldsm4(ahf, aaddr);
            ldsm4(alf, aaddr + (A_L-A_H));
            #pragma unroll
            for (int ntp=0;ntp<4;ntp++){
                uint32_t baddr = sb + GZ_BH + ((ncol0+ntp*16+b4_r)*136 + k0 + b4_c)*2;
                unsigned bh[4], bl[4];
                ldsm4(bh, baddr);
                ldsm4(bl, baddr + (GZ_BL-GZ_BH));
                float* a0 = acc[ntp*2], *a1 = acc[ntp*2+1];
                mma_bf16(a0, ahf, bh[0], bh[1]);
                mma_bf16(a0, ahf, bl[0], bl[1]);
                mma_bf16(a0, alf, bh[0], bh[1]);
                mma_bf16(a1, ahf, bh[2], bh[3]);
                mma_bf16(a1, ahf, bl[2], bl[3]);
                mma_bf16(a1, alf, bh[2], bh[3]);
            }
        }
        if (z==0){
            #pragma unroll
            for (int half=0; half<2; half++){
                int row = row0 + m0 + gq + half*8;
                #pragma unroll
                for (int nt=0;nt<8;nt++){
                    int col = col0 + ncol0 + nt*8 + q*2;
                    *(__half2*)&g_fth[row*HD+col] =
                        __floats2half2_rn(acc[nt][half*2], acc[nt][half*2+1]);
                }
            }
            #pragma unroll
            for (int half=0; half<2; half++){
                int rl = m0 + gq + half*8;
                float pl=0.f, pr=0.f;
                #pragma unroll
                for (int nt=0;nt<8;nt++){
                    int col = ncol0 + nt*8 + q*2;
                    float v0 = acc[nt][half*2], v1 = acc[nt][half*2+1];
                    pl += v0*s_al[col] + v1*s_al[col+1];
                    pr += v0*s_ar[col] + v1*s_ar[col+1];
                }
                pl += __shfl_xor_sync(0xffffffffu, pl, 1);
                pl += __shfl_xor_sync(0xffffffffu, pl, 2);
                pr += __shfl_xor_sync(0xffffffffu, pr, 1);
                pr += __shfl_xor_sync(0xffffffffu, pr, 2);
                if (q==0){ s_pl[rl][nh]=pl; s_pr[rl][nh]=pr; }
            }
            __syncthreads();
            if (tid<128){
                int row = row0 + tid;
                g_el[row*NH + blockIdx.y] = s_pl[tid][0]+s_pl[tid][1];
                g_er[row*NH + blockIdx.y] = s_pr[tid][0]+s_pr[tid][1];
            }
        } else {
            #pragma unroll
            for (int half=0; half<2; half++){
                int row = row0 + m0 + gq + half*8;
                #pragma unroll
                for (int nt=0;nt<8;nt++){
                    int col = col0 + ncol0 + nt*8 + q*2;
                    *(float2*)&g_res[row*HD+col] =
                        make_float2(acc[nt][half*2], acc[nt][half*2+1]);
                }
            }
        }
    }
}

// ---------------- edge pass + CSR fill (1 atomic/edge) ------------------------
__global__ __launch_bounds__(256) void k_edgefill(const float* __restrict__ e,
        const int* __restrict__ src, const int* __restrict__ dst,
        const float* __restrict__ W_fe, const float* __restrict__ attn_e){
    __shared__ float ce[NH];
    int wid = threadIdx.x>>5, lane = threadIdx.x&31;
    if (wid < NH){
        float p = 0.f;
        #pragma unroll
        for (int q=0;q<4;q++){
            int d = lane + q*32;
            p += W_fe[wid*HDIM+d]*attn_e[wid*HDIM+d];
        }
        #pragma unroll
        for (int off=16; off; off>>=1) p += __shfl_xor_sync(0xffffffffu, p, off);
        if (lane==0) ce[wid]=p;
    }
    __syncthreads();
    int ei = blockIdx.x*256 + threadIdx.x;
    if (ei >= N_EDGES) return;
    int s = src[ei], d = dst[ei];
    float ev = e[ei];
    float4 els = ((const float4*)g_el)[s];
    float4 erd = ((const float4*)g_er)[d];
    float sc[4];
    sc[0] = els.x + erd.x + ev*ce[0];
    sc[1] = els.y + erd.y + ev*ce[1];
    sc[2] = els.z + erd.z + ev*ce[2];
    sc[3] = els.w + erd.w + ev*ce[3];
    float wv[4];
    #pragma unroll
    for (int hh=0;hh<4;hh++){
        float v = sc[hh];
        v = v > 0.f ? v : SLOPE_*v;
        wv[hh] = expf(v);
    }
    int pos = g_rowptr[d] + atomicAdd(&g_cursor[d], 1);
    g_esrc[pos] = s;
    *(float4*)&g_wsH[pos*4] = make_float4(wv[0],wv[1],wv[2],wv[3]);
}

// ---------------- aggregation: fp16 gathers, local zsum ------------------------
__global__ __launch_bounds__(256) void k_agg(const float* __restrict__ gat_bias){
    int wid = threadIdx.x>>5, lane = threadIdx.x&31;
    int gw = blockIdx.x*8 + wid;
    int n = gw>>2, hh = gw&3;
    int beg = g_rowptr[n], end = g_rowptr[n+1];
    float4 acc = make_float4(0,0,0,0);
    float zsum = 0.f;
    const __half2* fth = (const __half2*)g_fth;
    const float* wp = g_wsH + hh;
    const int lofs = hh*64 + lane*2;    // __half2 index within node row (256 h2/row)
    int i = beg;
    for (; i+4<=end; i+=4){
        float w0 = wp[i*4],   w1 = wp[(i+1)*4], w2 = wp[(i+2)*4], w3 = wp[(i+3)*4];
        int   s0 = g_esrc[i], s1 = g_esrc[i+1], s2 = g_esrc[i+2], s3 = g_esrc[i+3];
        __half2 p0a = fth[s0*256 + lofs], p0b = fth[s0*256 + lofs + 1];
        __half2 p1a = fth[s1*256 + lofs], p1b = fth[s1*256 + lofs + 1];
        __half2 p2a = fth[s2*256 + lofs], p2b = fth[s2*256 + lofs + 1];
        __half2 p3a = fth[s3*256 + lofs], p3b = fth[s3*256 + lofs + 1];
        float2 f0a = __half22float2(p0a), f0b = __half22float2(p0b);
        float2 f1a = __half22float2(p1a), f1b = __half22float2(p1b);
        float2 f2a = __half22float2(p2a), f2b = __half22float2(p2b);
        float2 f3a = __half22float2(p3a), f3b = __half22float2(p3b);
        zsum += w0+w1+w2+w3;
        acc.x += w0*f0a.x + w1*f1a.x + w2*f2a.x + w3*f3a.x;
        acc.y += w0*f0a.y + w1*f1a.y + w2*f2a.y + w3*f3a.y;
        acc.z += w0*f0b.x + w1*f1b.x + w2*f2b.x + w3*f3b.x;
        acc.w += w0*f0b.y + w1*f1b.y + w2*f2b.y + w3*f3b.y;
    }
    for (; i<end; i++){
        float w0 = wp[i*4];
        int s0 = g_esrc[i];
        float2 fa = __half22float2(fth[s0*256 + lofs]);
        float2 fb = __half22float2(fth[s0*256 + lofs + 1]);
        zsum += w0;
        acc.x = fmaf(w0, fa.x, acc.x);
        acc.y = fmaf(w0, fa.y, acc.y);
        acc.z = fmaf(w0, fb.x, acc.z);
        acc.w = fmaf(w0, fb.y, acc.w);
    }
    float zi = zsum > 0.f ? 1.f/zsum : 1.f;
    int base = n*HD + hh*HDIM + lane*4;
    float4 r  = *(const float4*)&g_res[base];
    float4 bv = *(const float4*)&gat_bias[hh*HDIM + lane*4];
    float o0 = fmaxf(acc.x*zi + r.x + bv.x, 0.f);
    float o1 = fmaxf(acc.y*zi + r.y + bv.y, 0.f);
    float o2 = fmaxf(acc.z*zi + r.z + bv.z, 0.f);
    float o3 = fmaxf(acc.w*zi + r.w + bv.w, 0.f);
    int sbase = n*544 + hh*136 + lane*4;
    __nv_bfloat162 h01, h23, l01, l23;
    bsplit(o0, h01.x, l01.x); bsplit(o1, h01.y, l01.y);
    bsplit(o2, h23.x, l23.x); bsplit(o3, h23.y, l23.y);
    *(__nv_bfloat162*)&g_resh[sbase]   = h01;
    *(__nv_bfloat162*)&g_resh[sbase+2] = h23;
    *(__nv_bfloat162*)&g_resl[sbase]   = l01;
    *(__nv_bfloat162*)&g_resl[sbase+2] = l23;
}

// ---------------- MHA: cp.async A + double-buffered Wm -----------------------
#define MH_AH  0
#define MH_AL  34816
#define MH_W0H 69632
#define MH_W0L 104448
#define MH_W1H 139264
#define MH_W1L 174080

__global__ __launch_bounds__(512,1) void k_mha_mma(const float* __restrict__ bm,
        const float* __restrict__ h0, const float* __restrict__ g1,
        const float* __restrict__ be1){
    extern __shared__ char smem[];
    __shared__ float s_s1[128][2], s_s2[128][2];
    const uint32_t sb = smem_u32(smem);
    const int tid = threadIdx.x, lane = tid&31, w = tid>>5;
    const int strip = w>>1, nh = w&1;
    const int m0 = strip*16, ncol0 = nh*64;
    const int row0 = blockIdx.x*128;

    const int a_r = lane & 15, a_c = (lane & 16) >> 1;
    const int b4_r = (lane & 7) + ((lane & 16) >> 1);
    const int b4_c = lane & 8;
    const int q = lane & 3, gq = lane >> 2;

    float acc[8][4];
    #pragma unroll
    for (int i=0;i<8;i++){ acc[i][0]=0.f; acc[i][1]=0.f; acc[i][2]=0.f; acc[i][3]=0.f; }

    {
        const char* sh = (const char*)g_wmth;
        const char* sl = (const char*)g_wmtl;
        for (int i=tid;i<2176;i+=512){
            cpa16(sb + MH_W0H + i*16, sh + i*16);
            cpa16(sb + MH_W0L + i*16, sl + i*16);
        }
        CPA_COMMIT();
    }

    for (int c=0; c<4; c++){
        const int cur = c & 1;
        __syncthreads();
        {
            for (int i=tid;i<2176;i+=512){
                int m = i/17, o = i - m*17;
                long so = (long)(row0+m)*1088 + c*272 + o*16;
                cpa16(sb + MH_AH + m*272 + o*16, (const char*)g_resh + so);
                cpa16(sb + MH_AL + m*272 + o*16, (const char*)g_resl + so);
            }
            CPA_COMMIT();
        }
        if (c < 3){
            uint32_t dh = cur ? (uint32_t)MH_W0H : (uint32_t)MH_W1H;
            uint32_t dl = cur ? (uint32_t)MH_W0L : (uint32_t)MH_W1L;
            const char* sh = (const char*)(g_wmth + (c+1)*128*136);
            const char* sl = (const char*)(g_wmtl + (c+1)*128*136);
            for (int i=tid;i<2176;i+=512){
                cpa16(sb + dh + i*16, sh + i*16);
                cpa16(sb + dl + i*16, sl + i*16);
            }
            CPA_COMMIT();
            CPA_WAIT1();
        } else {
            CPA_WAIT0();
        }
        __syncthreads();

        const uint32_t wbh = cur ? (uint32_t)MH_W1H : (uint32_t)MH_W0H;
        const uint32_t wbl = cur ? (uint32_t)MH_W1L : (uint32_t)MH_W0L;
        #pragma unroll
        for (int kk=0;kk<8;kk++){
            const int k0 = kk*16;
            uint32_t aaddr = sb + MH_AH + ((m0+a_r)*136 + k0 + a_c)*2;
            unsigned ahf[4], alf[4];
            ldsm4(ahf, aaddr);
            ldsm4(alf, aaddr + (MH_AL-MH_AH));
            #pragma unroll
            for (int ntp=0;ntp<4;ntp++){
                uint32_t boff = ((ncol0+ntp*16+b4_r)*136 + k0 + b4_c)*2;
                unsigned bh[4], bl[4];
                ldsm4(bh, sb + wbh + boff);
                ldsm4(bl, sb + wbl + boff);
                float* a0 = acc[ntp*2], *a1 = acc[ntp*2+1];
                mma_bf16(a0, ahf, bh[0], bh[1]);
                mma_bf16(a0, ahf, bl[0], bl[1]);
                mma_bf16(a0, alf, bh[0], bh[1]);
                mma_bf16(a1, ahf, bh[2], bh[3]);
                mma_bf16(a1, ahf, bl[2], bl[3]);
                mma_bf16(a1, alf, bh[2], bh[3]);
            }
        }
    }

    #pragma unroll
    for (int half=0; half<2; half++){
        int rl = m0 + gq + half*8;
        int row = row0 + rl;
        float tv[16], s1=0.f, s2=0.f;
        #pragma unroll
        for (int nt=0;nt<8;nt++){
            int col = ncol0 + nt*8 + q*2;
            float t0 = fmaxf(acc[nt][half*2+0] + bm[col],   0.f) + h0[row*HID_+col];
            float t1 = fmaxf(acc[nt][half*2+1] + bm[col+1], 0.f) + h0[row*HID_+col+1];
            tv[nt*2]=t0; tv[nt*2+1]=t1;
            s1 += t0+t1; s2 += t0*t0+t1*t1;
        }
        s1 += __shfl_xor_sync(0xffffffffu, s1, 1); s2 += __shfl_xor_sync(0xffffffffu, s2, 1);
        s1 += __shfl_xor_sync(0xffffffffu, s1, 2); s2 += __shfl_xor_sync(0xffffffffu, s2, 2);
        if (q==0){ s_s1[rl][nh]=s1; s_s2[rl][nh]=s2; }
        __syncthreads();
        float fs1 = s_s1[rl][0]+s_s1[rl][1];
        float fs2 = s_s2[rl][0]+s_s2[rl][1];
        float mean = fs1*(1.f/HID_);
        float var  = fs2*(1.f/HID_) - mean*mean;
        float rs   = rsqrtf(var + EPS_);
        #pragma unroll
        for (int nt=0;nt<8;nt++){
            int col = ncol0 + nt*8 + q*2;
            float x0 = (tv[nt*2]  -mean)*rs*g1[col]   + be1[col];
            float x1 = (tv[nt*2+1]-mean)*rs*g1[col+1] + be1[col+1];
            *(float2*)&g_x1[row*HID_+col] = make_float2(x0, x1);
            __nv_bfloat162 hh, ll;
            bsplit(x0, hh.x, ll.x); bsplit(x1, hh.y, ll.y);
            *(__nv_bfloat162*)&g_x1h[row*136+col] = hh;
            *(__nv_bfloat162*)&g_x1l[row*136+col] = ll;
        }
        __syncthreads();
    }
}

// ---------------- FFN: cp.async xs/W1 + W2 double-buffer ----------------------
#define SM_XS_H 0
#define SM_XS_L 34816
#define SM_W1H  69632
#define SM_W1L  87040
#define SM_W2H  104448
#define SM_W2L  122880
#define SM_MIDH 141312
#define SM_MIDL 159744
#define SM_W2H2 178176
#define SM_W2L2 196608
#define SMEM_FFN 215040

__global__ __launch_bounds__(512,1) void k_ffn_mma(const float* __restrict__ b1v,
        const float* __restrict__ b2v, const float* __restrict__ g2,
        const float* __restrict__ be2, float* __restrict__ out){
    extern __shared__ char smem[];
    __shared__ float s_s1[128][2], s_s2[128][2];
    __nv_bfloat16* mid_h= (__nv_bfloat16*)(smem+SM_MIDH);
    __nv_bfloat16* mid_l= (__nv_bfloat16*)(smem+SM_MIDL);
    const uint32_t sb = smem_u32(smem);
    const int tid = threadIdx.x, lane = tid&31, w = tid>>5;
    const int strip = w>>1, nh = w&1;
    const int m0 = strip*16;
    const int row0 = blockIdx.x*128;

    {
        const char* sh = (const char*)g_x1h + row0*272;
        const char* sl = (const char*)g_x1l + row0*272;
        for (int i=tid;i<2176;i+=512){
            cpa16(sb + SM_XS_H + i*16, sh + i*16);
            cpa16(sb + SM_XS_L + i*16, sl + i*16);
        }
        CPA_COMMIT();
    }
    {
        const uint4* s2h = (const uint4*)(g_w2th);
        const uint4* s2l = (const uint4*)(g_w2tl);
        for (int i=tid;i<1152;i+=512){
            cpa16(sb + SM_W2H + i*16, s2h+i);
            cpa16(sb + SM_W2L + i*16, s2l+i);
        }
        CPA_COMMIT();
    }

    float acc2[8][4];
    #pragma unroll
    for (int i=0;i<8;i++){ acc2[i][0]=0.f; acc2[i][1]=0.f; acc2[i][2]=0.f; acc2[i][3]=0.f; }

    const int a_r = lane & 15, a_c = (lane & 16) >> 1;
    const int b4_r = (lane & 7) + ((lane & 16) >> 1);
    const int b4_c = lane & 8;
    const int q = lane & 3, gq = lane >> 2;

    for (int c=0; c<32; c++){
        const int cur = c & 1;
        __syncthreads();
        {
            const uint4* s1h = (const uint4*)(g_w1th + c*64*136);
            const uint4* s1l = (const uint4*)(g_w1tl + c*64*136);
            for (int i=tid;i<1088;i+=512){
                cpa16(sb + SM_W1H + i*16, s1h+i);
                cpa16(sb + SM_W1L + i*16, s1l+i);
            }
            CPA_COMMIT();
        }
        if (c+1 < 32){
            uint32_t dh = cur ? (uint32_t)SM_W2H : (uint32_t)SM_W2H2;
            uint32_t dl = cur ? (uint32_t)SM_W2L : (uint32_t)SM_W2L2;
            const uint4* s2h = (const uint4*)(g_w2th + (c+1)*128*72);
            const uint4* s2l = (const uint4*)(g_w2tl + (c+1)*128*72);
            for (int i=tid;i<1152;i+=512){
                cpa16(sb + dh + i*16, s2h+i);
                cpa16(sb + dl + i*16, s2l+i);
            }
            CPA_COMMIT();
            CPA_WAIT1();
        } else {
            CPA_WAIT0();
        }
        __syncthreads();

        float acc1[4][4];
        #pragma unroll
        for (int i=0;i<4;i++){ acc1[i][0]=0.f; acc1[i][1]=0.f; acc1[i][2]=0.f; acc1[i][3]=0.f; }
        #pragma unroll
        for (int kk=0;kk<8;kk++){
            const int k0 = kk*16;
            uint32_t aaddr = sb + SM_XS_H + ((m0+a_r)*136 + k0 + a_c)*2;
            unsigned ah[4], al[4];
            ldsm4(ah, aaddr);
            ldsm4(al, aaddr + (SM_XS_L - SM_XS_H));
            #pragma unroll
            for (int ntp=0;ntp<2;ntp++){
                uint32_t baddr = sb + SM_W1H + ((nh*32+ntp*16+b4_r)*136 + k0 + b4_c)*2;
                unsigned bh[4], bl[4];
                ldsm4(bh, baddr);
                ldsm4(bl, baddr + (SM_W1L - SM_W1H));
                float* a0 = acc1[ntp*2], *a1 = acc1[ntp*2+1];
                mma_bf16(a0, ah, bh[0], bh[1]);
                mma_bf16(a0, ah, bl[0], bl[1]);
                mma_bf16(a0, al, bh[0], bh[1]);
                mma_bf16(a1, ah, bh[2], bh[3]);
                mma_bf16(a1, ah, bl[2], bl[3]);
                mma_bf16(a1, al, bh[2], bh[3]);
            }
        }
        {
            const int r1 = m0 + gq, r2 = r1 + 8;
            #pragma unroll
            for (int nt=0;nt<2;nt++){
                int col = nh*32 + nt*8 + q*2;
                float bb0 = b1v[c*64+col], bb1 = b1v[c*64+col+1];
                float v0 = fmaxf(acc1[nt][0]+bb0, 0.f);
                float v1 = fmaxf(acc1[nt][1]+bb1, 0.f);
                float v2 = fmaxf(acc1[nt][2]+bb0, 0.f);
                float v3 = fmaxf(acc1[nt][3]+bb1, 0.f);
                __nv_bfloat162 hh, ll;
                bsplit(v0, hh.x, ll.x); bsplit(v1, hh.y, ll.y);
                *(__nv_bfloat162*)&mid_h[r1*72+col]=hh;
                *(__nv_bfloat162*)&mid_l[r1*72+col]=ll;
                bsplit(v2, hh.x, ll.x); bsplit(v3, hh.y, ll.y);
                *(__nv_bfloat162*)&mid_h[r2*72+col]=hh;
                *(__nv_bfloat162*)&mid_l[r2*72+col]=ll;
            }
            #pragma unroll
            for (int nt=2;nt<4;nt++){
                int col = nh*32 + (nt-2)*8 + 16 + q*2;
                float bb0 = b1v[c*64+col], bb1 = b1v[c*64+col+1];
                float v0 = fmaxf(acc1[nt][0]+bb0, 0.f);
                float v1 = fmaxf(acc1[nt][1]+bb1, 0.f);
                float v2 = fmaxf(acc1[nt][2]+bb0, 0.f);
                float v3 = fmaxf(acc1[nt][3]+bb1, 0.f);
                __nv_bfloat162 hh, ll;
                bsplit(v0, hh.x, ll.x); bsplit(v1, hh.y, ll.y);
                *(__nv_bfloat162*)&mid_h[r1*72+col]=hh;
                *(__nv_bfloat162*)&mid_l[r1*72+col]=ll;
                bsplit(v2, hh.x, ll.x); bsplit(v3, hh.y, ll.y);
                *(__nv_bfloat162*)&mid_h[r2*72+col]=hh;
                *(__nv_bfloat162*)&mid_l[r2*72+col]=ll;
            }
        }
        __syncthreads();

        const uint32_t w2h_base = cur ? (uint32_t)SM_W2H2 : (uint32_t)SM_W2H;
        #pragma unroll
        for (int kk=0;kk<4;kk++){
            const int k0 = kk*16;
            uint32_t aaddr = sb + SM_MIDH + ((m0+a_r)*72 + k0 + a_c)*2;
            unsigned ah[4], al[4];
            ldsm4(ah, aaddr);
            ldsm4(al, aaddr + (SM_MIDL - SM_MIDH));
            #pragma unroll
            for (int ntp=0;ntp<4;ntp++){
                uint32_t baddr = sb + w2h_base + ((nh*64+ntp*16+b4_r)*72 + k0 + b4_c)*2;
                unsigned bh[4], bl[4];
                ldsm4(bh, baddr);
                ldsm4(bl, baddr + 18432);
                float* a0 = acc2[ntp*2], *a1 = acc2[ntp*2+1];
                mma_bf16(a0, ah, bh[0], bh[1]);
                mma_bf16(a0, ah, bl[0], bl[1]);
                mma_bf16(a0, al, bh[0], bh[1]);
                mma_bf16(a1, ah, bh[2], bh[3]);
                mma_bf16(a1, ah, bl[2], bl[3]);
                mma_bf16(a1, al, bh[2], bh[3]);
            }
        }
    }

    #pragma unroll
    for (int half=0; half<2; half++){
        int rl = m0 + gq + half*8;
        int grow = row0 + rl;
        float tv[16], s1=0.f, s2=0.f;
        #pragma unroll
        for (int nt=0;nt<8;nt++){
            int col = nh*64 + nt*8 + q*2;
            float t0 = acc2[nt][half*2+0] + b2v[col]   + g_x1[grow*HID_+col];
            float t1 = acc2[nt][half*2+1] + b2v[col+1] + g_x1[grow*HID_+col+1];
            tv[nt*2]=t0; tv[nt*2+1]=t1;
            s1 += t0+t1; s2 += t0*t0+t1*t1;
        }
        s1 += __shfl_xor_sync(0xffffffffu, s1, 1); s2 += __shfl_xor_sync(0xffffffffu, s2, 1);
        s1 += __shfl_xor_sync(0xffffffffu, s1, 2); s2 += __shfl_xor_sync(0xffffffffu, s2, 2);
        if (q==0){ s_s1[rl][nh]=s1; s_s2[rl][nh]=s2; }
        __syncthreads();
        float fs1 = s_s1[rl][0]+s_s1[rl][1];
        float fs2 = s_s2[rl][0]+s_s2[rl][1];
        float mean = fs1*(1.f/HID_);
        float var  = fs2*(1.f/HID_) - mean*mean;
        float rs   = rsqrtf(var + EPS_);
        #pragma unroll
        for (int nt=0;nt<8;nt++){
            int col = nh*64 + nt*8 + q*2;
            out[grow*HID_+col]   = (tv[nt*2]  -mean)*rs*g2[col]   + be2[col];
            out[grow*HID_+col+1] = (tv[nt*2+1]-mean)*rs*g2[col+1] + be2[col+1];
        }
        __syncthreads();
    }
}

// ---------------- launch ----------------------------------------------------
extern "C" void kernel_launch(void* const* d_in, const int* in_sizes, int n_in,
                              void* d_out, int out_size){
    int o = (in_sizes[4] == 1) ? 1 : 0;
    const float* h       = (const float*)d_in[0];
    const float* e       = (const float*)d_in[1];
    const int*   src     = (const int*)  d_in[2];
    const int*   dst     = (const int*)  d_in[3];
    const float* W_fc    = (const float*)d_in[4+o];
    const float* attn_l  = (const float*)d_in[5+o];
    const float* attn_r  = (const float*)d_in[6+o];
    const float* W_fe    = (const float*)d_in[7+o];
    const float* attn_e  = (const float*)d_in[8+o];
    const float* W_res   = (const float*)d_in[9+o];
    const float* gatb    = (const float*)d_in[10+o];
    const float* W_mha   = (const float*)d_in[11+o];
    const float* b_mha   = (const float*)d_in[12+o];
    const float* n1_g    = (const float*)d_in[13+o];
    const float* n1_b    = (const float*)d_in[14+o];
    const float* n2_g    = (const float*)d_in[15+o];
    const float* n2_b    = (const float*)d_in[16+o];
    const float* W1      = (const float*)d_in[17+o];
    const float* b1      = (const float*)d_in[18+o];
    const float* W2      = (const float*)d_in[19+o];
    const float* b2      = (const float*)d_in[20+o];
    float* out = (float*)d_out;

    cudaFuncSetAttribute(k_ffn_mma,  cudaFuncAttributeMaxDynamicSharedMemorySize, SMEM_FFN);
    cudaFuncSetAttribute(k_gemmA_mma,cudaFuncAttributeMaxDynamicSharedMemorySize, SMEM_GZ);
    cudaFuncSetAttribute(k_mha_mma,  cudaFuncAttributeMaxDynamicSharedMemorySize, SMEM_MH);

    k_init<<<128,256>>>();
    k_prep<<<1024,256>>>(W1, W2, W_fc, W_res, W_mha, h, dst);
    k_scan1<<<128,256>>>();
    k_scan2<<<1,128>>>();
    k_scan3<<<128,256>>>();
    dim3 gA(64, 4, 2);
    k_gemmA_mma<<<gA,512,SMEM_GZ>>>(attn_l, attn_r);
    k_edgefill<<<N_EDGES/256,256>>>(e, src, dst, W_fe, attn_e);
    k_agg<<<N_NODES*NH/8,256>>>(gatb);
    k_mha_mma<<<N_NODES/128,512,SMEM_MH>>>(b_mha, h, n1_g, n1_b);
    k_ffn_mma<<<N_NODES/128,512,SMEM_FFN>>>(b1, b2, n2_g, n2_b, out);
}

// round 16
// speedup vs baseline: 1.6213x; 1.1481x over previous
#include <cuda_runtime.h>
#include <cuda_bf16.h>
#include <cuda_fp16.h>
#include <cstdint>

#define N_NODES 32768
#define N_EDGES 524288
#define NH      4
#define HDIM    128
#define HD      512
#define HID_    128
#define DFF_    2048
#define SLOPE_  0.2f
#define EPS_    1e-5f

// ---------------- scratch ----------------------------------------------------
__device__ __align__(16) __half g_fth[N_NODES*HD];   // ft in fp16 (k_agg only)
__device__ float    g_res[N_NODES*HD];
__device__ float    g_el [N_NODES*NH];
__device__ float    g_er [N_NODES*NH];
__device__ int      g_deg[N_NODES];
__device__ int      g_cursor[N_NODES];
__device__ int      g_rowptr[N_NODES+1];
__device__ int      g_bsum[128];
__device__ int      g_esrc[N_EDGES];
__device__ __align__(16) float g_wsH[N_EDGES*4];
__device__ float    g_x1 [N_NODES*HID_];

// pre-split activations
__device__ __align__(16) __nv_bfloat16 g_hh  [N_NODES*136];
__device__ __align__(16) __nv_bfloat16 g_hl  [N_NODES*136];
__device__ __align__(16) __nv_bfloat16 g_resh[N_NODES*544];
__device__ __align__(16) __nv_bfloat16 g_resl[N_NODES*544];
__device__ __align__(16) __half        g_x1f [N_NODES*136];   // x1 single fp16 (FFN)

// weights: FFN in fp16 hi/lo; gemmA/mha in bf16 hi/lo
__device__ __align__(16) __half g_w1th[32*64*136];
__device__ __align__(16) __half g_w1tl[32*64*136];
__device__ __align__(16) __half g_w2th[32*128*72];
__device__ __align__(16) __half g_w2tl[32*128*72];
__device__ __align__(16) __nv_bfloat16 g_wfth[512*136];
__device__ __align__(16) __nv_bfloat16 g_wftl[512*136];
__device__ __align__(16) __nv_bfloat16 g_wrth[512*136];
__device__ __align__(16) __nv_bfloat16 g_wrtl[512*136];
__device__ __align__(16) __nv_bfloat16 g_wmth[512*136];
__device__ __align__(16) __nv_bfloat16 g_wmtl[512*136];

// ---------------- helpers ------------------------------------------------------
__device__ __forceinline__ uint32_t smem_u32(const void* p){
    uint32_t a;
    asm("{ .reg .u64 t; cvta.to.shared.u64 t, %1; cvt.u32.u64 %0, t; }" : "=r"(a) : "l"(p));
    return a;
}
__device__ __forceinline__ void ldsm4(unsigned* r, uint32_t addr){
    asm volatile("ldmatrix.sync.aligned.m8n8.x4.shared.b16 {%0,%1,%2,%3}, [%4];"
        : "=r"(r[0]),"=r"(r[1]),"=r"(r[2]),"=r"(r[3]) : "r"(addr));
}
__device__ __forceinline__ void mma_bf16(float* c, const unsigned* a, unsigned b0, unsigned b1){
    asm volatile("mma.sync.aligned.m16n8k16.row.col.f32.bf16.bf16.f32 "
        "{%0,%1,%2,%3},{%4,%5,%6,%7},{%8,%9},{%0,%1,%2,%3};"
        : "+f"(c[0]),"+f"(c[1]),"+f"(c[2]),"+f"(c[3])
        : "r"(a[0]),"r"(a[1]),"r"(a[2]),"r"(a[3]),"r"(b0),"r"(b1));
}
__device__ __forceinline__ void mma_f16(float* c, const unsigned* a, unsigned b0, unsigned b1){
    asm volatile("mma.sync.aligned.m16n8k16.row.col.f32.f16.f16.f32 "
        "{%0,%1,%2,%3},{%4,%5,%6,%7},{%8,%9},{%0,%1,%2,%3};"
        : "+f"(c[0]),"+f"(c[1]),"+f"(c[2]),"+f"(c[3])
        : "r"(a[0]),"r"(a[1]),"r"(a[2]),"r"(a[3]),"r"(b0),"r"(b1));
}
__device__ __forceinline__ void bsplit(float v, __nv_bfloat16& hi, __nv_bfloat16& lo){
    hi = __float2bfloat16(v);
    lo = __float2bfloat16(v - __bfloat162float(hi));
}
__device__ __forceinline__ void hsplit(float v, __half& hi, __half& lo){
    hi = __float2half_rn(v);
    lo = __float2half_rn(v - __half2float(hi));
}
__device__ __forceinline__ void cpa16(uint32_t saddr, const void* g){
    asm volatile("cp.async.cg.shared.global [%0], [%1], 16;" :: "r"(saddr), "l"(g));
}
#define CPA_COMMIT() asm volatile("cp.async.commit_group;" ::: "memory")
#define CPA_WAIT1()  asm volatile("cp.async.wait_group 1;" ::: "memory")
#define CPA_WAIT0()  asm volatile("cp.async.wait_group 0;" ::: "memory")

// ---------------- init ------------------------------------------------------
__global__ void k_init(){
    int i = blockIdx.x*256 + threadIdx.x;
    if (i < N_NODES){ g_deg[i] = 0; g_cursor[i] = 0; }
}

// ---------------- prep (+ degree count) ---------------------------------------
__global__ void k_prep(const float* __restrict__ W1, const float* __restrict__ W2,
                       const float* __restrict__ Wfc, const float* __restrict__ Wres,
                       const float* __restrict__ Wm, const float* __restrict__ h,
                       const int* __restrict__ dst){
    int i = blockIdx.x*256 + threadIdx.x;   // 262144 threads
    atomicAdd(&g_deg[dst[i]], 1);
    atomicAdd(&g_deg[dst[i + 262144]], 1);
    {   // W1 [k=128][n=2048] -> fp16 hi/lo
        int k = i >> 11, n = i & 2047;
        __half hv, lv; hsplit(W1[i], hv, lv);
        int c = n >> 6, nn = n & 63;
        g_w1th[(c*64+nn)*136 + k] = hv;
        g_w1tl[(c*64+nn)*136 + k] = lv;
    }
    {   // W2 [k2=2048][n=128] -> fp16 hi/lo
        int k2 = i >> 7, n = i & 127;
        __half hv, lv; hsplit(W2[i], hv, lv);
        int c = k2 >> 6, kk = k2 & 63;
        g_w2th[(c*128+n)*72 + kk] = hv;
        g_w2tl[(c*128+n)*72 + kk] = lv;
    }
    #pragma unroll
    for (int j=0;j<16;j++){
        int idx = i + j*262144;
        int n = idx >> 7, k = idx & 127;
        __nv_bfloat16 hv, lv; bsplit(h[idx], hv, lv);
        g_hh[n*136+k] = hv;
        g_hl[n*136+k] = lv;
    }
    if (i < 65536){
        {   // Wfc/Wres [k=128][n=512]
            int k = i >> 9, n = i & 511;
            __nv_bfloat16 hv, lv;
            bsplit(Wfc[i], hv, lv);
            g_wfth[n*136 + k] = hv; g_wftl[n*136 + k] = lv;
            bsplit(Wres[i], hv, lv);
            g_wrth[n*136 + k] = hv; g_wrtl[n*136 + k] = lv;
        }
        {   // Wm [k2=512][n=128]
            int k2 = i >> 7, n = i & 127;
            __nv_bfloat16 hv, lv; bsplit(Wm[i], hv, lv);
            int c = k2 >> 7, kk = k2 & 127;
            g_wmth[(c*128+n)*136 + kk] = hv;
            g_wmtl[(c*128+n)*136 + kk] = lv;
        }
    }
}

// ---------------- hierarchical CSR scan ---------------------------------------
__global__ __launch_bounds__(256) void k_scan1(){
    int b = blockIdx.x, t = threadIdx.x;
    int node = b*256 + t;
    int d = g_deg[node];
    int v = d;
    #pragma unroll
    for (int off=1; off<32; off<<=1){
        int nv = __shfl_up_sync(0xffffffffu, v, off);
        if ((t&31) >= off) v += nv;
    }
    __shared__ int wsum[8];
    if ((t&31)==31) wsum[t>>5] = v;
    __syncthreads();
    if (t < 8){
        int wv = wsum[t];
        #pragma unroll
        for (int off=1; off<8; off<<=1){
            int nv = __shfl_up_sync(0xffu, wv, off);
            if (t >= off) wv += nv;
        }
        wsum[t] = wv;
    }
    __syncthreads();
    int incl = v + ((t>=32) ? wsum[(t>>5)-1] : 0);
    g_rowptr[node] = incl - d;
    if (t==255) g_bsum[b] = incl;
}

__global__ __launch_bounds__(128) void k_scan2(){
    int t = threadIdx.x;
    int v = g_bsum[t];
    int x = v;
    #pragma unroll
    for (int off=1; off<32; off<<=1){
        int nv = __shfl_up_sync(0xffffffffu, x, off);
        if ((t&31) >= off) x += nv;
    }
    __shared__ int ws[4];
    if ((t&31)==31) ws[t>>5] = x;
    __syncthreads();
    if (t < 4){
        int wv = ws[t];
        #pragma unroll
        for (int off=1; off<4; off<<=1){
            int nv = __shfl_up_sync(0xfu, wv, off);
            if (t >= off) wv += nv;
        }
        ws[t] = wv;
    }
    __syncthreads();
    int incl = x + ((t>=32) ? ws[(t>>5)-1] : 0);
    g_bsum[t] = incl - v;
    if (t==127) g_rowptr[N_NODES] = incl;
}

__global__ __launch_bounds__(256) void k_scan3(){
    int node = blockIdx.x*256 + threadIdx.x;
    g_rowptr[node] += g_bsum[blockIdx.x];
}

// ---------------- GEMM A: z-split, A double-buffered via cp.async ------------
#define GZ_A0H 0
#define GZ_A0L 34816
#define GZ_A1H 69632
#define GZ_A1L 104448
#define GZ_BH  139264
#define GZ_BL  174080
#define SMEM_GZ 208896
#define SMEM_MH 208896

__global__ __launch_bounds__(512,1) void k_gemmA_mma(
        const float* __restrict__ attn_l, const float* __restrict__ attn_r){
    extern __shared__ char smem[];
    __shared__ float s_al[128], s_ar[128];
    __shared__ float s_pl[128][2], s_pr[128][2];
    const uint32_t sb = smem_u32(smem);
    const int tid = threadIdx.x, lane = tid&31, w = tid>>5;
    const int strip = w>>1, nh = w&1;
    const int m0 = strip*16, ncol0 = nh*64;
    const int col0 = blockIdx.y*128;
    const int z = blockIdx.z;
    const __nv_bfloat16* Bh = z ? g_wrth : g_wfth;
    const __nv_bfloat16* Bl = z ? g_wrtl : g_wftl;

    if (z==0 && tid<128){
        s_al[tid] = attn_l[col0+tid];
        s_ar[tid] = attn_r[col0+tid];
    }
    {   // G0: B tile + A(0)
        const char* bh = (const char*)(Bh + col0*136);
        const char* bl = (const char*)(Bl + col0*136);
        const char* a0h = (const char*)g_hh + (blockIdx.x*4+0)*128*272;
        const char* a0l = (const char*)g_hl + (blockIdx.x*4+0)*128*272;
        for (int i=tid;i<2176;i+=512){
            cpa16(sb + GZ_BH  + i*16, bh  + i*16);
            cpa16(sb + GZ_BL  + i*16, bl  + i*16);
            cpa16(sb + GZ_A0H + i*16, a0h + i*16);
            cpa16(sb + GZ_A0L + i*16, a0l + i*16);
        }
        CPA_COMMIT();
    }

    const int a_r = lane & 15, a_c = (lane & 16) >> 1;
    const int b4_r = (lane & 7) + ((lane & 16) >> 1);
    const int b4_c = lane & 8;
    const int q = lane & 3, gq = lane >> 2;

    for (int rt=0; rt<4; rt++){
        const int row0 = (blockIdx.x*4+rt)*128;
        __syncthreads();
        if (rt<3){
            uint32_t dh = ((rt+1)&1) ? (uint32_t)GZ_A1H : (uint32_t)GZ_A0H;
            uint32_t dl = ((rt+1)&1) ? (uint32_t)GZ_A1L : (uint32_t)GZ_A0L;
            const char* ah = (const char*)g_hh + (blockIdx.x*4+rt+1)*128*272;
            const char* al_= (const char*)g_hl + (blockIdx.x*4+rt+1)*128*272;
            for (int i=tid;i<2176;i+=512){
                cpa16(sb + dh + i*16, ah + i*16);
                cpa16(sb + dl + i*16, al_+ i*16);
            }
            CPA_COMMIT();
            CPA_WAIT1();
        } else {
            CPA_WAIT0();
        }
        __syncthreads();
        const uint32_t A_H = (rt&1) ? (uint32_t)GZ_A1H : (uint32_t)GZ_A0H;
        const uint32_t A_L = (rt&1) ? (uint32_t)GZ_A1L : (uint32_t)GZ_A0L;

        float acc[8][4];
        #pragma unroll
        for (int i=0;i<8;i++){ acc[i][0]=0.f; acc[i][1]=0.f; acc[i][2]=0.f; acc[i][3]=0.f; }
        #pragma unroll
        for (int kk=0;kk<8;kk++){
            const int k0 = kk*16;
            uint32_t aaddr = sb + A_H + ((m0+a_r)*136 + k0 + a_c)*2;
            unsigned ahf[4], alf[4];
            ldsm4(ahf, aaddr);
            ldsm4(alf, aaddr + (A_L-A_H));
            #pragma unroll
            for (int ntp=0;ntp<4;ntp++){
                uint32_t baddr = sb + GZ_BH + ((ncol0+ntp*16+b4_r)*136 + k0 + b4_c)*2;
                unsigned bh[4], bl[4];
                ldsm4(bh, baddr);
                ldsm4(bl, baddr + (GZ_BL-GZ_BH));
                float* a0 = acc[ntp*2], *a1 = acc[ntp*2+1];
                mma_bf16(a0, ahf, bh[0], bh[1]);
                mma_bf16(a0, ahf, bl[0], bl[1]);
                mma_bf16(a0, alf, bh[0], bh[1]);
                mma_bf16(a1, ahf, bh[2], bh[3]);
                mma_bf16(a1, ahf, bl[2], bl[3]);
                mma_bf16(a1, alf, bh[2], bh[3]);
            }
        }
        if (z==0){
            #pragma unroll
            for (int half=0; half<2; half++){
                int row = row0 + m0 + gq + half*8;
                #pragma unroll
                for (int nt=0;nt<8;nt++){
                    int col = col0 + ncol0 + nt*8 + q*2;
                    *(__half2*)&g_fth[row*HD+col] =
                        __floats2half2_rn(acc[nt][half*2], acc[nt][half*2+1]);
                }
            }
            #pragma unroll
            for (int half=0; half<2; half++){
                int rl = m0 + gq + half*8;
                float pl=0.f, pr=0.f;
                #pragma unroll
                for (int nt=0;nt<8;nt++){
                    int col = ncol0 + nt*8 + q*2;
                    float v0 = acc[nt][half*2], v1 = acc[nt][half*2+1];
                    pl += v0*s_al[col] + v1*s_al[col+1];
                    pr += v0*s_ar[col] + v1*s_ar[col+1];
                }
                pl += __shfl_xor_sync(0xffffffffu, pl, 1);
                pl += __shfl_xor_sync(0xffffffffu, pl, 2);
                pr += __shfl_xor_sync(0xffffffffu, pr, 1);
                pr += __shfl_xor_sync(0xffffffffu, pr, 2);
                if (q==0){ s_pl[rl][nh]=pl; s_pr[rl][nh]=pr; }
            }
            __syncthreads();
            if (tid<128){
                int row = row0 + tid;
                g_el[row*NH + blockIdx.y] = s_pl[tid][0]+s_pl[tid][1];
                g_er[row*NH + blockIdx.y] = s_pr[tid][0]+s_pr[tid][1];
            }
        } else {
            #pragma unroll
            for (int half=0; half<2; half++){
                int row = row0 + m0 + gq + half*8;
                #pragma unroll
                for (int nt=0;nt<8;nt++){
                    int col = col0 + ncol0 + nt*8 + q*2;
                    *(float2*)&g_res[row*HD+col] =
                        make_float2(acc[nt][half*2], acc[nt][half*2+1]);
                }
            }
        }
    }
}

// ---------------- edge pass + CSR fill (1 atomic/edge) ------------------------
__global__ __launch_bounds__(256) void k_edgefill(const float* __restrict__ e,
        const int* __restrict__ src, const int* __restrict__ dst,
        const float* __restrict__ W_fe, const float* __restrict__ attn_e){
    __shared__ float ce[NH];
    int wid = threadIdx.x>>5, lane = threadIdx.x&31;
    if (wid < NH){
        float p = 0.f;
        #pragma unroll
        for (int q=0;q<4;q++){
            int d = lane + q*32;
            p += W_fe[wid*HDIM+d]*attn_e[wid*HDIM+d];
        }
        #pragma unroll
        for (int off=16; off; off>>=1) p += __shfl_xor_sync(0xffffffffu, p, off);
        if (lane==0) ce[wid]=p;
    }
    __syncthreads();
    int ei = blockIdx.x*256 + threadIdx.x;
    if (ei >= N_EDGES) return;
    int s = src[ei], d = dst[ei];
    float ev = e[ei];
    float4 els = ((const float4*)g_el)[s];
    float4 erd = ((const float4*)g_er)[d];
    float sc[4];
    sc[0] = els.x + erd.x + ev*ce[0];
    sc[1] = els.y + erd.y + ev*ce[1];
    sc[2] = els.z + erd.z + ev*ce[2];
    sc[3] = els.w + erd.w + ev*ce[3];
    float wv[4];
    #pragma unroll
    for (int hh=0;hh<4;hh++){
        float v = sc[hh];
        v = v > 0.f ? v : SLOPE_*v;
        wv[hh] = expf(v);
    }
    int pos = g_rowptr[d] + atomicAdd(&g_cursor[d], 1);
    g_esrc[pos] = s;
    *(float4*)&g_wsH[pos*4] = make_float4(wv[0],wv[1],wv[2],wv[3]);
}

// ---------------- aggregation: fp16 gathers, local zsum ------------------------
__global__ __launch_bounds__(256) void k_agg(const float* __restrict__ gat_bias){
    int wid = threadIdx.x>>5, lane = threadIdx.x&31;
    int gw = blockIdx.x*8 + wid;
    int n = gw>>2, hh = gw&3;
    int beg = g_rowptr[n], end = g_rowptr[n+1];
    float4 acc = make_float4(0,0,0,0);
    float zsum = 0.f;
    const __half2* fth = (const __half2*)g_fth;
    const float* wp = g_wsH + hh;
    const int lofs = hh*64 + lane*2;
    int i = beg;
    for (; i+4<=end; i+=4){
        float w0 = wp[i*4],   w1 = wp[(i+1)*4], w2 = wp[(i+2)*4], w3 = wp[(i+3)*4];
        int   s0 = g_esrc[i], s1 = g_esrc[i+1], s2 = g_esrc[i+2], s3 = g_esrc[i+3];
        __half2 p0a = fth[s0*256 + lofs], p0b = fth[s0*256 + lofs + 1];
        __half2 p1a = fth[s1*256 + lofs], p1b = fth[s1*256 + lofs + 1];
        __half2 p2a = fth[s2*256 + lofs], p2b = fth[s2*256 + lofs + 1];
        __half2 p3a = fth[s3*256 + lofs], p3b = fth[s3*256 + lofs + 1];
        float2 f0a = __half22float2(p0a), f0b = __half22float2(p0b);
        float2 f1a = __half22float2(p1a), f1b = __half22float2(p1b);
        float2 f2a = __half22float2(p2a), f2b = __half22float2(p2b);
        float2 f3a = __half22float2(p3a), f3b = __half22float2(p3b);
        zsum += w0+w1+w2+w3;
        acc.x += w0*f0a.x + w1*f1a.x + w2*f2a.x + w3*f3a.x;
        acc.y += w0*f0a.y + w1*f1a.y + w2*f2a.y + w3*f3a.y;
        acc.z += w0*f0b.x + w1*f1b.x + w2*f2b.x + w3*f3b.x;
        acc.w += w0*f0b.y + w1*f1b.y + w2*f2b.y + w3*f3b.y;
    }
    for (; i<end; i++){
        float w0 = wp[i*4];
        int s0 = g_esrc[i];
        float2 fa = __half22float2(fth[s0*256 + lofs]);
        float2 fb = __half22float2(fth[s0*256 + lofs + 1]);
        zsum += w0;
        acc.x = fmaf(w0, fa.x, acc.x);
        acc.y = fmaf(w0, fa.y, acc.y);
        acc.z = fmaf(w0, fb.x, acc.z);
        acc.w = fmaf(w0, fb.y, acc.w);
    }
    float zi = zsum > 0.f ? 1.f/zsum : 1.f;
    int base = n*HD + hh*HDIM + lane*4;
    float4 r  = *(const float4*)&g_res[base];
    float4 bv = *(const float4*)&gat_bias[hh*HDIM + lane*4];
    float o0 = fmaxf(acc.x*zi + r.x + bv.x, 0.f);
    float o1 = fmaxf(acc.y*zi + r.y + bv.y, 0.f);
    float o2 = fmaxf(acc.z*zi + r.z + bv.z, 0.f);
    float o3 = fmaxf(acc.w*zi + r.w + bv.w, 0.f);
    int sbase = n*544 + hh*136 + lane*4;
    __nv_bfloat162 h01, h23, l01, l23;
    bsplit(o0, h01.x, l01.x); bsplit(o1, h01.y, l01.y);
    bsplit(o2, h23.x, l23.x); bsplit(o3, h23.y, l23.y);
    *(__nv_bfloat162*)&g_resh[sbase]   = h01;
    *(__nv_bfloat162*)&g_resh[sbase+2] = h23;
    *(__nv_bfloat162*)&g_resl[sbase]   = l01;
    *(__nv_bfloat162*)&g_resl[sbase+2] = l23;
}

// ---------------- MHA: cp.async A + double-buffered Wm -----------------------
#define MH_AH  0
#define MH_AL  34816
#define MH_W0H 69632
#define MH_W0L 104448
#define MH_W1H 139264
#define MH_W1L 174080

__global__ __launch_bounds__(512,1) void k_mha_mma(const float* __restrict__ bm,
        const float* __restrict__ h0, const float* __restrict__ g1,
        const float* __restrict__ be1){
    extern __shared__ char smem[];
    __shared__ float s_s1[128][2], s_s2[128][2];
    const uint32_t sb = smem_u32(smem);
    const int tid = threadIdx.x, lane = tid&31, w = tid>>5;
    const int strip = w>>1, nh = w&1;
    const int m0 = strip*16, ncol0 = nh*64;
    const int row0 = blockIdx.x*128;

    const int a_r = lane & 15, a_c = (lane & 16) >> 1;
    const int b4_r = (lane & 7) + ((lane & 16) >> 1);
    const int b4_c = lane & 8;
    const int q = lane & 3, gq = lane >> 2;

    float acc[8][4];
    #pragma unroll
    for (int i=0;i<8;i++){ acc[i][0]=0.f; acc[i][1]=0.f; acc[i][2]=0.f; acc[i][3]=0.f; }

    {
        const char* sh = (const char*)g_wmth;
        const char* sl = (const char*)g_wmtl;
        for (int i=tid;i<2176;i+=512){
            cpa16(sb + MH_W0H + i*16, sh + i*16);
            cpa16(sb + MH_W0L + i*16, sl + i*16);
        }
        CPA_COMMIT();
    }

    for (int c=0; c<4; c++){
        const int cur = c & 1;
        __syncthreads();
        {
            for (int i=tid;i<2176;i+=512){
                int m = i/17, o = i - m*17;
                long so = (long)(row0+m)*1088 + c*272 + o*16;
                cpa16(sb + MH_AH + m*272 + o*16, (const char*)g_resh + so);
                cpa16(sb + MH_AL + m*272 + o*16, (const char*)g_resl + so);
            }
            CPA_COMMIT();
        }
        if (c < 3){
            uint32_t dh = cur ? (uint32_t)MH_W0H : (uint32_t)MH_W1H;
            uint32_t dl = cur ? (uint32_t)MH_W0L : (uint32_t)MH_W1L;
            const char* sh = (const char*)(g_wmth + (c+1)*128*136);
            const char* sl = (const char*)(g_wmtl + (c+1)*128*136);
            for (int i=tid;i<2176;i+=512){
                cpa16(sb + dh + i*16, sh + i*16);
                cpa16(sb + dl + i*16, sl + i*16);
            }
            CPA_COMMIT();
            CPA_WAIT1();
        } else {
            CPA_WAIT0();
        }
        __syncthreads();

        const uint32_t wbh = cur ? (uint32_t)MH_W1H : (uint32_t)MH_W0H;
        const uint32_t wbl = cur ? (uint32_t)MH_W1L : (uint32_t)MH_W0L;
        #pragma unroll
        for (int kk=0;kk<8;kk++){
            const int k0 = kk*16;
            uint32_t aaddr = sb + MH_AH + ((m0+a_r)*136 + k0 + a_c)*2;
            unsigned ahf[4], alf[4];
            ldsm4(ahf, aaddr);
            ldsm4(alf, aaddr + (MH_AL-MH_AH));
            #pragma unroll
            for (int ntp=0;ntp<4;ntp++){
                uint32_t boff = ((ncol0+ntp*16+b4_r)*136 + k0 + b4_c)*2;
                unsigned bh[4], bl[4];
                ldsm4(bh, sb + wbh + boff);
                ldsm4(bl, sb + wbl + boff);
                float* a0 = acc[ntp*2], *a1 = acc[ntp*2+1];
                mma_bf16(a0, ahf, bh[0], bh[1]);
                mma_bf16(a0, ahf, bl[0], bl[1]);
                mma_bf16(a0, alf, bh[0], bh[1]);
                mma_bf16(a1, ahf, bh[2], bh[3]);
                mma_bf16(a1, ahf, bl[2], bl[3]);
                mma_bf16(a1, alf, bh[2], bh[3]);
            }
        }
    }

    #pragma unroll
    for (int half=0; half<2; half++){
        int rl = m0 + gq + half*8;
        int row = row0 + rl;
        float tv[16], s1=0.f, s2=0.f;
        #pragma unroll
        for (int nt=0;nt<8;nt++){
            int col = ncol0 + nt*8 + q*2;
            float t0 = fmaxf(acc[nt][half*2+0] + bm[col],   0.f) + h0[row*HID_+col];
            float t1 = fmaxf(acc[nt][half*2+1] + bm[col+1], 0.f) + h0[row*HID_+col+1];
            tv[nt*2]=t0; tv[nt*2+1]=t1;
            s1 += t0+t1; s2 += t0*t0+t1*t1;
        }
        s1 += __shfl_xor_sync(0xffffffffu, s1, 1); s2 += __shfl_xor_sync(0xffffffffu, s2, 1);
        s1 += __shfl_xor_sync(0xffffffffu, s1, 2); s2 += __shfl_xor_sync(0xffffffffu, s2, 2);
        if (q==0){ s_s1[rl][nh]=s1; s_s2[rl][nh]=s2; }
        __syncthreads();
        float fs1 = s_s1[rl][0]+s_s1[rl][1];
        float fs2 = s_s2[rl][0]+s_s2[rl][1];
        float mean = fs1*(1.f/HID_);
        float var  = fs2*(1.f/HID_) - mean*mean;
        float rs   = rsqrtf(var + EPS_);
        #pragma unroll
        for (int nt=0;nt<8;nt++){
            int col = ncol0 + nt*8 + q*2;
            float x0 = (tv[nt*2]  -mean)*rs*g1[col]   + be1[col];
            float x1 = (tv[nt*2+1]-mean)*rs*g1[col+1] + be1[col+1];
            *(float2*)&g_x1[row*HID_+col] = make_float2(x0, x1);
            *(__half2*)&g_x1f[row*136+col] = __floats2half2_rn(x0, x1);
        }
        __syncthreads();
    }
}

// ---------------- FFN: fp16 2-term, single-buffer activations ----------------
#define F_XS   0
#define F_W1H  34816
#define F_W1L  52224
#define F_W2H  69632
#define F_W2L  88064
#define F_MID  106496
#define F_W2H2 124928
#define F_W2L2 143360
#define SMEM_FFN 161792

__global__ __launch_bounds__(512,1) void k_ffn_mma(const float* __restrict__ b1v,
        const float* __restrict__ b2v, const float* __restrict__ g2,
        const float* __restrict__ be2, float* __restrict__ out){
    extern __shared__ char smem[];
    __shared__ float s_s1[128][2], s_s2[128][2];
    __half* mid = (__half*)(smem+F_MID);
    const uint32_t sb = smem_u32(smem);
    const int tid = threadIdx.x, lane = tid&31, w = tid>>5;
    const int strip = w>>1, nh = w&1;
    const int m0 = strip*16;
    const int row0 = blockIdx.x*128;

    {   // xs (fp16 single) via cp.async
        const char* sx = (const char*)g_x1f + row0*272;
        for (int i=tid;i<2176;i+=512){
            cpa16(sb + F_XS + i*16, sx + i*16);
        }
        CPA_COMMIT();
    }
    {   // W2[0] -> buf0
        const uint4* s2h = (const uint4*)(g_w2th);
        const uint4* s2l = (const uint4*)(g_w2tl);
        for (int i=tid;i<1152;i+=512){
            cpa16(sb + F_W2H + i*16, s2h+i);
            cpa16(sb + F_W2L + i*16, s2l+i);
        }
        CPA_COMMIT();
    }

    float acc2[8][4];
    #pragma unroll
    for (int i=0;i<8;i++){ acc2[i][0]=0.f; acc2[i][1]=0.f; acc2[i][2]=0.f; acc2[i][3]=0.f; }

    const int a_r = lane & 15, a_c = (lane & 16) >> 1;
    const int b4_r = (lane & 7) + ((lane & 16) >> 1);
    const int b4_c = lane & 8;
    const int q = lane & 3, gq = lane >> 2;

    for (int c=0; c<32; c++){
        const int cur = c & 1;
        __syncthreads();
        {   // W1[c] (committed before W2[c+1])
            const uint4* s1h = (const uint4*)(g_w1th + c*64*136);
            const uint4* s1l = (const uint4*)(g_w1tl + c*64*136);
            for (int i=tid;i<1088;i+=512){
                cpa16(sb + F_W1H + i*16, s1h+i);
                cpa16(sb + F_W1L + i*16, s1l+i);
            }
            CPA_COMMIT();
        }
        if (c+1 < 32){
            uint32_t dh = cur ? (uint32_t)F_W2H : (uint32_t)F_W2H2;
            uint32_t dl = cur ? (uint32_t)F_W2L : (uint32_t)F_W2L2;
            const uint4* s2h = (const uint4*)(g_w2th + (c+1)*128*72);
            const uint4* s2l = (const uint4*)(g_w2tl + (c+1)*128*72);
            for (int i=tid;i<1152;i+=512){
                cpa16(sb + dh + i*16, s2h+i);
                cpa16(sb + dl + i*16, s2l+i);
            }
            CPA_COMMIT();
            CPA_WAIT1();
        } else {
            CPA_WAIT0();
        }
        __syncthreads();

        // GEMM1: mid[128x64] = xs @ W1^T (2-term fp16)
        float acc1[4][4];
        #pragma unroll
        for (int i=0;i<4;i++){ acc1[i][0]=0.f; acc1[i][1]=0.f; acc1[i][2]=0.f; acc1[i][3]=0.f; }
        #pragma unroll
        for (int kk=0;kk<8;kk++){
            const int k0 = kk*16;
            uint32_t aaddr = sb + F_XS + ((m0+a_r)*136 + k0 + a_c)*2;
            unsigned ax[4];
            ldsm4(ax, aaddr);
            #pragma unroll
            for (int ntp=0;ntp<2;ntp++){
                uint32_t baddr = sb + F_W1H + ((nh*32+ntp*16+b4_r)*136 + k0 + b4_c)*2;
                unsigned bh[4], bl[4];
                ldsm4(bh, baddr);
                ldsm4(bl, baddr + (F_W1L - F_W1H));
                float* a0 = acc1[ntp*2], *a1 = acc1[ntp*2+1];
                mma_f16(a0, ax, bh[0], bh[1]);
                mma_f16(a0, ax, bl[0], bl[1]);
                mma_f16(a1, ax, bh[2], bh[3]);
                mma_f16(a1, ax, bl[2], bl[3]);
            }
        }
        {   // epilogue1: +b1, relu, single fp16 -> mid
            const int r1 = m0 + gq, r2 = r1 + 8;
            #pragma unroll
            for (int nt=0;nt<4;nt++){
                int col = nh*32 + ((nt<2) ? nt*8 : (nt-2)*8 + 16) + q*2;
                float bb0 = b1v[c*64+col], bb1 = b1v[c*64+col+1];
                float v0 = fmaxf(acc1[nt][0]+bb0, 0.f);
                float v1 = fmaxf(acc1[nt][1]+bb1, 0.f);
                float v2 = fmaxf(acc1[nt][2]+bb0, 0.f);
                float v3 = fmaxf(acc1[nt][3]+bb1, 0.f);
                *(__half2*)&mid[r1*72+col] = __floats2half2_rn(v0, v1);
                *(__half2*)&mid[r2*72+col] = __floats2half2_rn(v2, v3);
            }
        }
        __syncthreads();

        // GEMM2: acc2 += mid @ W2^T (2-term fp16)
        const uint32_t w2h_base = cur ? (uint32_t)F_W2H2 : (uint32_t)F_W2H;
        #pragma unroll
        for (int kk=0;kk<4;kk++){
            const int k0 = kk*16;
            uint32_t aaddr = sb + F_MID + ((m0+a_r)*72 + k0 + a_c)*2;
            unsigned am[4];
            ldsm4(am, aaddr);
            #pragma unroll
            for (int ntp=0;ntp<4;ntp++){
                uint32_t baddr = sb + w2h_base + ((nh*64+ntp*16+b4_r)*72 + k0 + b4_c)*2;
                unsigned bh[4], bl[4];
                ldsm4(bh, baddr);
                ldsm4(bl, baddr + 18432);
                float* a0 = acc2[ntp*2], *a1 = acc2[ntp*2+1];
                mma_f16(a0, am, bh[0], bh[1]);
                mma_f16(a0, am, bl[0], bl[1]);
                mma_f16(a1, am, bh[2], bh[3]);
                mma_f16(a1, am, bl[2], bl[3]);
            }
        }
    }

    // epilogue: +b2 + residual + LN2
    #pragma unroll
    for (int half=0; half<2; half++){
        int rl = m0 + gq + half*8;
        int grow = row0 + rl;
        float tv[16], s1=0.f, s2=0.f;
        #pragma unroll
        for (int nt=0;nt<8;nt++){
            int col = nh*64 + nt*8 + q*2;
            float t0 = acc2[nt][half*2+0] + b2v[col]   + g_x1[grow*HID_+col];
            float t1 = acc2[nt][half*2+1] + b2v[col+1] + g_x1[grow*HID_+col+1];
            tv[nt*2]=t0; tv[nt*2+1]=t1;
            s1 += t0+t1; s2 += t0*t0+t1*t1;
        }
        s1 += __shfl_xor_sync(0xffffffffu, s1, 1); s2 += __shfl_xor_sync(0xffffffffu, s2, 1);
        s1 += __shfl_xor_sync(0xffffffffu, s1, 2); s2 += __shfl_xor_sync(0xffffffffu, s2, 2);
        if (q==0){ s_s1[rl][nh]=s1; s_s2[rl][nh]=s2; }
        __syncthreads();
        float fs1 = s_s1[rl][0]+s_s1[rl][1];
        float fs2 = s_s2[rl][0]+s_s2[rl][1];
        float mean = fs1*(1.f/HID_);
        float var  = fs2*(1.f/HID_) - mean*mean;
        float rs   = rsqrtf(var + EPS_);
        #pragma unroll
        for (int nt=0;nt<8;nt++){
            int col = nh*64 + nt*8 + q*2;
            out[grow*HID_+col]   = (tv[nt*2]  -mean)*rs*g2[col]   + be2[col];
            out[grow*HID_+col+1] = (tv[nt*2+1]-mean)*rs*g2[col+1] + be2[col+1];
        }
        __syncthreads();
    }
}

// ---------------- launch ----------------------------------------------------
extern "C" void kernel_launch(void* const* d_in, const int* in_sizes, int n_in,
                              void* d_out, int out_size){
    int o = (in_sizes[4] == 1) ? 1 : 0;
    const float* h       = (const float*)d_in[0];
    const float* e       = (const float*)d_in[1];
    const int*   src     = (const int*)  d_in[2];
    const int*   dst     = (const int*)  d_in[3];
    const float* W_fc    = (const float*)d_in[4+o];
    const float* attn_l  = (const float*)d_in[5+o];
    const float* attn_r  = (const float*)d_in[6+o];
    const float* W_fe    = (const float*)d_in[7+o];
    const float* attn_e  = (const float*)d_in[8+o];
    const float* W_res   = (const float*)d_in[9+o];
    const float* gatb    = (const float*)d_in[10+o];
    const float* W_mha   = (const float*)d_in[11+o];
    const float* b_mha   = (const float*)d_in[12+o];
    const float* n1_g    = (const float*)d_in[13+o];
    const float* n1_b    = (const float*)d_in[14+o];
    const float* n2_g    = (const float*)d_in[15+o];
    const float* n2_b    = (const float*)d_in[16+o];
    const float* W1      = (const float*)d_in[17+o];
    const float* b1      = (const float*)d_in[18+o];
    const float* W2      = (const float*)d_in[19+o];
    const float* b2      = (const float*)d_in[20+o];
    float* out = (float*)d_out;

    cudaFuncSetAttribute(k_ffn_mma,  cudaFuncAttributeMaxDynamicSharedMemorySize, SMEM_FFN);
    cudaFuncSetAttribute(k_gemmA_mma,cudaFuncAttributeMaxDynamicSharedMemorySize, SMEM_GZ);
    cudaFuncSetAttribute(k_mha_mma,  cudaFuncAttributeMaxDynamicSharedMemorySize, SMEM_MH);

    k_init<<<128,256>>>();
    k_prep<<<1024,256>>>(W1, W2, W_fc, W_res, W_mha, h, dst);
    k_scan1<<<128,256>>>();
    k_scan2<<<1,128>>>();
    k_scan3<<<128,256>>>();
    dim3 gA(64, 4, 2);
    k_gemmA_mma<<<gA,512,SMEM_GZ>>>(attn_l, attn_r);
    k_edgefill<<<N_EDGES/256,256>>>(e, src, dst, W_fe, attn_e);
    k_agg<<<N_NODES*NH/8,256>>>(gatb);
    k_mha_mma<<<N_NODES/128,512,SMEM_MH>>>(b_mha, h, n1_g, n1_b);
    k_ffn_mma<<<N_NODES/128,512,SMEM_FFN>>>(b1, b2, n2_g, n2_b, out);
}

// round 17
// speedup vs baseline: 1.6750x; 1.0332x over previous
#include <cuda_runtime.h>
#include <cuda_bf16.h>
#include <cuda_fp16.h>
#include <cstdint>

#define N_NODES 32768
#define N_EDGES 524288
#define NH      4
#define HDIM    128
#define HD      512
#define HID_    128
#define DFF_    2048
#define SLOPE_  0.2f
#define EPS_    1e-5f

// ---------------- scratch ----------------------------------------------------
__device__ __align__(16) __half g_fth[N_NODES*HD];   // ft in fp16 (k_agg only)
__device__ float    g_res[N_NODES*HD];
__device__ float    g_el [N_NODES*NH];
__device__ float    g_er [N_NODES*NH];
__device__ int      g_deg[N_NODES];
__device__ int      g_cursor[N_NODES];
__device__ int      g_rowptr[N_NODES+1];
__device__ int      g_bsum[128];
__device__ int      g_esrc[N_EDGES];
__device__ __align__(16) float g_wsH[N_EDGES*4];
__device__ float    g_x1 [N_NODES*HID_];

// pre-split activations
__device__ __align__(16) __nv_bfloat16 g_hh  [N_NODES*136];
__device__ __align__(16) __nv_bfloat16 g_hl  [N_NODES*136];
__device__ __align__(16) __half        g_resf[N_NODES*544];   // relu(rst) single fp16 (mha A)
__device__ __align__(16) __half        g_x1f [N_NODES*136];   // x1 single fp16 (FFN)

// weights: FFN+MHA fp16 hi/lo; gemmA bf16 hi/lo
__device__ __align__(16) __half g_w1th[32*64*136];
__device__ __align__(16) __half g_w1tl[32*64*136];
__device__ __align__(16) __half g_w2th[32*128*72];
__device__ __align__(16) __half g_w2tl[32*128*72];
__device__ __align__(16) __half g_wmth[512*136];
__device__ __align__(16) __half g_wmtl[512*136];
__device__ __align__(16) __nv_bfloat16 g_wfth[512*136];
__device__ __align__(16) __nv_bfloat16 g_wftl[512*136];
__device__ __align__(16) __nv_bfloat16 g_wrth[512*136];
__device__ __align__(16) __nv_bfloat16 g_wrtl[512*136];

// ---------------- helpers ------------------------------------------------------
__device__ __forceinline__ uint32_t smem_u32(const void* p){
    uint32_t a;
    asm("{ .reg .u64 t; cvta.to.shared.u64 t, %1; cvt.u32.u64 %0, t; }" : "=r"(a) : "l"(p));
    return a;
}
__device__ __forceinline__ void ldsm4(unsigned* r, uint32_t addr){
    asm volatile("ldmatrix.sync.aligned.m8n8.x4.shared.b16 {%0,%1,%2,%3}, [%4];"
        : "=r"(r[0]),"=r"(r[1]),"=r"(r[2]),"=r"(r[3]) : "r"(addr));
}
__device__ __forceinline__ void mma_bf16(float* c, const unsigned* a, unsigned b0, unsigned b1){
    asm volatile("mma.sync.aligned.m16n8k16.row.col.f32.bf16.bf16.f32 "
        "{%0,%1,%2,%3},{%4,%5,%6,%7},{%8,%9},{%0,%1,%2,%3};"
        : "+f"(c[0]),"+f"(c[1]),"+f"(c[2]),"+f"(c[3])
        : "r"(a[0]),"r"(a[1]),"r"(a[2]),"r"(a[3]),"r"(b0),"r"(b1));
}
__device__ __forceinline__ void mma_f16(float* c, const unsigned* a, unsigned b0, unsigned b1){
    asm volatile("mma.sync.aligned.m16n8k16.row.col.f32.f16.f16.f32 "
        "{%0,%1,%2,%3},{%4,%5,%6,%7},{%8,%9},{%0,%1,%2,%3};"
        : "+f"(c[0]),"+f"(c[1]),"+f"(c[2]),"+f"(c[3])
        : "r"(a[0]),"r"(a[1]),"r"(a[2]),"r"(a[3]),"r"(b0),"r"(b1));
}
__device__ __forceinline__ void bsplit(float v, __nv_bfloat16& hi, __nv_bfloat16& lo){
    hi = __float2bfloat16(v);
    lo = __float2bfloat16(v - __bfloat162float(hi));
}
__device__ __forceinline__ void hsplit(float v, __half& hi, __half& lo){
    hi = __float2half_rn(v);
    lo = __float2half_rn(v - __half2float(hi));
}
__device__ __forceinline__ void cpa16(uint32_t saddr, const void* g){
    asm volatile("cp.async.cg.shared.global [%0], [%1], 16;" :: "r"(saddr), "l"(g));
}
#define CPA_COMMIT() asm volatile("cp.async.commit_group;" ::: "memory")
#define CPA_WAIT1()  asm volatile("cp.async.wait_group 1;" ::: "memory")
#define CPA_WAIT0()  asm volatile("cp.async.wait_group 0;" ::: "memory")

// ---------------- init ------------------------------------------------------
__global__ void k_init(){
    int i = blockIdx.x*256 + threadIdx.x;
    if (i < N_NODES){ g_deg[i] = 0; g_cursor[i] = 0; }
}

// ---------------- prep (+ degree count) ---------------------------------------
__global__ void k_prep(const float* __restrict__ W1, const float* __restrict__ W2,
                       const float* __restrict__ Wfc, const float* __restrict__ Wres,
                       const float* __restrict__ Wm, const float* __restrict__ h,
                       const int* __restrict__ dst){
    int i = blockIdx.x*256 + threadIdx.x;   // 262144 threads
    atomicAdd(&g_deg[dst[i]], 1);
    atomicAdd(&g_deg[dst[i + 262144]], 1);
    {   // W1 [k=128][n=2048] -> fp16 hi/lo
        int k = i >> 11, n = i & 2047;
        __half hv, lv; hsplit(W1[i], hv, lv);
        int c = n >> 6, nn = n & 63;
        g_w1th[(c*64+nn)*136 + k] = hv;
        g_w1tl[(c*64+nn)*136 + k] = lv;
    }
    {   // W2 [k2=2048][n=128] -> fp16 hi/lo
        int k2 = i >> 7, n = i & 127;
        __half hv, lv; hsplit(W2[i], hv, lv);
        int c = k2 >> 6, kk = k2 & 63;
        g_w2th[(c*128+n)*72 + kk] = hv;
        g_w2tl[(c*128+n)*72 + kk] = lv;
    }
    #pragma unroll
    for (int j=0;j<16;j++){
        int idx = i + j*262144;
        int n = idx >> 7, k = idx & 127;
        __nv_bfloat16 hv, lv; bsplit(h[idx], hv, lv);
        g_hh[n*136+k] = hv;
        g_hl[n*136+k] = lv;
    }
    if (i < 65536){
        {   // Wfc/Wres [k=128][n=512] bf16 hi/lo
            int k = i >> 9, n = i & 511;
            __nv_bfloat16 hv, lv;
            bsplit(Wfc[i], hv, lv);
            g_wfth[n*136 + k] = hv; g_wftl[n*136 + k] = lv;
            bsplit(Wres[i], hv, lv);
            g_wrth[n*136 + k] = hv; g_wrtl[n*136 + k] = lv;
        }
        {   // Wm [k2=512][n=128] -> fp16 hi/lo
            int k2 = i >> 7, n = i & 127;
            __half hv, lv; hsplit(Wm[i], hv, lv);
            int c = k2 >> 7, kk = k2 & 127;
            g_wmth[(c*128+n)*136 + kk] = hv;
            g_wmtl[(c*128+n)*136 + kk] = lv;
        }
    }
}

// ---------------- hierarchical CSR scan ---------------------------------------
__global__ __launch_bounds__(256) void k_scan1(){
    int b = blockIdx.x, t = threadIdx.x;
    int node = b*256 + t;
    int d = g_deg[node];
    int v = d;
    #pragma unroll
    for (int off=1; off<32; off<<=1){
        int nv = __shfl_up_sync(0xffffffffu, v, off);
        if ((t&31) >= off) v += nv;
    }
    __shared__ int wsum[8];
    if ((t&31)==31) wsum[t>>5] = v;
    __syncthreads();
    if (t < 8){
        int wv = wsum[t];
        #pragma unroll
        for (int off=1; off<8; off<<=1){
            int nv = __shfl_up_sync(0xffu, wv, off);
            if (t >= off) wv += nv;
        }
        wsum[t] = wv;
    }
    __syncthreads();
    int incl = v + ((t>=32) ? wsum[(t>>5)-1] : 0);
    g_rowptr[node] = incl - d;
    if (t==255) g_bsum[b] = incl;
}

__global__ __launch_bounds__(128) void k_scan2(){
    int t = threadIdx.x;
    int v = g_bsum[t];
    int x = v;
    #pragma unroll
    for (int off=1; off<32; off<<=1){
        int nv = __shfl_up_sync(0xffffffffu, x, off);
        if ((t&31) >= off) x += nv;
    }
    __shared__ int ws[4];
    if ((t&31)==31) ws[t>>5] = x;
    __syncthreads();
    if (t < 4){
        int wv = ws[t];
        #pragma unroll
        for (int off=1; off<4; off<<=1){
            int nv = __shfl_up_sync(0xfu, wv, off);
            if (t >= off) wv += nv;
        }
        ws[t] = wv;
    }
    __syncthreads();
    int incl = x + ((t>=32) ? ws[(t>>5)-1] : 0);
    g_bsum[t] = incl - v;
    if (t==127) g_rowptr[N_NODES] = incl;
}

__global__ __launch_bounds__(256) void k_scan3(){
    int node = blockIdx.x*256 + threadIdx.x;
    g_rowptr[node] += g_bsum[blockIdx.x];
}

// ---------------- GEMM A: z-split, A double-buffered via cp.async ------------
#define GZ_A0H 0
#define GZ_A0L 34816
#define GZ_A1H 69632
#define GZ_A1L 104448
#define GZ_BH  139264
#define GZ_BL  174080
#define SMEM_GZ 208896

__global__ __launch_bounds__(512,1) void k_gemmA_mma(
        const float* __restrict__ attn_l, const float* __restrict__ attn_r){
    extern __shared__ char smem[];
    __shared__ float s_al[128], s_ar[128];
    __shared__ float s_pl[128][2], s_pr[128][2];
    const uint32_t sb = smem_u32(smem);
    const int tid = threadIdx.x, lane = tid&31, w = tid>>5;
    const int strip = w>>1, nh = w&1;
    const int m0 = strip*16, ncol0 = nh*64;
    const int col0 = blockIdx.y*128;
    const int z = blockIdx.z;
    const __nv_bfloat16* Bh = z ? g_wrth : g_wfth;
    const __nv_bfloat16* Bl = z ? g_wrtl : g_wftl;

    if (z==0 && tid<128){
        s_al[tid] = attn_l[col0+tid];
        s_ar[tid] = attn_r[col0+tid];
    }
    {   // G0: B tile + A(0)
        const char* bh = (const char*)(Bh + col0*136);
        const char* bl = (const char*)(Bl + col0*136);
        const char* a0h = (const char*)g_hh + (blockIdx.x*4+0)*128*272;
        const char* a0l = (const char*)g_hl + (blockIdx.x*4+0)*128*272;
        for (int i=tid;i<2176;i+=512){
            cpa16(sb + GZ_BH  + i*16, bh  + i*16);
            cpa16(sb + GZ_BL  + i*16, bl  + i*16);
            cpa16(sb + GZ_A0H + i*16, a0h + i*16);
            cpa16(sb + GZ_A0L + i*16, a0l + i*16);
        }
        CPA_COMMIT();
    }

    const int a_r = lane & 15, a_c = (lane & 16) >> 1;
    const int b4_r = (lane & 7) + ((lane & 16) >> 1);
    const int b4_c = lane & 8;
    const int q = lane & 3, gq = lane >> 2;

    for (int rt=0; rt<4; rt++){
        const int row0 = (blockIdx.x*4+rt)*128;
        __syncthreads();
        if (rt<3){
            uint32_t dh = ((rt+1)&1) ? (uint32_t)GZ_A1H : (uint32_t)GZ_A0H;
            uint32_t dl = ((rt+1)&1) ? (uint32_t)GZ_A1L : (uint32_t)GZ_A0L;
            const char* ah = (const char*)g_hh + (blockIdx.x*4+rt+1)*128*272;
            const char* al_= (const char*)g_hl + (blockIdx.x*4+rt+1)*128*272;
            for (int i=tid;i<2176;i+=512){
                cpa16(sb + dh + i*16, ah + i*16);
                cpa16(sb + dl + i*16, al_+ i*16);
            }
            CPA_COMMIT();
            CPA_WAIT1();
        } else {
            CPA_WAIT0();
        }
        __syncthreads();
        const uint32_t A_H = (rt&1) ? (uint32_t)GZ_A1H : (uint32_t)GZ_A0H;
        const uint32_t A_L = (rt&1) ? (uint32_t)GZ_A1L : (uint32_t)GZ_A0L;

        float acc[8][4];
        #pragma unroll
        for (int i=0;i<8;i++){ acc[i][0]=0.f; acc[i][1]=0.f; acc[i][2]=0.f; acc[i][3]=0.f; }
        #pragma unroll
        for (int kk=0;kk<8;kk++){
            const int k0 = kk*16;
            uint32_t aaddr = sb + A_H + ((m0+a_r)*136 + k0 + a_c)*2;
            unsigned ahf[4], alf[4];
            ldsm4(ahf, aaddr);
            ldsm4(alf, aaddr + (A_L-A_H));
            #pragma unroll
            for (int ntp=0;ntp<4;ntp++){
                uint32_t baddr = sb + GZ_BH + ((ncol0+ntp*16+b4_r)*136 + k0 + b4_c)*2;
                unsigned bh[4], bl[4];
                ldsm4(bh, baddr);
                ldsm4(bl, baddr + (GZ_BL-GZ_BH));
                float* a0 = acc[ntp*2], *a1 = acc[ntp*2+1];
                mma_bf16(a0, ahf, bh[0], bh[1]);
                mma_bf16(a0, ahf, bl[0], bl[1]);
                mma_bf16(a0, alf, bh[0], bh[1]);
                mma_bf16(a1, ahf, bh[2], bh[3]);
                mma_bf16(a1, ahf, bl[2], bl[3]);
                mma_bf16(a1, alf, bh[2], bh[3]);
            }
        }
        if (z==0){
            #pragma unroll
            for (int half=0; half<2; half++){
                int row = row0 + m0 + gq + half*8;
                #pragma unroll
                for (int nt=0;nt<8;nt++){
                    int col = col0 + ncol0 + nt*8 + q*2;
                    *(__half2*)&g_fth[row*HD+col] =
                        __floats2half2_rn(acc[nt][half*2], acc[nt][half*2+1]);
                }
            }
            #pragma unroll
            for (int half=0; half<2; half++){
                int rl = m0 + gq + half*8;
                float pl=0.f, pr=0.f;
                #pragma unroll
                for (int nt=0;nt<8;nt++){
                    int col = ncol0 + nt*8 + q*2;
                    float v0 = acc[nt][half*2], v1 = acc[nt][half*2+1];
                    pl += v0*s_al[col] + v1*s_al[col+1];
                    pr += v0*s_ar[col] + v1*s_ar[col+1];
                }
                pl += __shfl_xor_sync(0xffffffffu, pl, 1);
                pl += __shfl_xor_sync(0xffffffffu, pl, 2);
                pr += __shfl_xor_sync(0xffffffffu, pr, 1);
                pr += __shfl_xor_sync(0xffffffffu, pr, 2);
                if (q==0){ s_pl[rl][nh]=pl; s_pr[rl][nh]=pr; }
            }
            __syncthreads();
            if (tid<128){
                int row = row0 + tid;
                g_el[row*NH + blockIdx.y] = s_pl[tid][0]+s_pl[tid][1];
                g_er[row*NH + blockIdx.y] = s_pr[tid][0]+s_pr[tid][1];
            }
        } else {
            #pragma unroll
            for (int half=0; half<2; half++){
                int row = row0 + m0 + gq + half*8;
                #pragma unroll
                for (int nt=0;nt<8;nt++){
                    int col = col0 + ncol0 + nt*8 + q*2;
                    *(float2*)&g_res[row*HD+col] =
                        make_float2(acc[nt][half*2], acc[nt][half*2+1]);
                }
            }
        }
    }
}

// ---------------- edge pass + CSR fill (1 atomic/edge) ------------------------
__global__ __launch_bounds__(256) void k_edgefill(const float* __restrict__ e,
        const int* __restrict__ src, const int* __restrict__ dst,
        const float* __restrict__ W_fe, const float* __restrict__ attn_e){
    __shared__ float ce[NH];
    int wid = threadIdx.x>>5, lane = threadIdx.x&31;
    if (wid < NH){
        float p = 0.f;
        #pragma unroll
        for (int q=0;q<4;q++){
            int d = lane + q*32;
            p += W_fe[wid*HDIM+d]*attn_e[wid*HDIM+d];
        }
        #pragma unroll
        for (int off=16; off; off>>=1) p += __shfl_xor_sync(0xffffffffu, p, off);
        if (lane==0) ce[wid]=p;
    }
    __syncthreads();
    int ei = blockIdx.x*256 + threadIdx.x;
    if (ei >= N_EDGES) return;
    int s = src[ei], d = dst[ei];
    float ev = e[ei];
    float4 els = ((const float4*)g_el)[s];
    float4 erd = ((const float4*)g_er)[d];
    float sc[4];
    sc[0] = els.x + erd.x + ev*ce[0];
    sc[1] = els.y + erd.y + ev*ce[1];
    sc[2] = els.z + erd.z + ev*ce[2];
    sc[3] = els.w + erd.w + ev*ce[3];
    float wv[4];
    #pragma unroll
    for (int hh=0;hh<4;hh++){
        float v = sc[hh];
        v = v > 0.f ? v : SLOPE_*v;
        wv[hh] = expf(v);
    }
    int pos = g_rowptr[d] + atomicAdd(&g_cursor[d], 1);
    g_esrc[pos] = s;
    *(float4*)&g_wsH[pos*4] = make_float4(wv[0],wv[1],wv[2],wv[3]);
}

// ---------------- aggregation: fp16 gathers, local zsum ------------------------
__global__ __launch_bounds__(256) void k_agg(const float* __restrict__ gat_bias){
    int wid = threadIdx.x>>5, lane = threadIdx.x&31;
    int gw = blockIdx.x*8 + wid;
    int n = gw>>2, hh = gw&3;
    int beg = g_rowptr[n], end = g_rowptr[n+1];
    float4 acc = make_float4(0,0,0,0);
    float zsum = 0.f;
    const __half2* fth = (const __half2*)g_fth;
    const float* wp = g_wsH + hh;
    const int lofs = hh*64 + lane*2;
    int i = beg;
    for (; i+4<=end; i+=4){
        float w0 = wp[i*4],   w1 = wp[(i+1)*4], w2 = wp[(i+2)*4], w3 = wp[(i+3)*4];
        int   s0 = g_esrc[i], s1 = g_esrc[i+1], s2 = g_esrc[i+2], s3 = g_esrc[i+3];
        __half2 p0a = fth[s0*256 + lofs], p0b = fth[s0*256 + lofs + 1];
        __half2 p1a = fth[s1*256 + lofs], p1b = fth[s1*256 + lofs + 1];
        __half2 p2a = fth[s2*256 + lofs], p2b = fth[s2*256 + lofs + 1];
        __half2 p3a = fth[s3*256 + lofs], p3b = fth[s3*256 + lofs + 1];
        float2 f0a = __half22float2(p0a), f0b = __half22float2(p0b);
        float2 f1a = __half22float2(p1a), f1b = __half22float2(p1b);
        float2 f2a = __half22float2(p2a), f2b = __half22float2(p2b);
        float2 f3a = __half22float2(p3a), f3b = __half22float2(p3b);
        zsum += w0+w1+w2+w3;
        acc.x += w0*f0a.x + w1*f1a.x + w2*f2a.x + w3*f3a.x;
        acc.y += w0*f0a.y + w1*f1a.y + w2*f2a.y + w3*f3a.y;
        acc.z += w0*f0b.x + w1*f1b.x + w2*f2b.x + w3*f3b.x;
        acc.w += w0*f0b.y + w1*f1b.y + w2*f2b.y + w3*f3b.y;
    }
    for (; i<end; i++){
        float w0 = wp[i*4];
        int s0 = g_esrc[i];
        float2 fa = __half22float2(fth[s0*256 + lofs]);
        float2 fb = __half22float2(fth[s0*256 + lofs + 1]);
        zsum += w0;
        acc.x = fmaf(w0, fa.x, acc.x);
        acc.y = fmaf(w0, fa.y, acc.y);
        acc.z = fmaf(w0, fb.x, acc.z);
        acc.w = fmaf(w0, fb.y, acc.w);
    }
    float zi = zsum > 0.f ? 1.f/zsum : 1.f;
    int base = n*HD + hh*HDIM + lane*4;
    float4 r  = *(const float4*)&g_res[base];
    float4 bv = *(const float4*)&gat_bias[hh*HDIM + lane*4];
    float o0 = fmaxf(acc.x*zi + r.x + bv.x, 0.f);
    float o1 = fmaxf(acc.y*zi + r.y + bv.y, 0.f);
    float o2 = fmaxf(acc.z*zi + r.z + bv.z, 0.f);
    float o3 = fmaxf(acc.w*zi + r.w + bv.w, 0.f);
    int sbase = n*544 + hh*136 + lane*4;
    *(__half2*)&g_resf[sbase]   = __floats2half2_rn(o0, o1);
    *(__half2*)&g_resf[sbase+2] = __floats2half2_rn(o2, o3);
}

// ---------------- MHA: fp16 2-term, single-fp16 A + double-buffered Wm --------
#define MH_A   0
#define MH_W0H 34816
#define MH_W0L 69632
#define MH_W1H 104448
#define MH_W1L 139264
#define SMEM_MH 174080

__global__ __launch_bounds__(512,1) void k_mha_mma(const float* __restrict__ bm,
        const float* __restrict__ h0, const float* __restrict__ g1,
        const float* __restrict__ be1){
    extern __shared__ char smem[];
    __shared__ float s_s1[128][2], s_s2[128][2];
    const uint32_t sb = smem_u32(smem);
    const int tid = threadIdx.x, lane = tid&31, w = tid>>5;
    const int strip = w>>1, nh = w&1;
    const int m0 = strip*16, ncol0 = nh*64;
    const int row0 = blockIdx.x*128;

    const int a_r = lane & 15, a_c = (lane & 16) >> 1;
    const int b4_r = (lane & 7) + ((lane & 16) >> 1);
    const int b4_c = lane & 8;
    const int q = lane & 3, gq = lane >> 2;

    float acc[8][4];
    #pragma unroll
    for (int i=0;i<8;i++){ acc[i][0]=0.f; acc[i][1]=0.f; acc[i][2]=0.f; acc[i][3]=0.f; }

    {   // Wm[0] hi/lo -> buf0
        const char* sh = (const char*)g_wmth;
        const char* sl = (const char*)g_wmtl;
        for (int i=tid;i<2176;i+=512){
            cpa16(sb + MH_W0H + i*16, sh + i*16);
            cpa16(sb + MH_W0L + i*16, sl + i*16);
        }
        CPA_COMMIT();
    }

    for (int c=0; c<4; c++){
        const int cur = c & 1;
        __syncthreads();
        {   // A(c) single fp16 from g_resf
            for (int i=tid;i<2176;i+=512){
                int m = i/17, o = i - m*17;
                long so = (long)(row0+m)*1088 + c*272 + o*16;
                cpa16(sb + MH_A + m*272 + o*16, (const char*)g_resf + so);
            }
            CPA_COMMIT();
        }
        if (c < 3){
            uint32_t dh = cur ? (uint32_t)MH_W0H : (uint32_t)MH_W1H;
            uint32_t dl = cur ? (uint32_t)MH_W0L : (uint32_t)MH_W1L;
            const char* sh = (const char*)(g_wmth + (c+1)*128*136);
            const char* sl = (const char*)(g_wmtl + (c+1)*128*136);
            for (int i=tid;i<2176;i+=512){
                cpa16(sb + dh + i*16, sh + i*16);
                cpa16(sb + dl + i*16, sl + i*16);
            }
            CPA_COMMIT();
            CPA_WAIT1();
        } else {
            CPA_WAIT0();
        }
        __syncthreads();

        const uint32_t wbh = cur ? (uint32_t)MH_W1H : (uint32_t)MH_W0H;
        const uint32_t wbl = cur ? (uint32_t)MH_W1L : (uint32_t)MH_W0L;
        #pragma unroll
        for (int kk=0;kk<8;kk++){
            const int k0 = kk*16;
            uint32_t aaddr = sb + MH_A + ((m0+a_r)*136 + k0 + a_c)*2;
            unsigned ax[4];
            ldsm4(ax, aaddr);
            #pragma unroll
            for (int ntp=0;ntp<4;ntp++){
                uint32_t boff = ((ncol0+ntp*16+b4_r)*136 + k0 + b4_c)*2;
                unsigned bh[4], bl[4];
                ldsm4(bh, sb + wbh + boff);
                ldsm4(bl, sb + wbl + boff);
                float* a0 = acc[ntp*2], *a1 = acc[ntp*2+1];
                mma_f16(a0, ax, bh[0], bh[1]);
                mma_f16(a0, ax, bl[0], bl[1]);
                mma_f16(a1, ax, bh[2], bh[3]);
                mma_f16(a1, ax, bl[2], bl[3]);
            }
        }
    }

    #pragma unroll
    for (int half=0; half<2; half++){
        int rl = m0 + gq + half*8;
        int row = row0 + rl;
        float tv[16], s1=0.f, s2=0.f;
        #pragma unroll
        for (int nt=0;nt<8;nt++){
            int col = ncol0 + nt*8 + q*2;
            float t0 = fmaxf(acc[nt][half*2+0] + bm[col],   0.f) + h0[row*HID_+col];
            float t1 = fmaxf(acc[nt][half*2+1] + bm[col+1], 0.f) + h0[row*HID_+col+1];
            tv[nt*2]=t0; tv[nt*2+1]=t1;
            s1 += t0+t1; s2 += t0*t0+t1*t1;
        }
        s1 += __shfl_xor_sync(0xffffffffu, s1, 1); s2 += __shfl_xor_sync(0xffffffffu, s2, 1);
        s1 += __shfl_xor_sync(0xffffffffu, s1, 2); s2 += __shfl_xor_sync(0xffffffffu, s2, 2);
        if (q==0){ s_s1[rl][nh]=s1; s_s2[rl][nh]=s2; }
        __syncthreads();
        float fs1 = s_s1[rl][0]+s_s1[rl][1];
        float fs2 = s_s2[rl][0]+s_s2[rl][1];
        float mean = fs1*(1.f/HID_);
        float var  = fs2*(1.f/HID_) - mean*mean;
        float rs   = rsqrtf(var + EPS_);
        #pragma unroll
        for (int nt=0;nt<8;nt++){
            int col = ncol0 + nt*8 + q*2;
            float x0 = (tv[nt*2]  -mean)*rs*g1[col]   + be1[col];
            float x1 = (tv[nt*2+1]-mean)*rs*g1[col+1] + be1[col+1];
            *(float2*)&g_x1[row*HID_+col] = make_float2(x0, x1);
            *(__half2*)&g_x1f[row*136+col] = __floats2half2_rn(x0, x1);
        }
        __syncthreads();
    }
}

// ---------------- FFN: fp16 2-term, single-buffer activations ----------------
#define F_XS   0
#define F_W1H  34816
#define F_W1L  52224
#define F_W2H  69632
#define F_W2L  88064
#define F_MID  106496
#define F_W2H2 124928
#define F_W2L2 143360
#define SMEM_FFN 161792

__global__ __launch_bounds__(512,1) void k_ffn_mma(const float* __restrict__ b1v,
        const float* __restrict__ b2v, const float* __restrict__ g2,
        const float* __restrict__ be2, float* __restrict__ out){
    extern __shared__ char smem[];
    __shared__ float s_s1[128][2], s_s2[128][2];
    __half* mid = (__half*)(smem+F_MID);
    const uint32_t sb = smem_u32(smem);
    const int tid = threadIdx.x, lane = tid&31, w = tid>>5;
    const int strip = w>>1, nh = w&1;
    const int m0 = strip*16;
    const int row0 = blockIdx.x*128;

    {   // xs (fp16 single) via cp.async
        const char* sx = (const char*)g_x1f + row0*272;
        for (int i=tid;i<2176;i+=512){
            cpa16(sb + F_XS + i*16, sx + i*16);
        }
        CPA_COMMIT();
    }
    {   // W2[0] -> buf0
        const uint4* s2h = (const uint4*)(g_w2th);
        const uint4* s2l = (const uint4*)(g_w2tl);
        for (int i=tid;i<1152;i+=512){
            cpa16(sb + F_W2H + i*16, s2h+i);
            cpa16(sb + F_W2L + i*16, s2l+i);
        }
        CPA_COMMIT();
    }

    float acc2[8][4];
    #pragma unroll
    for (int i=0;i<8;i++){ acc2[i][0]=0.f; acc2[i][1]=0.f; acc2[i][2]=0.f; acc2[i][3]=0.f; }

    const int a_r = lane & 15, a_c = (lane & 16) >> 1;
    const int b4_r = (lane & 7) + ((lane & 16) >> 1);
    const int b4_c = lane & 8;
    const int q = lane & 3, gq = lane >> 2;

    for (int c=0; c<32; c++){
        const int cur = c & 1;
        __syncthreads();
        {   // W1[c] (committed before W2[c+1])
            const uint4* s1h = (const uint4*)(g_w1th + c*64*136);
            const uint4* s1l = (const uint4*)(g_w1tl + c*64*136);
            for (int i=tid;i<1088;i+=512){
                cpa16(sb + F_W1H + i*16, s1h+i);
                cpa16(sb + F_W1L + i*16, s1l+i);
            }
            CPA_COMMIT();
        }
        if (c+1 < 32){
            uint32_t dh = cur ? (uint32_t)F_W2H : (uint32_t)F_W2H2;
            uint32_t dl = cur ? (uint32_t)F_W2L : (uint32_t)F_W2L2;
            const uint4* s2h = (const uint4*)(g_w2th + (c+1)*128*72);
            const uint4* s2l = (const uint4*)(g_w2tl + (c+1)*128*72);
            for (int i=tid;i<1152;i+=512){
                cpa16(sb + dh + i*16, s2h+i);
                cpa16(sb + dl + i*16, s2l+i);
            }
            CPA_COMMIT();
            CPA_WAIT1();
        } else {
            CPA_WAIT0();
        }
        __syncthreads();

        // GEMM1: mid[128x64] = xs @ W1^T (2-term fp16)
        float acc1[4][4];
        #pragma unroll
        for (int i=0;i<4;i++){ acc1[i][0]=0.f; acc1[i][1]=0.f; acc1[i][2]=0.f; acc1[i][3]=0.f; }
        #pragma unroll
        for (int kk=0;kk<8;kk++){
            const int k0 = kk*16;
            uint32_t aaddr = sb + F_XS + ((m0+a_r)*136 + k0 + a_c)*2;
            unsigned ax[4];
            ldsm4(ax, aaddr);
            #pragma unroll
            for (int ntp=0;ntp<2;ntp++){
                uint32_t baddr = sb + F_W1H + ((nh*32+ntp*16+b4_r)*136 + k0 + b4_c)*2;
                unsigned bh[4], bl[4];
                ldsm4(bh, baddr);
                ldsm4(bl, baddr + (F_W1L - F_W1H));
                float* a0 = acc1[ntp*2], *a1 = acc1[ntp*2+1];
                mma_f16(a0, ax, bh[0], bh[1]);
                mma_f16(a0, ax, bl[0], bl[1]);
                mma_f16(a1, ax, bh[2], bh[3]);
                mma_f16(a1, ax, bl[2], bl[3]);
            }
        }
        {   // epilogue1: +b1, relu, single fp16 -> mid
            const int r1 = m0 + gq, r2 = r1 + 8;
            #pragma unroll
            for (int nt=0;nt<4;nt++){
                int col = nh*32 + ((nt<2) ? nt*8 : (nt-2)*8 + 16) + q*2;
                float bb0 = b1v[c*64+col], bb1 = b1v[c*64+col+1];
                float v0 = fmaxf(acc1[nt][0]+bb0, 0.f);
                float v1 = fmaxf(acc1[nt][1]+bb1, 0.f);
                float v2 = fmaxf(acc1[nt][2]+bb0, 0.f);
                float v3 = fmaxf(acc1[nt][3]+bb1, 0.f);
                *(__half2*)&mid[r1*72+col] = __floats2half2_rn(v0, v1);
                *(__half2*)&mid[r2*72+col] = __floats2half2_rn(v2, v3);
            }
        }
        __syncthreads();

        // GEMM2: acc2 += mid @ W2^T (2-term fp16)
        const uint32_t w2h_base = cur ? (uint32_t)F_W2H2 : (uint32_t)F_W2H;
        #pragma unroll
        for (int kk=0;kk<4;kk++){
            const int k0 = kk*16;
            uint32_t aaddr = sb + F_MID + ((m0+a_r)*72 + k0 + a_c)*2;
            unsigned am[4];
            ldsm4(am, aaddr);
            #pragma unroll
            for (int ntp=0;ntp<4;ntp++){
                uint32_t baddr = sb + w2h_base + ((nh*64+ntp*16+b4_r)*72 + k0 + b4_c)*2;
                unsigned bh[4], bl[4];
                ldsm4(bh, baddr);
                ldsm4(bl, baddr + 18432);
                float* a0 = acc2[ntp*2], *a1 = acc2[ntp*2+1];
                mma_f16(a0, am, bh[0], bh[1]);
                mma_f16(a0, am, bl[0], bl[1]);
                mma_f16(a1, am, bh[2], bh[3]);
                mma_f16(a1, am, bl[2], bl[3]);
            }
        }
    }

    // epilogue: +b2 + residual + LN2
    #pragma unroll
    for (int half=0; half<2; half++){
        int rl = m0 + gq + half*8;
        int grow = row0 + rl;
        float tv[16], s1=0.f, s2=0.f;
        #pragma unroll
        for (int nt=0;nt<8;nt++){
            int col = nh*64 + nt*8 + q*2;
            float t0 = acc2[nt][half*2+0] + b2v[col]   + g_x1[grow*HID_+col];
            float t1 = acc2[nt][half*2+1] + b2v[col+1] + g_x1[grow*HID_+col+1];
            tv[nt*2]=t0; tv[nt*2+1]=t1;
            s1 += t0+t1; s2 += t0*t0+t1*t1;
        }
        s1 += __shfl_xor_sync(0xffffffffu, s1, 1); s2 += __shfl_xor_sync(0xffffffffu, s2, 1);
        s1 += __shfl_xor_sync(0xffffffffu, s1, 2); s2 += __shfl_xor_sync(0xffffffffu, s2, 2);
        if (q==0){ s_s1[rl][nh]=s1; s_s2[rl][nh]=s2; }
        __syncthreads();
        float fs1 = s_s1[rl][0]+s_s1[rl][1];
        float fs2 = s_s2[rl][0]+s_s2[rl][1];
        float mean = fs1*(1.f/HID_);
        float var  = fs2*(1.f/HID_) - mean*mean;
        float rs   = rsqrtf(var + EPS_);
        #pragma unroll
        for (int nt=0;nt<8;nt++){
            int col = nh*64 + nt*8 + q*2;
            out[grow*HID_+col]   = (tv[nt*2]  -mean)*rs*g2[col]   + be2[col];
            out[grow*HID_+col+1] = (tv[nt*2+1]-mean)*rs*g2[col+1] + be2[col+1];
        }
        __syncthreads();
    }
}

// ---------------- launch ----------------------------------------------------
extern "C" void kernel_launch(void* const* d_in, const int* in_sizes, int n_in,
                              void* d_out, int out_size){
    int o = (in_sizes[4] == 1) ? 1 : 0;
    const float* h       = (const float*)d_in[0];
    const float* e       = (const float*)d_in[1];
    const int*   src     = (const int*)  d_in[2];
    const int*   dst     = (const int*)  d_in[3];
    const float* W_fc    = (const float*)d_in[4+o];
    const float* attn_l  = (const float*)d_in[5+o];
    const float* attn_r  = (const float*)d_in[6+o];
    const float* W_fe    = (const float*)d_in[7+o];
    const float* attn_e  = (const float*)d_in[8+o];
    const float* W_res   = (const float*)d_in[9+o];
    const float* gatb    = (const float*)d_in[10+o];
    const float* W_mha   = (const float*)d_in[11+o];
    const float* b_mha   = (const float*)d_in[12+o];
    const float* n1_g    = (const float*)d_in[13+o];
    const float* n1_b    = (const float*)d_in[14+o];
    const float* n2_g    = (const float*)d_in[15+o];
    const float* n2_b    = (const float*)d_in[16+o];
    const float* W1      = (const float*)d_in[17+o];
    const float* b1      = (const float*)d_in[18+o];
    const float* W2      = (const float*)d_in[19+o];
    const float* b2      = (const float*)d_in[20+o];
    float* out = (float*)d_out;

    cudaFuncSetAttribute(k_ffn_mma,  cudaFuncAttributeMaxDynamicSharedMemorySize, SMEM_FFN);
    cudaFuncSetAttribute(k_gemmA_mma,cudaFuncAttributeMaxDynamicSharedMemorySize, SMEM_GZ);
    cudaFuncSetAttribute(k_mha_mma,  cudaFuncAttributeMaxDynamicSharedMemorySize, SMEM_MH);

    k_init<<<128,256>>>();
    k_prep<<<1024,256>>>(W1, W2, W_fc, W_res, W_mha, h, dst);
    k_scan1<<<128,256>>>();
    k_scan2<<<1,128>>>();
    k_scan3<<<128,256>>>();
    dim3 gA(64, 4, 2);
    k_gemmA_mma<<<gA,512,SMEM_GZ>>>(attn_l, attn_r);
    k_edgefill<<<N_EDGES/256,256>>>(e, src, dst, W_fe, attn_e);
    k_agg<<<N_NODES*NH/8,256>>>(gatb);
    k_mha_mma<<<N_NODES/128,512,SMEM_MH>>>(b_mha, h, n1_g, n1_b);
    k_ffn_mma<<<N_NODES/128,512,SMEM_FFN>>>(b1, b2, n2_g, n2_b, out);
}